// round 8
// baseline (speedup 1.0000x reference)
#include <cuda_runtime.h>
#include <cuda_bf16.h>
#include <cstdint>
#include <math.h>

#define BB 4
#define SS 1024
#define DD 2048
#define HH 16
#define KVHN 8
#define HD 128
#define FFN 8192
#define MM (BB*SS)
#define EPS_RMS 1e-6f
#define KMASK -1e30f

// ================= PTX helpers (base sm_103 ISA only) =================
__device__ __forceinline__ uint32_t smem_to_u32(const void* p) {
    uint32_t a;
    asm("{ .reg .u64 t; cvta.to.shared.u64 t, %1; cvt.u32.u64 %0, t; }" : "=r"(a) : "l"(p));
    return a;
}
#define CP_ASYNC16(sa, gp) \
    asm volatile("cp.async.cg.shared.global [%0], [%1], 16;" :: "r"(sa), "l"(gp) : "memory")
#define CP_COMMIT() asm volatile("cp.async.commit_group;" ::: "memory")
#define CP_WAIT(n)  asm volatile("cp.async.wait_group %0;" :: "n"(n) : "memory")

#define LDSM_X4(r0, r1, r2, r3, sa) \
    asm volatile("ldmatrix.sync.aligned.m8n8.x4.shared.b16 {%0,%1,%2,%3}, [%4];" \
                 : "=r"(r0), "=r"(r1), "=r"(r2), "=r"(r3) : "r"(sa))

#define MMA16816(d, a, b0, b1) \
    asm volatile("mma.sync.aligned.m16n8k16.row.col.f32.bf16.bf16.f32 " \
                 "{%0,%1,%2,%3}, {%4,%5,%6,%7}, {%8,%9}, {%0,%1,%2,%3};" \
                 : "+f"((d)[0]), "+f"((d)[1]), "+f"((d)[2]), "+f"((d)[3]) \
                 : "r"((a)[0]), "r"((a)[1]), "r"((a)[2]), "r"((a)[3]), "r"(b0), "r"(b1))

// ================= scratch =================
__device__ float g_q   [(size_t)MM*HH*HD];
__device__ float g_k   [(size_t)MM*KVHN*HD];
__device__ float g_v   [(size_t)MM*KVHN*HD];
__device__ float g_sc  [(size_t)BB*HH*SS*SS];
__device__ float g_tmp [(size_t)MM*DD];
__device__ float g_x2  [(size_t)MM*DD];
__device__ float g_gate[(size_t)MM*FFN];
__device__ float g_up  [(size_t)MM*FFN];
__device__ float g_ffn [(size_t)MM*DD];
__device__ __nv_bfloat16 g_ah[(size_t)MM*FFN];
__device__ __nv_bfloat16 g_al[(size_t)MM*FFN];
__device__ __nv_bfloat16 g_wqh[(size_t)HH*HD*DD],  g_wql[(size_t)HH*HD*DD];
__device__ __nv_bfloat16 g_wkh[(size_t)KVHN*HD*DD],g_wkl[(size_t)KVHN*HD*DD];
__device__ __nv_bfloat16 g_wvh[(size_t)KVHN*HD*DD],g_wvl[(size_t)KVHN*HD*DD];
__device__ __nv_bfloat16 g_woh[(size_t)DD*HH*HD],  g_wol[(size_t)DD*HH*HD];
__device__ __nv_bfloat16 g_wgh[(size_t)FFN*DD],    g_wgl[(size_t)FFN*DD];
__device__ __nv_bfloat16 g_wuh[(size_t)FFN*DD],    g_wul[(size_t)FFN*DD];
__device__ __nv_bfloat16 g_wdh[(size_t)DD*FFN],    g_wdl[(size_t)DD*FFN];

__device__ __forceinline__ void split2(float v, __nv_bfloat16& h, __nv_bfloat16& l) {
    h = __float2bfloat16(v);
    l = __float2bfloat16(v - __bfloat162float(h));
}

// ================= weight split =================
__global__ __launch_bounds__(256) void split_kernel(
    const float4* __restrict__ x, __nv_bfloat162* __restrict__ hi,
    __nv_bfloat162* __restrict__ lo, int n4)
{
    int i = blockIdx.x * 256 + threadIdx.x;
    if (i < n4) {
        float4 v = x[i];
        __nv_bfloat162 a, b, c, d;
        split2(v.x, a.x, c.x); split2(v.y, a.y, c.y);
        split2(v.z, b.x, d.x); split2(v.w, b.y, d.y);
        hi[2*i] = a; hi[2*i+1] = b; lo[2*i] = c; lo[2*i+1] = d;
    }
}

// ================= RMSNorm =================
__global__ __launch_bounds__(256) void rmsnorm_kernel(
    const float* __restrict__ in, const float* __restrict__ scale,
    const float* __restrict__ resid, const float* __restrict__ lsc,
    float* __restrict__ out, __nv_bfloat16* __restrict__ oh,
    __nv_bfloat16* __restrict__ ol, int N)
{
    __shared__ float red[8];
    const size_t row = blockIdx.x;
    const float* x = in + row * (size_t)N;
    float ss = 0.f;
    for (int j = threadIdx.x; j < N; j += 256) { float v = x[j]; ss = fmaf(v, v, ss); }
    int lane = threadIdx.x & 31, wid = threadIdx.x >> 5;
    #pragma unroll
    for (int o = 16; o > 0; o >>= 1) ss += __shfl_down_sync(0xffffffffu, ss, o);
    if (lane == 0) red[wid] = ss;
    __syncthreads();
    if (threadIdx.x == 0) {
        float s = 0.f;
        #pragma unroll
        for (int w = 0; w < 8; w++) s += red[w];
        red[0] = s;
    }
    __syncthreads();
    const float r = rsqrtf(red[0] / (float)N + EPS_RMS);
    const float ls = lsc ? lsc[0] : 1.f;
    const float* rp = resid ? resid + row * (size_t)N : nullptr;
    for (int j = threadIdx.x; j < N; j += 256) {
        float v = x[j] * r;
        if (scale) v *= scale[j];
        if (rp) v += rp[j];
        v *= ls;
        if (out) out[row * (size_t)N + j] = v;
        if (oh) {
            __nv_bfloat16 h, l; split2(v, h, l);
            oh[row * (size_t)N + j] = h; ol[row * (size_t)N + j] = l;
        }
    }
}

// ================= per-head RMSNorm (+ RoPE) =================
__global__ __launch_bounds__(128) void headnorm_rope_kernel(
    float* __restrict__ data, const float* __restrict__ scale,
    const int* __restrict__ positions, int nheads, int do_rope)
{
    __shared__ float red[4];
    __shared__ float sv[HD];
    const int d = threadIdx.x;
    const int idx = blockIdx.x;
    const int token = idx / nheads;
    float* p = data + (size_t)idx * HD;
    float v = p[d];
    float ss = v * v;
    int lane = d & 31, wid = d >> 5;
    #pragma unroll
    for (int o = 16; o > 0; o >>= 1) ss += __shfl_down_sync(0xffffffffu, ss, o);
    if (lane == 0) red[wid] = ss;
    __syncthreads();
    const float total = red[0] + red[1] + red[2] + red[3];
    const float r = rsqrtf(total * (1.0f / HD) + EPS_RMS);
    float nv = v * r;
    if (scale) nv *= scale[d];
    if (do_rope) {
        sv[d] = nv;
        __syncthreads();
        if (d < 64) {
            const int pos = positions[token];
            double freq = pow(10000.0, -((double)(2 * d) / 128.0));
            double ang = (double)pos * freq;
            double dsin, dcos;
            sincos(ang, &dsin, &dcos);
            float c = (float)dcos, s = (float)dsin;
            float x1 = sv[d], x2 = sv[d + 64];
            p[d]      = x1 * c - x2 * s;
            p[d + 64] = x2 * c + x1 * s;
        }
    } else {
        p[d] = nv;
    }
}

// ================= HMMA bf16x3 GEMM: C[M,N] = A[M,K] * B[N,K]^T =================
// CTA 256x128, 16 warps (4x4), warp tile 64x32, K-chunk 32, 3-stage cp.async.
// Inner loop issues the 3 split terms in WAVES (hh x4, hl x4, lh x4) so each
// accumulator's dependent HMMAs are separated by 3 independent ones.
#define ROW2  80                     // 32 bf16 = 64B data + 16B pad
#define APART (256 * ROW2)           // 20480
#define BPART (128 * ROW2)           // 10240
#define STG2  (2 * APART + 2 * BPART)// 61440
#define GSMEM2 (3 * STG2)            // 184320

__global__ __launch_bounds__(512, 1) void gemm_mma(
    const __nv_bfloat16* __restrict__ Ah, const __nv_bfloat16* __restrict__ Al,
    const __nv_bfloat16* __restrict__ Bh, const __nv_bfloat16* __restrict__ Bl,
    float* __restrict__ C, int M, int N, int K)
{
    extern __shared__ __align__(128) char smem[];
    const uint32_t sb = smem_to_u32(smem);
    const int tid = threadIdx.x;
    const int wid = tid >> 5, lane = tid & 31;
    const int wm = wid >> 2, wn = wid & 3;          // 4 x 4 warp grid
    const int m0 = blockIdx.y * 256, n0 = blockIdx.x * 128;

    const int arow = tid >> 1;
    const int acs  = (tid & 1) * 2;
    const int brow = tid >> 2;
    const int bcs  = tid & 3;
    const __nv_bfloat16* gAh = Ah + (size_t)(m0 + arow) * K + acs * 8;
    const __nv_bfloat16* gAl = Al + (size_t)(m0 + arow) * K + acs * 8;
    const __nv_bfloat16* gBh = Bh + (size_t)(n0 + brow) * K + bcs * 8;
    const __nv_bfloat16* gBl = Bl + (size_t)(n0 + brow) * K + bcs * 8;
    const uint32_t aS = (uint32_t)(arow * ROW2 + acs * 16);
    const uint32_t bS = (uint32_t)(brow * ROW2 + bcs * 16);

    const int nch = K / 32;

    auto issue = [&](int c) {
        const uint32_t st = sb + (uint32_t)(c % 3) * STG2;
        const size_t ko = (size_t)c * 32;
        CP_ASYNC16(st + aS,                 gAh + ko);
        CP_ASYNC16(st + aS + 16,            gAh + ko + 8);
        CP_ASYNC16(st + APART + aS,         gAl + ko);
        CP_ASYNC16(st + APART + aS + 16,    gAl + ko + 8);
        CP_ASYNC16(st + 2 * APART + bS,         gBh + ko);
        CP_ASYNC16(st + 2 * APART + BPART + bS, gBl + ko);
    };

    issue(0); CP_COMMIT();
    issue(1); CP_COMMIT();

    const uint32_t aOff = (uint32_t)((wm * 64 + (lane & 15)) * ROW2 + (lane >> 4) * 16);
    const uint32_t bOff = (uint32_t)((wn * 32 + ((lane & 7) | ((lane >> 4) << 3))) * ROW2
                                     + ((lane >> 3) & 1) * 16);

    float acc[4][4][4];
    #pragma unroll
    for (int i = 0; i < 4; i++)
        #pragma unroll
        for (int j = 0; j < 4; j++)
            #pragma unroll
            for (int q = 0; q < 4; q++) acc[i][j][q] = 0.f;

    for (int c = 0; c < nch; ++c) {
        if (c + 1 < nch) { CP_WAIT(1); } else { CP_WAIT(0); }
        __syncthreads();
        if (c + 2 < nch) { issue(c + 2); CP_COMMIT(); }

        const uint32_t st = sb + (uint32_t)(c % 3) * STG2;
        const uint32_t aH = st + aOff;
        const uint32_t aL = aH + APART;
        const uint32_t bH = st + 2 * APART + bOff;
        const uint32_t bL = bH + BPART;

        #pragma unroll
        for (int ks = 0; ks < 2; ks++) {
            uint32_t bh[2][4], bl[2][4];
            #pragma unroll
            for (int np = 0; np < 2; np++) {
                const uint32_t o = (uint32_t)(np * 16 * ROW2 + ks * 32);
                LDSM_X4(bh[np][0], bh[np][1], bh[np][2], bh[np][3], bH + o);
                LDSM_X4(bl[np][0], bl[np][1], bl[np][2], bl[np][3], bL + o);
            }
            #pragma unroll
            for (int mi = 0; mi < 4; mi++) {
                uint32_t ah[4], al[4];
                const uint32_t o = (uint32_t)(mi * 16 * ROW2 + ks * 32);
                LDSM_X4(ah[0], ah[1], ah[2], ah[3], aH + o);
                LDSM_X4(al[0], al[1], al[2], al[3], aL + o);
                // wave 1: hi*hi into all 4 accumulators (independent chains)
                #pragma unroll
                for (int np = 0; np < 2; np++)
                    #pragma unroll
                    for (int hf = 0; hf < 2; hf++)
                        MMA16816(acc[mi][np * 2 + hf], ah, bh[np][hf * 2], bh[np][hf * 2 + 1]);
                // wave 2: hi*lo
                #pragma unroll
                for (int np = 0; np < 2; np++)
                    #pragma unroll
                    for (int hf = 0; hf < 2; hf++)
                        MMA16816(acc[mi][np * 2 + hf], ah, bl[np][hf * 2], bl[np][hf * 2 + 1]);
                // wave 3: lo*hi
                #pragma unroll
                for (int np = 0; np < 2; np++)
                    #pragma unroll
                    for (int hf = 0; hf < 2; hf++)
                        MMA16816(acc[mi][np * 2 + hf], al, bh[np][hf * 2], bh[np][hf * 2 + 1]);
            }
        }
    }

    // epilogue
    #pragma unroll
    for (int mi = 0; mi < 4; mi++) {
        const int r = m0 + wm * 64 + mi * 16 + (lane >> 2);
        #pragma unroll
        for (int ni = 0; ni < 4; ni++) {
            const int cc = n0 + wn * 32 + ni * 8 + (lane & 3) * 2;
            *(float2*)&C[(size_t)r * N + cc]       = make_float2(acc[mi][ni][0], acc[mi][ni][1]);
            *(float2*)&C[(size_t)(r + 8) * N + cc] = make_float2(acc[mi][ni][2], acc[mi][ni][3]);
        }
    }
}

// ================= attention scores =================
__global__ __launch_bounds__(256) void attn_scores_kernel(
    const float* __restrict__ q, const float* __restrict__ k, float* __restrict__ sc)
{
    const int bh = blockIdx.z;
    const int b = bh >> 4;
    const int h = bh & 15;
    const int i0 = blockIdx.y * 64, j0 = blockIdx.x * 64;
    const int tid = threadIdx.x;
    const int tx = tid & 15, ty = tid >> 4;
    float* Cb = sc + (size_t)bh * SS * SS;
    if (j0 > i0 + 63) {
        float4 m4 = make_float4(KMASK, KMASK, KMASK, KMASK);
        #pragma unroll
        for (int ii = 0; ii < 4; ii++)
            *(float4*)(Cb + (size_t)(i0 + ty * 4 + ii) * SS + j0 + tx * 4) = m4;
        return;
    }
    __shared__ float Qs[8][64];
    __shared__ float Ks[8][64];
    const float* Q  = q + (size_t)b * SS * HH * HD + (size_t)h * HD;
    const float* Kp = k + (size_t)b * SS * KVHN * HD + (size_t)(h >> 1) * HD;
    const int lrow = tid >> 2;
    const int lk = (tid & 3) * 2;
    float acc[4][4];
    #pragma unroll
    for (int i = 0; i < 4; i++)
        #pragma unroll
        for (int j = 0; j < 4; j++) acc[i][j] = 0.f;
    for (int kc = 0; kc < HD; kc += 8) {
        float2 qa = *(const float2*)(Q  + (size_t)(i0 + lrow) * (HH * HD)   + kc + lk);
        float2 ka = *(const float2*)(Kp + (size_t)(j0 + lrow) * (KVHN * HD) + kc + lk);
        Qs[lk][lrow] = qa.x; Qs[lk + 1][lrow] = qa.y;
        Ks[lk][lrow] = ka.x; Ks[lk + 1][lrow] = ka.y;
        __syncthreads();
        #pragma unroll
        for (int kk = 0; kk < 8; kk++) {
            float a[4], bb2[4];
            *(float4*)a   = *(const float4*)&Qs[kk][ty * 4];
            *(float4*)bb2 = *(const float4*)&Ks[kk][tx * 4];
            #pragma unroll
            for (int i = 0; i < 4; i++)
                #pragma unroll
                for (int j = 0; j < 4; j++) acc[i][j] = fmaf(a[i], bb2[j], acc[i][j]);
        }
        __syncthreads();
    }
    #pragma unroll
    for (int ii = 0; ii < 4; ii++) {
        const int i = i0 + ty * 4 + ii;
        float vals[4];
        #pragma unroll
        for (int jj = 0; jj < 4; jj++) {
            const int j = j0 + tx * 4 + jj;
            float s = tanhf(acc[ii][jj] * 0.02f) * 50.f;
            vals[jj] = (j <= i) ? s : KMASK;
        }
        *(float4*)(Cb + (size_t)i * SS + j0 + tx * 4) =
            make_float4(vals[0], vals[1], vals[2], vals[3]);
    }
}

// ================= row softmax =================
__global__ __launch_bounds__(256) void softmax_kernel(float* __restrict__ sc)
{
    __shared__ float red[8];
    float* p = sc + (size_t)blockIdx.x * SS;
    const int lane = threadIdx.x & 31, wid = threadIdx.x >> 5;
    float m = -3.4e38f;
    for (int j = threadIdx.x; j < SS; j += 256) m = fmaxf(m, p[j]);
    #pragma unroll
    for (int o = 16; o > 0; o >>= 1) m = fmaxf(m, __shfl_down_sync(0xffffffffu, m, o));
    if (lane == 0) red[wid] = m;
    __syncthreads();
    if (threadIdx.x == 0) {
        float s = red[0];
        #pragma unroll
        for (int w = 1; w < 8; w++) s = fmaxf(s, red[w]);
        red[0] = s;
    }
    __syncthreads();
    m = red[0];
    __syncthreads();
    float sum = 0.f;
    for (int j = threadIdx.x; j < SS; j += 256) {
        float e = __expf(p[j] - m);
        p[j] = e;
        sum += e;
    }
    #pragma unroll
    for (int o = 16; o > 0; o >>= 1) sum += __shfl_down_sync(0xffffffffu, sum, o);
    if (lane == 0) red[wid] = sum;
    __syncthreads();
    if (threadIdx.x == 0) {
        float s = 0.f;
        #pragma unroll
        for (int w = 0; w < 8; w++) s += red[w];
        red[0] = s;
    }
    __syncthreads();
    const float inv = 1.f / red[0];
    for (int j = threadIdx.x; j < SS; j += 256) p[j] *= inv;
}

// ================= P·V -> bf16 hi/lo =================
__global__ __launch_bounds__(256) void attn_pv_kernel(
    const float* __restrict__ probs, const float* __restrict__ v,
    __nv_bfloat16* __restrict__ Oh, __nv_bfloat16* __restrict__ Ol)
{
    const int bh = blockIdx.z;
    const int b = bh >> 4;
    const int h = bh & 15;
    const int i0 = blockIdx.y * 64, d0 = blockIdx.x * 64;
    const float* P = probs + (size_t)bh * SS * SS;
    const float* V = v + (size_t)b * SS * KVHN * HD + (size_t)(h >> 1) * HD;
    const size_t obase = (size_t)b * SS * HH * HD + (size_t)h * HD;
    __shared__ float Ps_[8][64];
    __shared__ float Vs[8][64];
    const int tid = threadIdx.x;
    const int tx = tid & 15, ty = tid >> 4;
    const int prow = tid >> 2, pk = (tid & 3) * 2;
    const int vrow = tid >> 5, vcol = (tid & 31) * 2;
    float acc[4][4];
    #pragma unroll
    for (int i = 0; i < 4; i++)
        #pragma unroll
        for (int j = 0; j < 4; j++) acc[i][j] = 0.f;
    const int kend = i0 + 64;
    for (int kc = 0; kc < kend; kc += 8) {
        float2 pa = *(const float2*)(P + (size_t)(i0 + prow) * SS + kc + pk);
        float2 va = *(const float2*)(V + (size_t)(kc + vrow) * (KVHN * HD) + d0 + vcol);
        Ps_[pk][prow] = pa.x; Ps_[pk + 1][prow] = pa.y;
        Vs[vrow][vcol] = va.x; Vs[vrow][vcol + 1] = va.y;
        __syncthreads();
        #pragma unroll
        for (int kk = 0; kk < 8; kk++) {
            float a[4], bb2[4];
            *(float4*)a   = *(const float4*)&Ps_[kk][ty * 4];
            *(float4*)bb2 = *(const float4*)&Vs[kk][tx * 4];
            #pragma unroll
            for (int i = 0; i < 4; i++)
                #pragma unroll
                for (int j = 0; j < 4; j++) acc[i][j] = fmaf(a[i], bb2[j], acc[i][j]);
        }
        __syncthreads();
    }
    #pragma unroll
    for (int ii = 0; ii < 4; ii++) {
        const size_t off = obase + (size_t)(i0 + ty * 4 + ii) * (HH * HD) + d0 + tx * 4;
        __nv_bfloat162 h01, h23, l01, l23;
        split2(acc[ii][0], h01.x, l01.x); split2(acc[ii][1], h01.y, l01.y);
        split2(acc[ii][2], h23.x, l23.x); split2(acc[ii][3], h23.y, l23.y);
        *(__nv_bfloat162*)(Oh + off)     = h01;
        *(__nv_bfloat162*)(Oh + off + 2) = h23;
        *(__nv_bfloat162*)(Ol + off)     = l01;
        *(__nv_bfloat162*)(Ol + off + 2) = l23;
    }
}

// ================= GeGLU -> bf16 hi/lo =================
__global__ __launch_bounds__(256) void geglu_kernel(
    const float* __restrict__ gate, const float* __restrict__ up,
    __nv_bfloat16* __restrict__ oh, __nv_bfloat16* __restrict__ ol, size_t n)
{
    size_t i = (size_t)blockIdx.x * 256 + threadIdx.x;
    if (i < n) {
        float x = gate[i];
        float t = 0.7978845608028654f * (x + 0.044715f * x * x * x);
        float g = 0.5f * x * (1.f + tanhf(t));
        float r = g * up[i];
        __nv_bfloat16 h, l; split2(r, h, l);
        oh[i] = h; ol[i] = l;
    }
}

// ================= launch =================
static inline void run_split(const float* w, __nv_bfloat16* h, __nv_bfloat16* l, size_t n) {
    int n4 = (int)(n / 4);
    split_kernel<<<(n4 + 255) / 256, 256>>>((const float4*)w, (__nv_bfloat162*)h,
                                            (__nv_bfloat162*)l, n4);
}

extern "C" void kernel_launch(void* const* d_in, const int* in_sizes, int n_in,
                              void* d_out, int out_size)
{
    const float* x          = (const float*)d_in[0];
    const int*   positions  = (const int*)  d_in[1];
    const float* wq         = (const float*)d_in[4];
    const float* wk         = (const float*)d_in[5];
    const float* wv         = (const float*)d_in[6];
    const float* wo         = (const float*)d_in[7];
    const float* q_scale    = (const float*)d_in[8];
    const float* k_scale    = (const float*)d_in[9];
    const float* pre_attn   = (const float*)d_in[10];
    const float* post_attn  = (const float*)d_in[11];
    const float* pre_ffn    = (const float*)d_in[12];
    const float* post_ffn   = (const float*)d_in[13];
    const float* w_gate     = (const float*)d_in[14];
    const float* w_up       = (const float*)d_in[15];
    const float* w_down     = (const float*)d_in[16];
    const float* layer_scal = (const float*)d_in[17];
    float* out = (float*)d_out;

    float *q_, *k_, *v_, *sc_, *tmp_, *x2_, *gate_, *up_, *ffn_;
    __nv_bfloat16 *ah_, *al_;
    __nv_bfloat16 *wqh, *wql, *wkh, *wkl, *wvh, *wvl, *woh, *wol, *wgh, *wgl, *wuh, *wul, *wdh, *wdl;
    cudaGetSymbolAddress((void**)&q_,   g_q);
    cudaGetSymbolAddress((void**)&k_,   g_k);
    cudaGetSymbolAddress((void**)&v_,   g_v);
    cudaGetSymbolAddress((void**)&sc_,  g_sc);
    cudaGetSymbolAddress((void**)&tmp_, g_tmp);
    cudaGetSymbolAddress((void**)&x2_,  g_x2);
    cudaGetSymbolAddress((void**)&gate_,g_gate);
    cudaGetSymbolAddress((void**)&up_,  g_up);
    cudaGetSymbolAddress((void**)&ffn_, g_ffn);
    cudaGetSymbolAddress((void**)&ah_,  g_ah);
    cudaGetSymbolAddress((void**)&al_,  g_al);
    cudaGetSymbolAddress((void**)&wqh, g_wqh); cudaGetSymbolAddress((void**)&wql, g_wql);
    cudaGetSymbolAddress((void**)&wkh, g_wkh); cudaGetSymbolAddress((void**)&wkl, g_wkl);
    cudaGetSymbolAddress((void**)&wvh, g_wvh); cudaGetSymbolAddress((void**)&wvl, g_wvl);
    cudaGetSymbolAddress((void**)&woh, g_woh); cudaGetSymbolAddress((void**)&wol, g_wol);
    cudaGetSymbolAddress((void**)&wgh, g_wgh); cudaGetSymbolAddress((void**)&wgl, g_wgl);
    cudaGetSymbolAddress((void**)&wuh, g_wuh); cudaGetSymbolAddress((void**)&wul, g_wul);
    cudaGetSymbolAddress((void**)&wdh, g_wdh); cudaGetSymbolAddress((void**)&wdl, g_wdl);

    cudaFuncSetAttribute(gemm_mma, cudaFuncAttributeMaxDynamicSharedMemorySize, GSMEM2);

    // weight splits
    run_split(wq,     wqh, wql, (size_t)HH * HD * DD);
    run_split(wk,     wkh, wkl, (size_t)KVHN * HD * DD);
    run_split(wv,     wvh, wvl, (size_t)KVHN * HD * DD);
    run_split(wo,     woh, wol, (size_t)DD * HH * HD);
    run_split(w_gate, wgh, wgl, (size_t)FFN * DD);
    run_split(w_up,   wuh, wul, (size_t)FFN * DD);
    run_split(w_down, wdh, wdl, (size_t)DD * FFN);

    // ---- attention sub-block ----
    rmsnorm_kernel<<<MM, 256>>>(x, pre_attn, nullptr, nullptr, nullptr, ah_, al_, DD);
    gemm_mma<<<dim3((HH*HD)/128,   MM/256), 512, GSMEM2>>>(ah_, al_, wqh, wql, q_, MM, HH*HD,   DD);
    gemm_mma<<<dim3((KVHN*HD)/128, MM/256), 512, GSMEM2>>>(ah_, al_, wkh, wkl, k_, MM, KVHN*HD, DD);
    gemm_mma<<<dim3((KVHN*HD)/128, MM/256), 512, GSMEM2>>>(ah_, al_, wvh, wvl, v_, MM, KVHN*HD, DD);
    headnorm_rope_kernel<<<MM * HH,   128>>>(q_, q_scale, positions, HH,   1);
    headnorm_rope_kernel<<<MM * KVHN, 128>>>(k_, k_scale, positions, KVHN, 1);
    headnorm_rope_kernel<<<MM * KVHN, 128>>>(v_, nullptr, positions, KVHN, 0);
    attn_scores_kernel<<<dim3(SS/64, SS/64, BB*HH), 256>>>(q_, k_, sc_);
    softmax_kernel<<<BB * HH * SS, 256>>>(sc_);
    attn_pv_kernel<<<dim3(HD/64, SS/64, BB*HH), 256>>>(sc_, v_, ah_, al_);
    gemm_mma<<<dim3(DD/128, MM/256), 512, GSMEM2>>>(ah_, al_, woh, wol, tmp_, MM, DD, HH*HD);
    rmsnorm_kernel<<<MM, 256>>>(tmp_, post_attn, x, nullptr, x2_, nullptr, nullptr, DD);

    // ---- FFN sub-block ----
    rmsnorm_kernel<<<MM, 256>>>(x2_, pre_ffn, nullptr, nullptr, nullptr, ah_, al_, DD);
    gemm_mma<<<dim3(FFN/128, MM/256), 512, GSMEM2>>>(ah_, al_, wgh, wgl, gate_, MM, FFN, DD);
    gemm_mma<<<dim3(FFN/128, MM/256), 512, GSMEM2>>>(ah_, al_, wuh, wul, up_,   MM, FFN, DD);
    size_t nact = (size_t)MM * FFN;
    geglu_kernel<<<(unsigned)((nact + 255) / 256), 256>>>(gate_, up_, ah_, al_, nact);
    gemm_mma<<<dim3(DD/128, MM/256), 512, GSMEM2>>>(ah_, al_, wdh, wdl, ffn_, MM, DD, FFN);
    rmsnorm_kernel<<<MM, 256>>>(ffn_, post_ffn, x2_, layer_scal, out, nullptr, nullptr, DD);
}

// round 9
// speedup vs baseline: 1.0000x; 1.0000x over previous
#include <cuda_runtime.h>
#include <cuda_bf16.h>
#include <cstdint>
#include <math.h>

#define BB 4
#define SS 1024
#define DD 2048
#define HH 16
#define KVHN 8
#define HD 128
#define FFN 8192
#define MM (BB*SS)
#define EPS_RMS 1e-6f
#define KMASK -1e30f

// ================= PTX helpers (base sm_103 ISA only) =================
__device__ __forceinline__ uint32_t smem_to_u32(const void* p) {
    uint32_t a;
    asm("{ .reg .u64 t; cvta.to.shared.u64 t, %1; cvt.u32.u64 %0, t; }" : "=r"(a) : "l"(p));
    return a;
}
#define CP_ASYNC16(sa, gp) \
    asm volatile("cp.async.cg.shared.global [%0], [%1], 16;" :: "r"(sa), "l"(gp) : "memory")
#define CP_COMMIT() asm volatile("cp.async.commit_group;" ::: "memory")
#define CP_WAIT(n)  asm volatile("cp.async.wait_group %0;" :: "n"(n) : "memory")

#define LDSM_X4(r0, r1, r2, r3, sa) \
    asm volatile("ldmatrix.sync.aligned.m8n8.x4.shared.b16 {%0,%1,%2,%3}, [%4];" \
                 : "=r"(r0), "=r"(r1), "=r"(r2), "=r"(r3) : "r"(sa))

#define MMA16816(d, a, b0, b1) \
    asm volatile("mma.sync.aligned.m16n8k16.row.col.f32.bf16.bf16.f32 " \
                 "{%0,%1,%2,%3}, {%4,%5,%6,%7}, {%8,%9}, {%0,%1,%2,%3};" \
                 : "+f"((d)[0]), "+f"((d)[1]), "+f"((d)[2]), "+f"((d)[3]) \
                 : "r"((a)[0]), "r"((a)[1]), "r"((a)[2]), "r"((a)[3]), "r"(b0), "r"(b1))

// ================= scratch =================
__device__ float g_q   [(size_t)MM*HH*HD];
__device__ float g_k   [(size_t)MM*KVHN*HD];
__device__ float g_v   [(size_t)MM*KVHN*HD];
__device__ float g_sc  [(size_t)BB*HH*SS*SS];
__device__ float g_tmp [(size_t)MM*DD];
__device__ float g_x2  [(size_t)MM*DD];
__device__ float g_gate[(size_t)MM*FFN];
__device__ float g_up  [(size_t)MM*FFN];
__device__ float g_ffn [(size_t)MM*DD];
__device__ __nv_bfloat16 g_ah[(size_t)MM*FFN];
__device__ __nv_bfloat16 g_al[(size_t)MM*FFN];
__device__ __nv_bfloat16 g_wqh[(size_t)HH*HD*DD],  g_wql[(size_t)HH*HD*DD];
__device__ __nv_bfloat16 g_wkh[(size_t)KVHN*HD*DD],g_wkl[(size_t)KVHN*HD*DD];
__device__ __nv_bfloat16 g_wvh[(size_t)KVHN*HD*DD],g_wvl[(size_t)KVHN*HD*DD];
__device__ __nv_bfloat16 g_woh[(size_t)DD*HH*HD],  g_wol[(size_t)DD*HH*HD];
__device__ __nv_bfloat16 g_wgh[(size_t)FFN*DD],    g_wgl[(size_t)FFN*DD];
__device__ __nv_bfloat16 g_wuh[(size_t)FFN*DD],    g_wul[(size_t)FFN*DD];
__device__ __nv_bfloat16 g_wdh[(size_t)DD*FFN],    g_wdl[(size_t)DD*FFN];

__device__ __forceinline__ void split2(float v, __nv_bfloat16& h, __nv_bfloat16& l) {
    h = __float2bfloat16(v);
    l = __float2bfloat16(v - __bfloat162float(h));
}

// ================= weight split =================
__global__ __launch_bounds__(256) void split_kernel(
    const float4* __restrict__ x, __nv_bfloat162* __restrict__ hi,
    __nv_bfloat162* __restrict__ lo, int n4)
{
    int i = blockIdx.x * 256 + threadIdx.x;
    if (i < n4) {
        float4 v = x[i];
        __nv_bfloat162 a, b, c, d;
        split2(v.x, a.x, c.x); split2(v.y, a.y, c.y);
        split2(v.z, b.x, d.x); split2(v.w, b.y, d.y);
        hi[2*i] = a; hi[2*i+1] = b; lo[2*i] = c; lo[2*i+1] = d;
    }
}

// ================= RMSNorm =================
__global__ __launch_bounds__(256) void rmsnorm_kernel(
    const float* __restrict__ in, const float* __restrict__ scale,
    const float* __restrict__ resid, const float* __restrict__ lsc,
    float* __restrict__ out, __nv_bfloat16* __restrict__ oh,
    __nv_bfloat16* __restrict__ ol, int N)
{
    __shared__ float red[8];
    const size_t row = blockIdx.x;
    const float* x = in + row * (size_t)N;
    float ss = 0.f;
    for (int j = threadIdx.x; j < N; j += 256) { float v = x[j]; ss = fmaf(v, v, ss); }
    int lane = threadIdx.x & 31, wid = threadIdx.x >> 5;
    #pragma unroll
    for (int o = 16; o > 0; o >>= 1) ss += __shfl_down_sync(0xffffffffu, ss, o);
    if (lane == 0) red[wid] = ss;
    __syncthreads();
    if (threadIdx.x == 0) {
        float s = 0.f;
        #pragma unroll
        for (int w = 0; w < 8; w++) s += red[w];
        red[0] = s;
    }
    __syncthreads();
    const float r = rsqrtf(red[0] / (float)N + EPS_RMS);
    const float ls = lsc ? lsc[0] : 1.f;
    const float* rp = resid ? resid + row * (size_t)N : nullptr;
    for (int j = threadIdx.x; j < N; j += 256) {
        float v = x[j] * r;
        if (scale) v *= scale[j];
        if (rp) v += rp[j];
        v *= ls;
        if (out) out[row * (size_t)N + j] = v;
        if (oh) {
            __nv_bfloat16 h, l; split2(v, h, l);
            oh[row * (size_t)N + j] = h; ol[row * (size_t)N + j] = l;
        }
    }
}

// ================= per-head RMSNorm (+ RoPE) =================
__global__ __launch_bounds__(128) void headnorm_rope_kernel(
    float* __restrict__ data, const float* __restrict__ scale,
    const int* __restrict__ positions, int nheads, int do_rope)
{
    __shared__ float red[4];
    __shared__ float sv[HD];
    const int d = threadIdx.x;
    const int idx = blockIdx.x;
    const int token = idx / nheads;
    float* p = data + (size_t)idx * HD;
    float v = p[d];
    float ss = v * v;
    int lane = d & 31, wid = d >> 5;
    #pragma unroll
    for (int o = 16; o > 0; o >>= 1) ss += __shfl_down_sync(0xffffffffu, ss, o);
    if (lane == 0) red[wid] = ss;
    __syncthreads();
    const float total = red[0] + red[1] + red[2] + red[3];
    const float r = rsqrtf(total * (1.0f / HD) + EPS_RMS);
    float nv = v * r;
    if (scale) nv *= scale[d];
    if (do_rope) {
        sv[d] = nv;
        __syncthreads();
        if (d < 64) {
            const int pos = positions[token];
            double freq = pow(10000.0, -((double)(2 * d) / 128.0));
            double ang = (double)pos * freq;
            double dsin, dcos;
            sincos(ang, &dsin, &dcos);
            float c = (float)dcos, s = (float)dsin;
            float x1 = sv[d], x2 = sv[d + 64];
            p[d]      = x1 * c - x2 * s;
            p[d + 64] = x2 * c + x1 * s;
        }
    } else {
        p[d] = nv;
    }
}

// ================= HMMA bf16x3 GEMM: C[M,N] = A[M,K] * B[N,K]^T =================
// CTA 256x128, 16 warps (4x4), warp tile 64x32, K-chunk 32, 3-stage cp.async.
// Inner loop issues the 3 split terms in WAVES (hh x4, hl x4, lh x4) so each
// accumulator's dependent HMMAs are separated by 3 independent ones.
#define ROW2  80                     // 32 bf16 = 64B data + 16B pad
#define APART (256 * ROW2)           // 20480
#define BPART (128 * ROW2)           // 10240
#define STG2  (2 * APART + 2 * BPART)// 61440
#define GSMEM2 (3 * STG2)            // 184320

__global__ __launch_bounds__(512, 1) void gemm_mma(
    const __nv_bfloat16* __restrict__ Ah, const __nv_bfloat16* __restrict__ Al,
    const __nv_bfloat16* __restrict__ Bh, const __nv_bfloat16* __restrict__ Bl,
    float* __restrict__ C, int M, int N, int K)
{
    extern __shared__ __align__(128) char smem[];
    const uint32_t sb = smem_to_u32(smem);
    const int tid = threadIdx.x;
    const int wid = tid >> 5, lane = tid & 31;
    const int wm = wid >> 2, wn = wid & 3;          // 4 x 4 warp grid
    const int m0 = blockIdx.y * 256, n0 = blockIdx.x * 128;

    const int arow = tid >> 1;
    const int acs  = (tid & 1) * 2;
    const int brow = tid >> 2;
    const int bcs  = tid & 3;
    const __nv_bfloat16* gAh = Ah + (size_t)(m0 + arow) * K + acs * 8;
    const __nv_bfloat16* gAl = Al + (size_t)(m0 + arow) * K + acs * 8;
    const __nv_bfloat16* gBh = Bh + (size_t)(n0 + brow) * K + bcs * 8;
    const __nv_bfloat16* gBl = Bl + (size_t)(n0 + brow) * K + bcs * 8;
    const uint32_t aS = (uint32_t)(arow * ROW2 + acs * 16);
    const uint32_t bS = (uint32_t)(brow * ROW2 + bcs * 16);

    const int nch = K / 32;

    auto issue = [&](int c) {
        const uint32_t st = sb + (uint32_t)(c % 3) * STG2;
        const size_t ko = (size_t)c * 32;
        CP_ASYNC16(st + aS,                 gAh + ko);
        CP_ASYNC16(st + aS + 16,            gAh + ko + 8);
        CP_ASYNC16(st + APART + aS,         gAl + ko);
        CP_ASYNC16(st + APART + aS + 16,    gAl + ko + 8);
        CP_ASYNC16(st + 2 * APART + bS,         gBh + ko);
        CP_ASYNC16(st + 2 * APART + BPART + bS, gBl + ko);
    };

    issue(0); CP_COMMIT();
    issue(1); CP_COMMIT();

    const uint32_t aOff = (uint32_t)((wm * 64 + (lane & 15)) * ROW2 + (lane >> 4) * 16);
    const uint32_t bOff = (uint32_t)((wn * 32 + ((lane & 7) | ((lane >> 4) << 3))) * ROW2
                                     + ((lane >> 3) & 1) * 16);

    float acc[4][4][4];
    #pragma unroll
    for (int i = 0; i < 4; i++)
        #pragma unroll
        for (int j = 0; j < 4; j++)
            #pragma unroll
            for (int q = 0; q < 4; q++) acc[i][j][q] = 0.f;

    for (int c = 0; c < nch; ++c) {
        if (c + 1 < nch) { CP_WAIT(1); } else { CP_WAIT(0); }
        __syncthreads();
        if (c + 2 < nch) { issue(c + 2); CP_COMMIT(); }

        const uint32_t st = sb + (uint32_t)(c % 3) * STG2;
        const uint32_t aH = st + aOff;
        const uint32_t aL = aH + APART;
        const uint32_t bH = st + 2 * APART + bOff;
        const uint32_t bL = bH + BPART;

        #pragma unroll
        for (int ks = 0; ks < 2; ks++) {
            uint32_t bh[2][4], bl[2][4];
            #pragma unroll
            for (int np = 0; np < 2; np++) {
                const uint32_t o = (uint32_t)(np * 16 * ROW2 + ks * 32);
                LDSM_X4(bh[np][0], bh[np][1], bh[np][2], bh[np][3], bH + o);
                LDSM_X4(bl[np][0], bl[np][1], bl[np][2], bl[np][3], bL + o);
            }
            #pragma unroll
            for (int mi = 0; mi < 4; mi++) {
                uint32_t ah[4], al[4];
                const uint32_t o = (uint32_t)(mi * 16 * ROW2 + ks * 32);
                LDSM_X4(ah[0], ah[1], ah[2], ah[3], aH + o);
                LDSM_X4(al[0], al[1], al[2], al[3], aL + o);
                // wave 1: hi*hi into all 4 accumulators (independent chains)
                #pragma unroll
                for (int np = 0; np < 2; np++)
                    #pragma unroll
                    for (int hf = 0; hf < 2; hf++)
                        MMA16816(acc[mi][np * 2 + hf], ah, bh[np][hf * 2], bh[np][hf * 2 + 1]);
                // wave 2: hi*lo
                #pragma unroll
                for (int np = 0; np < 2; np++)
                    #pragma unroll
                    for (int hf = 0; hf < 2; hf++)
                        MMA16816(acc[mi][np * 2 + hf], ah, bl[np][hf * 2], bl[np][hf * 2 + 1]);
                // wave 3: lo*hi
                #pragma unroll
                for (int np = 0; np < 2; np++)
                    #pragma unroll
                    for (int hf = 0; hf < 2; hf++)
                        MMA16816(acc[mi][np * 2 + hf], al, bh[np][hf * 2], bh[np][hf * 2 + 1]);
            }
        }
    }

    // epilogue
    #pragma unroll
    for (int mi = 0; mi < 4; mi++) {
        const int r = m0 + wm * 64 + mi * 16 + (lane >> 2);
        #pragma unroll
        for (int ni = 0; ni < 4; ni++) {
            const int cc = n0 + wn * 32 + ni * 8 + (lane & 3) * 2;
            *(float2*)&C[(size_t)r * N + cc]       = make_float2(acc[mi][ni][0], acc[mi][ni][1]);
            *(float2*)&C[(size_t)(r + 8) * N + cc] = make_float2(acc[mi][ni][2], acc[mi][ni][3]);
        }
    }
}

// ================= attention scores =================
__global__ __launch_bounds__(256) void attn_scores_kernel(
    const float* __restrict__ q, const float* __restrict__ k, float* __restrict__ sc)
{
    const int bh = blockIdx.z;
    const int b = bh >> 4;
    const int h = bh & 15;
    const int i0 = blockIdx.y * 64, j0 = blockIdx.x * 64;
    const int tid = threadIdx.x;
    const int tx = tid & 15, ty = tid >> 4;
    float* Cb = sc + (size_t)bh * SS * SS;
    if (j0 > i0 + 63) {
        float4 m4 = make_float4(KMASK, KMASK, KMASK, KMASK);
        #pragma unroll
        for (int ii = 0; ii < 4; ii++)
            *(float4*)(Cb + (size_t)(i0 + ty * 4 + ii) * SS + j0 + tx * 4) = m4;
        return;
    }
    __shared__ float Qs[8][64];
    __shared__ float Ks[8][64];
    const float* Q  = q + (size_t)b * SS * HH * HD + (size_t)h * HD;
    const float* Kp = k + (size_t)b * SS * KVHN * HD + (size_t)(h >> 1) * HD;
    const int lrow = tid >> 2;
    const int lk = (tid & 3) * 2;
    float acc[4][4];
    #pragma unroll
    for (int i = 0; i < 4; i++)
        #pragma unroll
        for (int j = 0; j < 4; j++) acc[i][j] = 0.f;
    for (int kc = 0; kc < HD; kc += 8) {
        float2 qa = *(const float2*)(Q  + (size_t)(i0 + lrow) * (HH * HD)   + kc + lk);
        float2 ka = *(const float2*)(Kp + (size_t)(j0 + lrow) * (KVHN * HD) + kc + lk);
        Qs[lk][lrow] = qa.x; Qs[lk + 1][lrow] = qa.y;
        Ks[lk][lrow] = ka.x; Ks[lk + 1][lrow] = ka.y;
        __syncthreads();
        #pragma unroll
        for (int kk = 0; kk < 8; kk++) {
            float a[4], bb2[4];
            *(float4*)a   = *(const float4*)&Qs[kk][ty * 4];
            *(float4*)bb2 = *(const float4*)&Ks[kk][tx * 4];
            #pragma unroll
            for (int i = 0; i < 4; i++)
                #pragma unroll
                for (int j = 0; j < 4; j++) acc[i][j] = fmaf(a[i], bb2[j], acc[i][j]);
        }
        __syncthreads();
    }
    #pragma unroll
    for (int ii = 0; ii < 4; ii++) {
        const int i = i0 + ty * 4 + ii;
        float vals[4];
        #pragma unroll
        for (int jj = 0; jj < 4; jj++) {
            const int j = j0 + tx * 4 + jj;
            float s = tanhf(acc[ii][jj] * 0.02f) * 50.f;
            vals[jj] = (j <= i) ? s : KMASK;
        }
        *(float4*)(Cb + (size_t)i * SS + j0 + tx * 4) =
            make_float4(vals[0], vals[1], vals[2], vals[3]);
    }
}

// ================= row softmax =================
__global__ __launch_bounds__(256) void softmax_kernel(float* __restrict__ sc)
{
    __shared__ float red[8];
    float* p = sc + (size_t)blockIdx.x * SS;
    const int lane = threadIdx.x & 31, wid = threadIdx.x >> 5;
    float m = -3.4e38f;
    for (int j = threadIdx.x; j < SS; j += 256) m = fmaxf(m, p[j]);
    #pragma unroll
    for (int o = 16; o > 0; o >>= 1) m = fmaxf(m, __shfl_down_sync(0xffffffffu, m, o));
    if (lane == 0) red[wid] = m;
    __syncthreads();
    if (threadIdx.x == 0) {
        float s = red[0];
        #pragma unroll
        for (int w = 1; w < 8; w++) s = fmaxf(s, red[w]);
        red[0] = s;
    }
    __syncthreads();
    m = red[0];
    __syncthreads();
    float sum = 0.f;
    for (int j = threadIdx.x; j < SS; j += 256) {
        float e = __expf(p[j] - m);
        p[j] = e;
        sum += e;
    }
    #pragma unroll
    for (int o = 16; o > 0; o >>= 1) sum += __shfl_down_sync(0xffffffffu, sum, o);
    if (lane == 0) red[wid] = sum;
    __syncthreads();
    if (threadIdx.x == 0) {
        float s = 0.f;
        #pragma unroll
        for (int w = 0; w < 8; w++) s += red[w];
        red[0] = s;
    }
    __syncthreads();
    const float inv = 1.f / red[0];
    for (int j = threadIdx.x; j < SS; j += 256) p[j] *= inv;
}

// ================= P·V -> bf16 hi/lo =================
__global__ __launch_bounds__(256) void attn_pv_kernel(
    const float* __restrict__ probs, const float* __restrict__ v,
    __nv_bfloat16* __restrict__ Oh, __nv_bfloat16* __restrict__ Ol)
{
    const int bh = blockIdx.z;
    const int b = bh >> 4;
    const int h = bh & 15;
    const int i0 = blockIdx.y * 64, d0 = blockIdx.x * 64;
    const float* P = probs + (size_t)bh * SS * SS;
    const float* V = v + (size_t)b * SS * KVHN * HD + (size_t)(h >> 1) * HD;
    const size_t obase = (size_t)b * SS * HH * HD + (size_t)h * HD;
    __shared__ float Ps_[8][64];
    __shared__ float Vs[8][64];
    const int tid = threadIdx.x;
    const int tx = tid & 15, ty = tid >> 4;
    const int prow = tid >> 2, pk = (tid & 3) * 2;
    const int vrow = tid >> 5, vcol = (tid & 31) * 2;
    float acc[4][4];
    #pragma unroll
    for (int i = 0; i < 4; i++)
        #pragma unroll
        for (int j = 0; j < 4; j++) acc[i][j] = 0.f;
    const int kend = i0 + 64;
    for (int kc = 0; kc < kend; kc += 8) {
        float2 pa = *(const float2*)(P + (size_t)(i0 + prow) * SS + kc + pk);
        float2 va = *(const float2*)(V + (size_t)(kc + vrow) * (KVHN * HD) + d0 + vcol);
        Ps_[pk][prow] = pa.x; Ps_[pk + 1][prow] = pa.y;
        Vs[vrow][vcol] = va.x; Vs[vrow][vcol + 1] = va.y;
        __syncthreads();
        #pragma unroll
        for (int kk = 0; kk < 8; kk++) {
            float a[4], bb2[4];
            *(float4*)a   = *(const float4*)&Ps_[kk][ty * 4];
            *(float4*)bb2 = *(const float4*)&Vs[kk][tx * 4];
            #pragma unroll
            for (int i = 0; i < 4; i++)
                #pragma unroll
                for (int j = 0; j < 4; j++) acc[i][j] = fmaf(a[i], bb2[j], acc[i][j]);
        }
        __syncthreads();
    }
    #pragma unroll
    for (int ii = 0; ii < 4; ii++) {
        const size_t off = obase + (size_t)(i0 + ty * 4 + ii) * (HH * HD) + d0 + tx * 4;
        __nv_bfloat162 h01, h23, l01, l23;
        split2(acc[ii][0], h01.x, l01.x); split2(acc[ii][1], h01.y, l01.y);
        split2(acc[ii][2], h23.x, l23.x); split2(acc[ii][3], h23.y, l23.y);
        *(__nv_bfloat162*)(Oh + off)     = h01;
        *(__nv_bfloat162*)(Oh + off + 2) = h23;
        *(__nv_bfloat162*)(Ol + off)     = l01;
        *(__nv_bfloat162*)(Ol + off + 2) = l23;
    }
}

// ================= GeGLU -> bf16 hi/lo =================
__global__ __launch_bounds__(256) void geglu_kernel(
    const float* __restrict__ gate, const float* __restrict__ up,
    __nv_bfloat16* __restrict__ oh, __nv_bfloat16* __restrict__ ol, size_t n)
{
    size_t i = (size_t)blockIdx.x * 256 + threadIdx.x;
    if (i < n) {
        float x = gate[i];
        float t = 0.7978845608028654f * (x + 0.044715f * x * x * x);
        float g = 0.5f * x * (1.f + tanhf(t));
        float r = g * up[i];
        __nv_bfloat16 h, l; split2(r, h, l);
        oh[i] = h; ol[i] = l;
    }
}

// ================= launch =================
static inline void run_split(const float* w, __nv_bfloat16* h, __nv_bfloat16* l, size_t n) {
    int n4 = (int)(n / 4);
    split_kernel<<<(n4 + 255) / 256, 256>>>((const float4*)w, (__nv_bfloat162*)h,
                                            (__nv_bfloat162*)l, n4);
}

extern "C" void kernel_launch(void* const* d_in, const int* in_sizes, int n_in,
                              void* d_out, int out_size)
{
    const float* x          = (const float*)d_in[0];
    const int*   positions  = (const int*)  d_in[1];
    const float* wq         = (const float*)d_in[4];
    const float* wk         = (const float*)d_in[5];
    const float* wv         = (const float*)d_in[6];
    const float* wo         = (const float*)d_in[7];
    const float* q_scale    = (const float*)d_in[8];
    const float* k_scale    = (const float*)d_in[9];
    const float* pre_attn   = (const float*)d_in[10];
    const float* post_attn  = (const float*)d_in[11];
    const float* pre_ffn    = (const float*)d_in[12];
    const float* post_ffn   = (const float*)d_in[13];
    const float* w_gate     = (const float*)d_in[14];
    const float* w_up       = (const float*)d_in[15];
    const float* w_down     = (const float*)d_in[16];
    const float* layer_scal = (const float*)d_in[17];
    float* out = (float*)d_out;

    float *q_, *k_, *v_, *sc_, *tmp_, *x2_, *gate_, *up_, *ffn_;
    __nv_bfloat16 *ah_, *al_;
    __nv_bfloat16 *wqh, *wql, *wkh, *wkl, *wvh, *wvl, *woh, *wol, *wgh, *wgl, *wuh, *wul, *wdh, *wdl;
    cudaGetSymbolAddress((void**)&q_,   g_q);
    cudaGetSymbolAddress((void**)&k_,   g_k);
    cudaGetSymbolAddress((void**)&v_,   g_v);
    cudaGetSymbolAddress((void**)&sc_,  g_sc);
    cudaGetSymbolAddress((void**)&tmp_, g_tmp);
    cudaGetSymbolAddress((void**)&x2_,  g_x2);
    cudaGetSymbolAddress((void**)&gate_,g_gate);
    cudaGetSymbolAddress((void**)&up_,  g_up);
    cudaGetSymbolAddress((void**)&ffn_, g_ffn);
    cudaGetSymbolAddress((void**)&ah_,  g_ah);
    cudaGetSymbolAddress((void**)&al_,  g_al);
    cudaGetSymbolAddress((void**)&wqh, g_wqh); cudaGetSymbolAddress((void**)&wql, g_wql);
    cudaGetSymbolAddress((void**)&wkh, g_wkh); cudaGetSymbolAddress((void**)&wkl, g_wkl);
    cudaGetSymbolAddress((void**)&wvh, g_wvh); cudaGetSymbolAddress((void**)&wvl, g_wvl);
    cudaGetSymbolAddress((void**)&woh, g_woh); cudaGetSymbolAddress((void**)&wol, g_wol);
    cudaGetSymbolAddress((void**)&wgh, g_wgh); cudaGetSymbolAddress((void**)&wgl, g_wgl);
    cudaGetSymbolAddress((void**)&wuh, g_wuh); cudaGetSymbolAddress((void**)&wul, g_wul);
    cudaGetSymbolAddress((void**)&wdh, g_wdh); cudaGetSymbolAddress((void**)&wdl, g_wdl);

    cudaFuncSetAttribute(gemm_mma, cudaFuncAttributeMaxDynamicSharedMemorySize, GSMEM2);

    // weight splits
    run_split(wq,     wqh, wql, (size_t)HH * HD * DD);
    run_split(wk,     wkh, wkl, (size_t)KVHN * HD * DD);
    run_split(wv,     wvh, wvl, (size_t)KVHN * HD * DD);
    run_split(wo,     woh, wol, (size_t)DD * HH * HD);
    run_split(w_gate, wgh, wgl, (size_t)FFN * DD);
    run_split(w_up,   wuh, wul, (size_t)FFN * DD);
    run_split(w_down, wdh, wdl, (size_t)DD * FFN);

    // ---- attention sub-block ----
    rmsnorm_kernel<<<MM, 256>>>(x, pre_attn, nullptr, nullptr, nullptr, ah_, al_, DD);
    gemm_mma<<<dim3((HH*HD)/128,   MM/256), 512, GSMEM2>>>(ah_, al_, wqh, wql, q_, MM, HH*HD,   DD);
    gemm_mma<<<dim3((KVHN*HD)/128, MM/256), 512, GSMEM2>>>(ah_, al_, wkh, wkl, k_, MM, KVHN*HD, DD);
    gemm_mma<<<dim3((KVHN*HD)/128, MM/256), 512, GSMEM2>>>(ah_, al_, wvh, wvl, v_, MM, KVHN*HD, DD);
    headnorm_rope_kernel<<<MM * HH,   128>>>(q_, q_scale, positions, HH,   1);
    headnorm_rope_kernel<<<MM * KVHN, 128>>>(k_, k_scale, positions, KVHN, 1);
    headnorm_rope_kernel<<<MM * KVHN, 128>>>(v_, nullptr, positions, KVHN, 0);
    attn_scores_kernel<<<dim3(SS/64, SS/64, BB*HH), 256>>>(q_, k_, sc_);
    softmax_kernel<<<BB * HH * SS, 256>>>(sc_);
    attn_pv_kernel<<<dim3(HD/64, SS/64, BB*HH), 256>>>(sc_, v_, ah_, al_);
    gemm_mma<<<dim3(DD/128, MM/256), 512, GSMEM2>>>(ah_, al_, woh, wol, tmp_, MM, DD, HH*HD);
    rmsnorm_kernel<<<MM, 256>>>(tmp_, post_attn, x, nullptr, x2_, nullptr, nullptr, DD);

    // ---- FFN sub-block ----
    rmsnorm_kernel<<<MM, 256>>>(x2_, pre_ffn, nullptr, nullptr, nullptr, ah_, al_, DD);
    gemm_mma<<<dim3(FFN/128, MM/256), 512, GSMEM2>>>(ah_, al_, wgh, wgl, gate_, MM, FFN, DD);
    gemm_mma<<<dim3(FFN/128, MM/256), 512, GSMEM2>>>(ah_, al_, wuh, wul, up_,   MM, FFN, DD);
    size_t nact = (size_t)MM * FFN;
    geglu_kernel<<<(unsigned)((nact + 255) / 256), 256>>>(gate_, up_, ah_, al_, nact);
    gemm_mma<<<dim3(DD/128, MM/256), 512, GSMEM2>>>(ah_, al_, wdh, wdl, ffn_, MM, DD, FFN);
    rmsnorm_kernel<<<MM, 256>>>(ffn_, post_ffn, x2_, layer_scal, out, nullptr, nullptr, DD);
}

// round 10
// speedup vs baseline: 1.0537x; 1.0536x over previous
#include <cuda_runtime.h>
#include <cuda_bf16.h>
#include <cstdint>
#include <math.h>

#define BB 4
#define SS 1024
#define DD 2048
#define HH 16
#define KVHN 8
#define HD 128
#define FFN 8192
#define MM (BB*SS)
#define EPS_RMS 1e-6f
#define KMASK -1e30f

// ================= PTX helpers (base sm_103 ISA only) =================
__device__ __forceinline__ uint32_t smem_to_u32(const void* p) {
    uint32_t a;
    asm("{ .reg .u64 t; cvta.to.shared.u64 t, %1; cvt.u32.u64 %0, t; }" : "=r"(a) : "l"(p));
    return a;
}
#define CP_ASYNC16(sa, gp) \
    asm volatile("cp.async.cg.shared.global [%0], [%1], 16;" :: "r"(sa), "l"(gp) : "memory")
#define CP_COMMIT() asm volatile("cp.async.commit_group;" ::: "memory")
#define CP_WAIT(n)  asm volatile("cp.async.wait_group %0;" :: "n"(n) : "memory")

#define LDSM_X4(r0, r1, r2, r3, sa) \
    asm volatile("ldmatrix.sync.aligned.m8n8.x4.shared.b16 {%0,%1,%2,%3}, [%4];" \
                 : "=r"(r0), "=r"(r1), "=r"(r2), "=r"(r3) : "r"(sa))

#define MMA16816(d, a, b0, b1) \
    asm volatile("mma.sync.aligned.m16n8k16.row.col.f32.bf16.bf16.f32 " \
                 "{%0,%1,%2,%3}, {%4,%5,%6,%7}, {%8,%9}, {%0,%1,%2,%3};" \
                 : "+f"((d)[0]), "+f"((d)[1]), "+f"((d)[2]), "+f"((d)[3]) \
                 : "r"((a)[0]), "r"((a)[1]), "r"((a)[2]), "r"((a)[3]), "r"(b0), "r"(b1))

// ================= scratch =================
__device__ float g_q   [(size_t)MM*HH*HD];
__device__ float g_k   [(size_t)MM*KVHN*HD];
__device__ float g_v   [(size_t)MM*KVHN*HD];
__device__ float g_sc  [(size_t)BB*HH*SS*SS];
__device__ float g_tmp [(size_t)MM*DD];
__device__ float g_x2  [(size_t)MM*DD];
__device__ float g_gate[(size_t)MM*FFN];
__device__ float g_up  [(size_t)MM*FFN];
__device__ float g_ffn [(size_t)MM*DD];
__device__ __nv_bfloat16 g_ah[(size_t)MM*FFN];
__device__ __nv_bfloat16 g_al[(size_t)MM*FFN];
// attention bf16 operands
__device__ __nv_bfloat16 g_qh[(size_t)MM*HH*HD],   g_ql[(size_t)MM*HH*HD];
__device__ __nv_bfloat16 g_kh[(size_t)MM*KVHN*HD], g_kl[(size_t)MM*KVHN*HD];
__device__ __nv_bfloat16 g_vth[(size_t)MM*KVHN*HD],g_vtl[(size_t)MM*KVHN*HD];
__device__ __nv_bfloat16 g_ph[(size_t)BB*HH*SS*SS],g_pl[(size_t)BB*HH*SS*SS];
// bf16 hi/lo weights
__device__ __nv_bfloat16 g_wqh[(size_t)HH*HD*DD],  g_wql[(size_t)HH*HD*DD];
__device__ __nv_bfloat16 g_wkh[(size_t)KVHN*HD*DD],g_wkl[(size_t)KVHN*HD*DD];
__device__ __nv_bfloat16 g_wvh[(size_t)KVHN*HD*DD],g_wvl[(size_t)KVHN*HD*DD];
__device__ __nv_bfloat16 g_woh[(size_t)DD*HH*HD],  g_wol[(size_t)DD*HH*HD];
__device__ __nv_bfloat16 g_wgh[(size_t)FFN*DD],    g_wgl[(size_t)FFN*DD];
__device__ __nv_bfloat16 g_wuh[(size_t)FFN*DD],    g_wul[(size_t)FFN*DD];
__device__ __nv_bfloat16 g_wdh[(size_t)DD*FFN],    g_wdl[(size_t)DD*FFN];

__device__ __forceinline__ void split2(float v, __nv_bfloat16& h, __nv_bfloat16& l) {
    h = __float2bfloat16(v);
    l = __float2bfloat16(v - __bfloat162float(h));
}

// ================= weight split =================
__global__ __launch_bounds__(256) void split_kernel(
    const float4* __restrict__ x, __nv_bfloat162* __restrict__ hi,
    __nv_bfloat162* __restrict__ lo, int n4)
{
    int i = blockIdx.x * 256 + threadIdx.x;
    if (i < n4) {
        float4 v = x[i];
        __nv_bfloat162 a, b, c, d;
        split2(v.x, a.x, c.x); split2(v.y, a.y, c.y);
        split2(v.z, b.x, d.x); split2(v.w, b.y, d.y);
        hi[2*i] = a; hi[2*i+1] = b; lo[2*i] = c; lo[2*i+1] = d;
    }
}

// ================= RMSNorm =================
__global__ __launch_bounds__(256) void rmsnorm_kernel(
    const float* __restrict__ in, const float* __restrict__ scale,
    const float* __restrict__ resid, const float* __restrict__ lsc,
    float* __restrict__ out, __nv_bfloat16* __restrict__ oh,
    __nv_bfloat16* __restrict__ ol, int N)
{
    __shared__ float red[8];
    const size_t row = blockIdx.x;
    const float* x = in + row * (size_t)N;
    float ss = 0.f;
    for (int j = threadIdx.x; j < N; j += 256) { float v = x[j]; ss = fmaf(v, v, ss); }
    int lane = threadIdx.x & 31, wid = threadIdx.x >> 5;
    #pragma unroll
    for (int o = 16; o > 0; o >>= 1) ss += __shfl_down_sync(0xffffffffu, ss, o);
    if (lane == 0) red[wid] = ss;
    __syncthreads();
    if (threadIdx.x == 0) {
        float s = 0.f;
        #pragma unroll
        for (int w = 0; w < 8; w++) s += red[w];
        red[0] = s;
    }
    __syncthreads();
    const float r = rsqrtf(red[0] / (float)N + EPS_RMS);
    const float ls = lsc ? lsc[0] : 1.f;
    const float* rp = resid ? resid + row * (size_t)N : nullptr;
    for (int j = threadIdx.x; j < N; j += 256) {
        float v = x[j] * r;
        if (scale) v *= scale[j];
        if (rp) v += rp[j];
        v *= ls;
        if (out) out[row * (size_t)N + j] = v;
        if (oh) {
            __nv_bfloat16 h, l; split2(v, h, l);
            oh[row * (size_t)N + j] = h; ol[row * (size_t)N + j] = l;
        }
    }
}

// ================= per-head RMSNorm (+ RoPE); optional bf16 hi/lo output =================
__global__ __launch_bounds__(128) void headnorm_rope_kernel(
    float* __restrict__ data, const float* __restrict__ scale,
    const int* __restrict__ positions, int nheads, int do_rope,
    __nv_bfloat16* __restrict__ oh, __nv_bfloat16* __restrict__ ol)
{
    __shared__ float red[4];
    __shared__ float sv[HD];
    const int d = threadIdx.x;
    const int idx = blockIdx.x;
    const int token = idx / nheads;
    float* p = data + (size_t)idx * HD;
    float v = p[d];
    float ss = v * v;
    int lane = d & 31, wid = d >> 5;
    #pragma unroll
    for (int o = 16; o > 0; o >>= 1) ss += __shfl_down_sync(0xffffffffu, ss, o);
    if (lane == 0) red[wid] = ss;
    __syncthreads();
    const float total = red[0] + red[1] + red[2] + red[3];
    const float r = rsqrtf(total * (1.0f / HD) + EPS_RMS);
    float nv = v * r;
    if (scale) nv *= scale[d];
    if (do_rope) {
        sv[d] = nv;
        __syncthreads();
        if (d < 64) {
            const int pos = positions[token];
            double freq = pow(10000.0, -((double)(2 * d) / 128.0));
            double ang = (double)pos * freq;
            double dsin, dcos;
            sincos(ang, &dsin, &dcos);
            float c = (float)dcos, s = (float)dsin;
            float x1 = sv[d], x2 = sv[d + 64];
            float o1 = x1 * c - x2 * s;
            float o2 = x2 * c + x1 * s;
            __nv_bfloat16 h1, l1, h2, l2;
            split2(o1, h1, l1); split2(o2, h2, l2);
            oh[(size_t)idx * HD + d]      = h1; ol[(size_t)idx * HD + d]      = l1;
            oh[(size_t)idx * HD + d + 64] = h2; ol[(size_t)idx * HD + d + 64] = l2;
        }
    } else {
        p[d] = nv;   // v path: fp32 in place (transposed/split afterwards)
    }
}

// ================= V transpose + split: v[b,s,hk,d] -> vt[b,hk,d,s] bf16 hi/lo =================
__global__ __launch_bounds__(256) void vtrans_kernel(
    const float* __restrict__ v, __nv_bfloat16* __restrict__ vth,
    __nv_bfloat16* __restrict__ vtl)
{
    __shared__ float tile[32][33];
    const int z = blockIdx.z;
    const int b = z >> 3, hk = z & 7;
    const int s0 = blockIdx.x * 32, d0 = blockIdx.y * 32;
    const int tx = threadIdx.x & 31, ty = threadIdx.x >> 5;
    #pragma unroll
    for (int r = ty; r < 32; r += 8)
        tile[r][tx] = v[(size_t)(b * SS + s0 + r) * (KVHN * HD) + hk * HD + d0 + tx];
    __syncthreads();
    #pragma unroll
    for (int r = ty; r < 32; r += 8) {
        float val = tile[tx][r];   // v[s0+tx][d0+r]
        __nv_bfloat16 h, l; split2(val, h, l);
        const size_t off = ((size_t)(b * KVHN + hk) * HD + d0 + r) * SS + s0 + tx;
        vth[off] = h; vtl[off] = l;
    }
}

// ================= HMMA bf16x3 GEMM: C[M,N] = A[M,K] * B[N,K]^T =================
#define ROW2  80
#define APART (256 * ROW2)
#define BPART (128 * ROW2)
#define STG2  (2 * APART + 2 * BPART)
#define GSMEM2 (3 * STG2)

__global__ __launch_bounds__(512, 1) void gemm_mma(
    const __nv_bfloat16* __restrict__ Ah, const __nv_bfloat16* __restrict__ Al,
    const __nv_bfloat16* __restrict__ Bh, const __nv_bfloat16* __restrict__ Bl,
    float* __restrict__ C, int M, int N, int K)
{
    extern __shared__ __align__(128) char smem[];
    const uint32_t sb = smem_to_u32(smem);
    const int tid = threadIdx.x;
    const int wid = tid >> 5, lane = tid & 31;
    const int wm = wid >> 2, wn = wid & 3;
    const int m0 = blockIdx.y * 256, n0 = blockIdx.x * 128;

    const int arow = tid >> 1;
    const int acs  = (tid & 1) * 2;
    const int brow = tid >> 2;
    const int bcs  = tid & 3;
    const __nv_bfloat16* gAh = Ah + (size_t)(m0 + arow) * K + acs * 8;
    const __nv_bfloat16* gAl = Al + (size_t)(m0 + arow) * K + acs * 8;
    const __nv_bfloat16* gBh = Bh + (size_t)(n0 + brow) * K + bcs * 8;
    const __nv_bfloat16* gBl = Bl + (size_t)(n0 + brow) * K + bcs * 8;
    const uint32_t aS = (uint32_t)(arow * ROW2 + acs * 16);
    const uint32_t bS = (uint32_t)(brow * ROW2 + bcs * 16);

    const int nch = K / 32;

    auto issue = [&](int c) {
        const uint32_t st = sb + (uint32_t)(c % 3) * STG2;
        const size_t ko = (size_t)c * 32;
        CP_ASYNC16(st + aS,                 gAh + ko);
        CP_ASYNC16(st + aS + 16,            gAh + ko + 8);
        CP_ASYNC16(st + APART + aS,         gAl + ko);
        CP_ASYNC16(st + APART + aS + 16,    gAl + ko + 8);
        CP_ASYNC16(st + 2 * APART + bS,         gBh + ko);
        CP_ASYNC16(st + 2 * APART + BPART + bS, gBl + ko);
    };

    issue(0); CP_COMMIT();
    issue(1); CP_COMMIT();

    const uint32_t aOff = (uint32_t)((wm * 64 + (lane & 15)) * ROW2 + (lane >> 4) * 16);
    const uint32_t bOff = (uint32_t)((wn * 32 + ((lane & 7) | ((lane >> 4) << 3))) * ROW2
                                     + ((lane >> 3) & 1) * 16);

    float acc[4][4][4];
    #pragma unroll
    for (int i = 0; i < 4; i++)
        #pragma unroll
        for (int j = 0; j < 4; j++)
            #pragma unroll
            for (int q = 0; q < 4; q++) acc[i][j][q] = 0.f;

    for (int c = 0; c < nch; ++c) {
        if (c + 1 < nch) { CP_WAIT(1); } else { CP_WAIT(0); }
        __syncthreads();
        if (c + 2 < nch) { issue(c + 2); CP_COMMIT(); }

        const uint32_t st = sb + (uint32_t)(c % 3) * STG2;
        const uint32_t aH = st + aOff;
        const uint32_t aL = aH + APART;
        const uint32_t bH = st + 2 * APART + bOff;
        const uint32_t bL = bH + BPART;

        #pragma unroll
        for (int ks = 0; ks < 2; ks++) {
            uint32_t bh[2][4], bl[2][4];
            #pragma unroll
            for (int np = 0; np < 2; np++) {
                const uint32_t o = (uint32_t)(np * 16 * ROW2 + ks * 32);
                LDSM_X4(bh[np][0], bh[np][1], bh[np][2], bh[np][3], bH + o);
                LDSM_X4(bl[np][0], bl[np][1], bl[np][2], bl[np][3], bL + o);
            }
            #pragma unroll
            for (int mi = 0; mi < 4; mi++) {
                uint32_t ah[4], al[4];
                const uint32_t o = (uint32_t)(mi * 16 * ROW2 + ks * 32);
                LDSM_X4(ah[0], ah[1], ah[2], ah[3], aH + o);
                LDSM_X4(al[0], al[1], al[2], al[3], aL + o);
                #pragma unroll
                for (int np = 0; np < 2; np++)
                    #pragma unroll
                    for (int hf = 0; hf < 2; hf++)
                        MMA16816(acc[mi][np * 2 + hf], ah, bh[np][hf * 2], bh[np][hf * 2 + 1]);
                #pragma unroll
                for (int np = 0; np < 2; np++)
                    #pragma unroll
                    for (int hf = 0; hf < 2; hf++)
                        MMA16816(acc[mi][np * 2 + hf], ah, bl[np][hf * 2], bl[np][hf * 2 + 1]);
                #pragma unroll
                for (int np = 0; np < 2; np++)
                    #pragma unroll
                    for (int hf = 0; hf < 2; hf++)
                        MMA16816(acc[mi][np * 2 + hf], al, bh[np][hf * 2], bh[np][hf * 2 + 1]);
            }
        }
    }

    #pragma unroll
    for (int mi = 0; mi < 4; mi++) {
        const int r = m0 + wm * 64 + mi * 16 + (lane >> 2);
        #pragma unroll
        for (int ni = 0; ni < 4; ni++) {
            const int cc = n0 + wn * 32 + ni * 8 + (lane & 3) * 2;
            *(float2*)&C[(size_t)r * N + cc]       = make_float2(acc[mi][ni][0], acc[mi][ni][1]);
            *(float2*)&C[(size_t)(r + 8) * N + cc] = make_float2(acc[mi][ni][2], acc[mi][ni][3]);
        }
    }
}

// ================= HMMA attention scores: sc = softcap(q·k^T) + causal mask =================
// CTA 128x128, 8 warps (2x4), K=128 single-shot smem, row stride 272 (conflict-free).
#define SROW  272
#define SPART (128 * SROW)   // 34816
#define SSMEM (4 * SPART)    // 139264

__global__ __launch_bounds__(256, 1) void attn_scores_mma(
    const __nv_bfloat16* __restrict__ qh, const __nv_bfloat16* __restrict__ ql,
    const __nv_bfloat16* __restrict__ kh, const __nv_bfloat16* __restrict__ kl,
    float* __restrict__ sc)
{
    const int bh = blockIdx.z;
    const int b = bh >> 4, h = bh & 15, hk = h >> 1;
    const int i0 = blockIdx.y * 128, j0 = blockIdx.x * 128;
    const int tid = threadIdx.x;
    float* Cb = sc + (size_t)bh * SS * SS;

    if (j0 > i0) {  // fully masked tile
        #pragma unroll
        for (int it = 0; it < 16; it++) {
            const int li = it * 256 + tid;            // float4 slot
            const int row = li >> 5, c4 = li & 31;
            *(float4*)&Cb[(size_t)(i0 + row) * SS + j0 + c4 * 4] =
                make_float4(KMASK, KMASK, KMASK, KMASK);
        }
        return;
    }

    extern __shared__ __align__(128) char smem[];
    const uint32_t sb = smem_to_u32(smem);
    const int wid = tid >> 5, lane = tid & 31;
    const int wm = wid >> 2, wn = wid & 3;

    // load full K=128 tiles: Qh, Ql, Kh, Kl
    {
        const int lrow = tid >> 1, half = tid & 1;
        const size_t qoff = ((size_t)(b * SS + i0 + lrow) * HH + h) * HD + half * 64;
        const size_t koff = ((size_t)(b * SS + j0 + lrow) * KVHN + hk) * HD + half * 64;
        const uint32_t sA = (uint32_t)(lrow * SROW + half * 128);
        #pragma unroll
        for (int j = 0; j < 8; j++) {
            CP_ASYNC16(sb + sA + j * 16,             qh + qoff + j * 8);
            CP_ASYNC16(sb + SPART + sA + j * 16,     ql + qoff + j * 8);
            CP_ASYNC16(sb + 2 * SPART + sA + j * 16, kh + koff + j * 8);
            CP_ASYNC16(sb + 3 * SPART + sA + j * 16, kl + koff + j * 8);
        }
    }
    CP_COMMIT(); CP_WAIT(0);
    __syncthreads();

    const uint32_t aOff = (uint32_t)((wm * 64 + (lane & 15)) * SROW + (lane >> 4) * 16);
    const uint32_t bOff = (uint32_t)((wn * 32 + ((lane & 7) | ((lane >> 4) << 3))) * SROW
                                     + ((lane >> 3) & 1) * 16);

    float acc[4][4][4];
    #pragma unroll
    for (int i = 0; i < 4; i++)
        #pragma unroll
        for (int j = 0; j < 4; j++)
            #pragma unroll
            for (int q = 0; q < 4; q++) acc[i][j][q] = 0.f;

    #pragma unroll
    for (int ks = 0; ks < 8; ks++) {
        const uint32_t kof = (uint32_t)(ks * 32);
        uint32_t bhf[2][4], blf[2][4];
        #pragma unroll
        for (int np = 0; np < 2; np++) {
            const uint32_t o = (uint32_t)(np * 16 * SROW) + kof;
            LDSM_X4(bhf[np][0], bhf[np][1], bhf[np][2], bhf[np][3], sb + 2 * SPART + bOff + o);
            LDSM_X4(blf[np][0], blf[np][1], blf[np][2], blf[np][3], sb + 3 * SPART + bOff + o);
        }
        #pragma unroll
        for (int mi = 0; mi < 4; mi++) {
            uint32_t ah[4], al[4];
            const uint32_t o = (uint32_t)(mi * 16 * SROW) + kof;
            LDSM_X4(ah[0], ah[1], ah[2], ah[3], sb + aOff + o);
            LDSM_X4(al[0], al[1], al[2], al[3], sb + SPART + aOff + o);
            #pragma unroll
            for (int np = 0; np < 2; np++)
                #pragma unroll
                for (int hf = 0; hf < 2; hf++)
                    MMA16816(acc[mi][np * 2 + hf], ah, bhf[np][hf * 2], bhf[np][hf * 2 + 1]);
            #pragma unroll
            for (int np = 0; np < 2; np++)
                #pragma unroll
                for (int hf = 0; hf < 2; hf++)
                    MMA16816(acc[mi][np * 2 + hf], ah, blf[np][hf * 2], blf[np][hf * 2 + 1]);
            #pragma unroll
            for (int np = 0; np < 2; np++)
                #pragma unroll
                for (int hf = 0; hf < 2; hf++)
                    MMA16816(acc[mi][np * 2 + hf], al, bhf[np][hf * 2], bhf[np][hf * 2 + 1]);
        }
    }

    // epilogue: softcap + causal mask
    #pragma unroll
    for (int mi = 0; mi < 4; mi++) {
        #pragma unroll
        for (int rr = 0; rr < 2; rr++) {
            const int r = i0 + wm * 64 + mi * 16 + rr * 8 + (lane >> 2);
            #pragma unroll
            for (int ni = 0; ni < 4; ni++) {
                const int c = j0 + wn * 32 + ni * 8 + (lane & 3) * 2;
                float v0 = tanhf(acc[mi][ni][rr * 2 + 0] * 0.02f) * 50.f;
                float v1 = tanhf(acc[mi][ni][rr * 2 + 1] * 0.02f) * 50.f;
                if (c > r)     v0 = KMASK;
                if (c + 1 > r) v1 = KMASK;
                *(float2*)&Cb[(size_t)r * SS + c] = make_float2(v0, v1);
            }
        }
    }
}

// ================= row softmax -> bf16 hi/lo probs =================
__global__ __launch_bounds__(256) void softmax_kernel(
    const float* __restrict__ sc, __nv_bfloat16* __restrict__ ph,
    __nv_bfloat16* __restrict__ pl)
{
    __shared__ float red[8];
    const float* p = sc + (size_t)blockIdx.x * SS;
    __nv_bfloat16* oph = ph + (size_t)blockIdx.x * SS;
    __nv_bfloat16* opl = pl + (size_t)blockIdx.x * SS;
    const int lane = threadIdx.x & 31, wid = threadIdx.x >> 5;
    float m = -3.4e38f;
    for (int j = threadIdx.x; j < SS; j += 256) m = fmaxf(m, p[j]);
    #pragma unroll
    for (int o = 16; o > 0; o >>= 1) m = fmaxf(m, __shfl_down_sync(0xffffffffu, m, o));
    if (lane == 0) red[wid] = m;
    __syncthreads();
    if (threadIdx.x == 0) {
        float s = red[0];
        #pragma unroll
        for (int w = 1; w < 8; w++) s = fmaxf(s, red[w]);
        red[0] = s;
    }
    __syncthreads();
    m = red[0];
    __syncthreads();
    float sum = 0.f;
    float ev[4];
    for (int j = threadIdx.x, q = 0; j < SS; j += 256, q++) {
        float e = __expf(p[j] - m);
        ev[q] = e;
        sum += e;
    }
    #pragma unroll
    for (int o = 16; o > 0; o >>= 1) sum += __shfl_down_sync(0xffffffffu, sum, o);
    if (lane == 0) red[wid] = sum;
    __syncthreads();
    if (threadIdx.x == 0) {
        float s = 0.f;
        #pragma unroll
        for (int w = 0; w < 8; w++) s += red[w];
        red[0] = s;
    }
    __syncthreads();
    const float inv = 1.f / red[0];
    for (int j = threadIdx.x, q = 0; j < SS; j += 256, q++) {
        __nv_bfloat16 h, l; split2(ev[q] * inv, h, l);
        oph[j] = h; opl[j] = l;
    }
}

// ================= HMMA P·V: out = probs · V, causal-truncated, bf16 hi/lo output =================
// CTA 128(i) x 128(d), 8 warps (2x4), K-chunk 32 keys, 3-stage cp.async.
#define PROW  80
#define PPART (128 * PROW)   // 10240
#define PSTG  (4 * PPART)    // 40960
#define PSMEM (3 * PSTG)     // 122880

__global__ __launch_bounds__(256, 1) void attn_pv_mma(
    const __nv_bfloat16* __restrict__ ph, const __nv_bfloat16* __restrict__ pl,
    const __nv_bfloat16* __restrict__ vth, const __nv_bfloat16* __restrict__ vtl,
    __nv_bfloat16* __restrict__ Oh, __nv_bfloat16* __restrict__ Ol)
{
    extern __shared__ __align__(128) char smem[];
    const uint32_t sb = smem_to_u32(smem);
    const int bh = blockIdx.z;
    const int b = bh >> 4, h = bh & 15, hk = h >> 1;
    const int i0 = (7 - blockIdx.y) * 128;   // big tiles first (load balance)
    const int tid = threadIdx.x;
    const int wid = tid >> 5, lane = tid & 31;
    const int wm = wid >> 2, wn = wid & 3;

    const int lrow = tid >> 1, half = tid & 1;
    const size_t pbase = ((size_t)bh * SS + i0 + lrow) * SS + half * 16;
    const size_t vbase = ((size_t)(b * KVHN + hk) * HD + lrow) * SS + half * 16;
    const uint32_t sA = (uint32_t)(lrow * PROW + half * 32);

    const int nch = (i0 + 128) / 32;

    auto issue = [&](int c) {
        const uint32_t st = sb + (uint32_t)(c % 3) * PSTG;
        const size_t ko = (size_t)c * 32;
        CP_ASYNC16(st + sA,                 ph + pbase + ko);
        CP_ASYNC16(st + sA + 16,            ph + pbase + ko + 8);
        CP_ASYNC16(st + PPART + sA,         pl + pbase + ko);
        CP_ASYNC16(st + PPART + sA + 16,    pl + pbase + ko + 8);
        CP_ASYNC16(st + 2 * PPART + sA,       vth + vbase + ko);
        CP_ASYNC16(st + 2 * PPART + sA + 16,  vth + vbase + ko + 8);
        CP_ASYNC16(st + 3 * PPART + sA,       vtl + vbase + ko);
        CP_ASYNC16(st + 3 * PPART + sA + 16,  vtl + vbase + ko + 8);
    };

    issue(0); CP_COMMIT();
    issue(1); CP_COMMIT();

    const uint32_t aOff = (uint32_t)((wm * 64 + (lane & 15)) * PROW + (lane >> 4) * 16);
    const uint32_t bOff = (uint32_t)((wn * 32 + ((lane & 7) | ((lane >> 4) << 3))) * PROW
                                     + ((lane >> 3) & 1) * 16);

    float acc[4][4][4];
    #pragma unroll
    for (int i = 0; i < 4; i++)
        #pragma unroll
        for (int j = 0; j < 4; j++)
            #pragma unroll
            for (int q = 0; q < 4; q++) acc[i][j][q] = 0.f;

    for (int c = 0; c < nch; ++c) {
        if (c + 1 < nch) { CP_WAIT(1); } else { CP_WAIT(0); }
        __syncthreads();
        if (c + 2 < nch) { issue(c + 2); CP_COMMIT(); }

        const uint32_t st = sb + (uint32_t)(c % 3) * PSTG;
        const uint32_t aH = st + aOff;
        const uint32_t aL = aH + PPART;
        const uint32_t bH = st + 2 * PPART + bOff;
        const uint32_t bL = bH + PPART;

        #pragma unroll
        for (int ks = 0; ks < 2; ks++) {
            uint32_t bhf[2][4], blf[2][4];
            #pragma unroll
            for (int np = 0; np < 2; np++) {
                const uint32_t o = (uint32_t)(np * 16 * PROW + ks * 32);
                LDSM_X4(bhf[np][0], bhf[np][1], bhf[np][2], bhf[np][3], bH + o);
                LDSM_X4(blf[np][0], blf[np][1], blf[np][2], blf[np][3], bL + o);
            }
            #pragma unroll
            for (int mi = 0; mi < 4; mi++) {
                uint32_t ah[4], al[4];
                const uint32_t o = (uint32_t)(mi * 16 * PROW + ks * 32);
                LDSM_X4(ah[0], ah[1], ah[2], ah[3], aH + o);
                LDSM_X4(al[0], al[1], al[2], al[3], aL + o);
                #pragma unroll
                for (int np = 0; np < 2; np++)
                    #pragma unroll
                    for (int hf = 0; hf < 2; hf++)
                        MMA16816(acc[mi][np * 2 + hf], ah, bhf[np][hf * 2], bhf[np][hf * 2 + 1]);
                #pragma unroll
                for (int np = 0; np < 2; np++)
                    #pragma unroll
                    for (int hf = 0; hf < 2; hf++)
                        MMA16816(acc[mi][np * 2 + hf], ah, blf[np][hf * 2], blf[np][hf * 2 + 1]);
                #pragma unroll
                for (int np = 0; np < 2; np++)
                    #pragma unroll
                    for (int hf = 0; hf < 2; hf++)
                        MMA16816(acc[mi][np * 2 + hf], al, bhf[np][hf * 2], bhf[np][hf * 2 + 1]);
            }
        }
    }

    // epilogue: bf16 hi/lo into wo-GEMM input layout [b, s, H*HD]
    #pragma unroll
    for (int mi = 0; mi < 4; mi++) {
        #pragma unroll
        for (int rr = 0; rr < 2; rr++) {
            const int r = wm * 64 + mi * 16 + rr * 8 + (lane >> 2);
            const size_t rowoff = ((size_t)b * SS + i0 + r) * (HH * HD) + h * HD;
            #pragma unroll
            for (int ni = 0; ni < 4; ni++) {
                const int cc = wn * 32 + ni * 8 + (lane & 3) * 2;
                __nv_bfloat162 hv, lv;
                split2(acc[mi][ni][rr * 2 + 0], hv.x, lv.x);
                split2(acc[mi][ni][rr * 2 + 1], hv.y, lv.y);
                *(__nv_bfloat162*)(Oh + rowoff + cc) = hv;
                *(__nv_bfloat162*)(Ol + rowoff + cc) = lv;
            }
        }
    }
}

// ================= GeGLU -> bf16 hi/lo =================
__global__ __launch_bounds__(256) void geglu_kernel(
    const float* __restrict__ gate, const float* __restrict__ up,
    __nv_bfloat16* __restrict__ oh, __nv_bfloat16* __restrict__ ol, size_t n)
{
    size_t i = (size_t)blockIdx.x * 256 + threadIdx.x;
    if (i < n) {
        float x = gate[i];
        float t = 0.7978845608028654f * (x + 0.044715f * x * x * x);
        float g = 0.5f * x * (1.f + tanhf(t));
        float r = g * up[i];
        __nv_bfloat16 h, l; split2(r, h, l);
        oh[i] = h; ol[i] = l;
    }
}

// ================= launch =================
static inline void run_split(const float* w, __nv_bfloat16* h, __nv_bfloat16* l, size_t n) {
    int n4 = (int)(n / 4);
    split_kernel<<<(n4 + 255) / 256, 256>>>((const float4*)w, (__nv_bfloat162*)h,
                                            (__nv_bfloat162*)l, n4);
}

extern "C" void kernel_launch(void* const* d_in, const int* in_sizes, int n_in,
                              void* d_out, int out_size)
{
    const float* x          = (const float*)d_in[0];
    const int*   positions  = (const int*)  d_in[1];
    const float* wq         = (const float*)d_in[4];
    const float* wk         = (const float*)d_in[5];
    const float* wv         = (const float*)d_in[6];
    const float* wo         = (const float*)d_in[7];
    const float* q_scale    = (const float*)d_in[8];
    const float* k_scale    = (const float*)d_in[9];
    const float* pre_attn   = (const float*)d_in[10];
    const float* post_attn  = (const float*)d_in[11];
    const float* pre_ffn    = (const float*)d_in[12];
    const float* post_ffn   = (const float*)d_in[13];
    const float* w_gate     = (const float*)d_in[14];
    const float* w_up       = (const float*)d_in[15];
    const float* w_down     = (const float*)d_in[16];
    const float* layer_scal = (const float*)d_in[17];
    float* out = (float*)d_out;

    float *q_, *k_, *v_, *sc_, *tmp_, *x2_, *gate_, *up_, *ffn_;
    __nv_bfloat16 *ah_, *al_, *qh_, *ql_, *kh_, *kl_, *vth_, *vtl_, *ph_, *pl_;
    __nv_bfloat16 *wqh, *wql, *wkh, *wkl, *wvh, *wvl, *woh, *wol, *wgh, *wgl, *wuh, *wul, *wdh, *wdl;
    cudaGetSymbolAddress((void**)&q_,   g_q);
    cudaGetSymbolAddress((void**)&k_,   g_k);
    cudaGetSymbolAddress((void**)&v_,   g_v);
    cudaGetSymbolAddress((void**)&sc_,  g_sc);
    cudaGetSymbolAddress((void**)&tmp_, g_tmp);
    cudaGetSymbolAddress((void**)&x2_,  g_x2);
    cudaGetSymbolAddress((void**)&gate_,g_gate);
    cudaGetSymbolAddress((void**)&up_,  g_up);
    cudaGetSymbolAddress((void**)&ffn_, g_ffn);
    cudaGetSymbolAddress((void**)&ah_,  g_ah);
    cudaGetSymbolAddress((void**)&al_,  g_al);
    cudaGetSymbolAddress((void**)&qh_,  g_qh);  cudaGetSymbolAddress((void**)&ql_,  g_ql);
    cudaGetSymbolAddress((void**)&kh_,  g_kh);  cudaGetSymbolAddress((void**)&kl_,  g_kl);
    cudaGetSymbolAddress((void**)&vth_, g_vth); cudaGetSymbolAddress((void**)&vtl_, g_vtl);
    cudaGetSymbolAddress((void**)&ph_,  g_ph);  cudaGetSymbolAddress((void**)&pl_,  g_pl);
    cudaGetSymbolAddress((void**)&wqh, g_wqh); cudaGetSymbolAddress((void**)&wql, g_wql);
    cudaGetSymbolAddress((void**)&wkh, g_wkh); cudaGetSymbolAddress((void**)&wkl, g_wkl);
    cudaGetSymbolAddress((void**)&wvh, g_wvh); cudaGetSymbolAddress((void**)&wvl, g_wvl);
    cudaGetSymbolAddress((void**)&woh, g_woh); cudaGetSymbolAddress((void**)&wol, g_wol);
    cudaGetSymbolAddress((void**)&wgh, g_wgh); cudaGetSymbolAddress((void**)&wgl, g_wgl);
    cudaGetSymbolAddress((void**)&wuh, g_wuh); cudaGetSymbolAddress((void**)&wul, g_wul);
    cudaGetSymbolAddress((void**)&wdh, g_wdh); cudaGetSymbolAddress((void**)&wdl, g_wdl);

    cudaFuncSetAttribute(gemm_mma,        cudaFuncAttributeMaxDynamicSharedMemorySize, GSMEM2);
    cudaFuncSetAttribute(attn_scores_mma, cudaFuncAttributeMaxDynamicSharedMemorySize, SSMEM);
    cudaFuncSetAttribute(attn_pv_mma,     cudaFuncAttributeMaxDynamicSharedMemorySize, PSMEM);

    // weight splits
    run_split(wq,     wqh, wql, (size_t)HH * HD * DD);
    run_split(wk,     wkh, wkl, (size_t)KVHN * HD * DD);
    run_split(wv,     wvh, wvl, (size_t)KVHN * HD * DD);
    run_split(wo,     woh, wol, (size_t)DD * HH * HD);
    run_split(w_gate, wgh, wgl, (size_t)FFN * DD);
    run_split(w_up,   wuh, wul, (size_t)FFN * DD);
    run_split(w_down, wdh, wdl, (size_t)DD * FFN);

    // ---- attention sub-block ----
    rmsnorm_kernel<<<MM, 256>>>(x, pre_attn, nullptr, nullptr, nullptr, ah_, al_, DD);
    gemm_mma<<<dim3((HH*HD)/128,   MM/256), 512, GSMEM2>>>(ah_, al_, wqh, wql, q_, MM, HH*HD,   DD);
    gemm_mma<<<dim3((KVHN*HD)/128, MM/256), 512, GSMEM2>>>(ah_, al_, wkh, wkl, k_, MM, KVHN*HD, DD);
    gemm_mma<<<dim3((KVHN*HD)/128, MM/256), 512, GSMEM2>>>(ah_, al_, wvh, wvl, v_, MM, KVHN*HD, DD);
    headnorm_rope_kernel<<<MM * HH,   128>>>(q_, q_scale, positions, HH,   1, qh_, ql_);
    headnorm_rope_kernel<<<MM * KVHN, 128>>>(k_, k_scale, positions, KVHN, 1, kh_, kl_);
    headnorm_rope_kernel<<<MM * KVHN, 128>>>(v_, nullptr, positions, KVHN, 0, nullptr, nullptr);
    vtrans_kernel<<<dim3(SS/32, HD/32, BB*KVHN), 256>>>(v_, vth_, vtl_);
    attn_scores_mma<<<dim3(SS/128, SS/128, BB*HH), 256, SSMEM>>>(qh_, ql_, kh_, kl_, sc_);
    softmax_kernel<<<BB * HH * SS, 256>>>(sc_, ph_, pl_);
    attn_pv_mma<<<dim3(1, SS/128, BB*HH), 256, PSMEM>>>(ph_, pl_, vth_, vtl_, ah_, al_);
    gemm_mma<<<dim3(DD/128, MM/256), 512, GSMEM2>>>(ah_, al_, woh, wol, tmp_, MM, DD, HH*HD);
    rmsnorm_kernel<<<MM, 256>>>(tmp_, post_attn, x, nullptr, x2_, nullptr, nullptr, DD);

    // ---- FFN sub-block ----
    rmsnorm_kernel<<<MM, 256>>>(x2_, pre_ffn, nullptr, nullptr, nullptr, ah_, al_, DD);
    gemm_mma<<<dim3(FFN/128, MM/256), 512, GSMEM2>>>(ah_, al_, wgh, wgl, gate_, MM, FFN, DD);
    gemm_mma<<<dim3(FFN/128, MM/256), 512, GSMEM2>>>(ah_, al_, wuh, wul, up_,   MM, FFN, DD);
    size_t nact = (size_t)MM * FFN;
    geglu_kernel<<<(unsigned)((nact + 255) / 256), 256>>>(gate_, up_, ah_, al_, nact);
    gemm_mma<<<dim3(DD/128, MM/256), 512, GSMEM2>>>(ah_, al_, wdh, wdl, ffn_, MM, DD, FFN);
    rmsnorm_kernel<<<MM, 256>>>(ffn_, post_ffn, x2_, layer_scal, out, nullptr, nullptr, DD);
}

// round 12
// speedup vs baseline: 1.0824x; 1.0273x over previous
#include <cuda_runtime.h>
#include <cuda_bf16.h>
#include <cstdint>
#include <math.h>

#define BB 4
#define SS 1024
#define DD 2048
#define HH 16
#define KVHN 8
#define HD 128
#define FFN 8192
#define MM (BB*SS)
#define EPS_RMS 1e-6f
#define KMASK -1e30f

// ================= PTX helpers (base sm_103 ISA only) =================
__device__ __forceinline__ uint32_t smem_to_u32(const void* p) {
    uint32_t a;
    asm("{ .reg .u64 t; cvta.to.shared.u64 t, %1; cvt.u32.u64 %0, t; }" : "=r"(a) : "l"(p));
    return a;
}
#define CP_ASYNC16(sa, gp) \
    asm volatile("cp.async.cg.shared.global [%0], [%1], 16;" :: "r"(sa), "l"(gp) : "memory")
#define CP_COMMIT() asm volatile("cp.async.commit_group;" ::: "memory")
#define CP_WAIT(n)  asm volatile("cp.async.wait_group %0;" :: "n"(n) : "memory")

#define LDSM_X4(r0, r1, r2, r3, sa) \
    asm volatile("ldmatrix.sync.aligned.m8n8.x4.shared.b16 {%0,%1,%2,%3}, [%4];" \
                 : "=r"(r0), "=r"(r1), "=r"(r2), "=r"(r3) : "r"(sa))

#define MMA16816(d, a, b0, b1) \
    asm volatile("mma.sync.aligned.m16n8k16.row.col.f32.bf16.bf16.f32 " \
                 "{%0,%1,%2,%3}, {%4,%5,%6,%7}, {%8,%9}, {%0,%1,%2,%3};" \
                 : "+f"((d)[0]), "+f"((d)[1]), "+f"((d)[2]), "+f"((d)[3]) \
                 : "r"((a)[0]), "r"((a)[1]), "r"((a)[2]), "r"((a)[3]), "r"(b0), "r"(b1))

// ================= scratch =================
__device__ float g_q   [(size_t)MM*HH*HD];
__device__ float g_k   [(size_t)MM*KVHN*HD];
__device__ float g_v   [(size_t)MM*KVHN*HD];
__device__ float g_tmp [(size_t)MM*DD];
__device__ float g_x2  [(size_t)MM*DD];
__device__ float g_gate[(size_t)MM*FFN];
__device__ float g_up  [(size_t)MM*FFN];
__device__ float g_ffn [(size_t)MM*DD];
__device__ __nv_bfloat16 g_ah[(size_t)MM*FFN];
__device__ __nv_bfloat16 g_al[(size_t)MM*FFN];
// attention bf16 operands
__device__ __nv_bfloat16 g_qh[(size_t)MM*HH*HD],   g_ql[(size_t)MM*HH*HD];
__device__ __nv_bfloat16 g_kh[(size_t)MM*KVHN*HD], g_kl[(size_t)MM*KVHN*HD];
__device__ __nv_bfloat16 g_vth[(size_t)MM*KVHN*HD],g_vtl[(size_t)MM*KVHN*HD];
// bf16 hi/lo weights
__device__ __nv_bfloat16 g_wqh[(size_t)HH*HD*DD],  g_wql[(size_t)HH*HD*DD];
__device__ __nv_bfloat16 g_wkh[(size_t)KVHN*HD*DD],g_wkl[(size_t)KVHN*HD*DD];
__device__ __nv_bfloat16 g_wvh[(size_t)KVHN*HD*DD],g_wvl[(size_t)KVHN*HD*DD];
__device__ __nv_bfloat16 g_woh[(size_t)DD*HH*HD],  g_wol[(size_t)DD*HH*HD];
__device__ __nv_bfloat16 g_wgh[(size_t)FFN*DD],    g_wgl[(size_t)FFN*DD];
__device__ __nv_bfloat16 g_wuh[(size_t)FFN*DD],    g_wul[(size_t)FFN*DD];
__device__ __nv_bfloat16 g_wdh[(size_t)DD*FFN],    g_wdl[(size_t)DD*FFN];

__device__ __forceinline__ void split2(float v, __nv_bfloat16& h, __nv_bfloat16& l) {
    h = __float2bfloat16(v);
    l = __float2bfloat16(v - __bfloat162float(h));
}

// ================= weight split =================
__global__ __launch_bounds__(256) void split_kernel(
    const float4* __restrict__ x, __nv_bfloat162* __restrict__ hi,
    __nv_bfloat162* __restrict__ lo, int n4)
{
    int i = blockIdx.x * 256 + threadIdx.x;
    if (i < n4) {
        float4 v = x[i];
        __nv_bfloat162 a, b, c, d;
        split2(v.x, a.x, c.x); split2(v.y, a.y, c.y);
        split2(v.z, b.x, d.x); split2(v.w, b.y, d.y);
        hi[2*i] = a; hi[2*i+1] = b; lo[2*i] = c; lo[2*i+1] = d;
    }
}

// ================= RMSNorm =================
__global__ __launch_bounds__(256) void rmsnorm_kernel(
    const float* __restrict__ in, const float* __restrict__ scale,
    const float* __restrict__ resid, const float* __restrict__ lsc,
    float* __restrict__ out, __nv_bfloat16* __restrict__ oh,
    __nv_bfloat16* __restrict__ ol, int N)
{
    __shared__ float red[8];
    const size_t row = blockIdx.x;
    const float* x = in + row * (size_t)N;
    float ss = 0.f;
    for (int j = threadIdx.x; j < N; j += 256) { float v = x[j]; ss = fmaf(v, v, ss); }
    int lane = threadIdx.x & 31, wid = threadIdx.x >> 5;
    #pragma unroll
    for (int o = 16; o > 0; o >>= 1) ss += __shfl_down_sync(0xffffffffu, ss, o);
    if (lane == 0) red[wid] = ss;
    __syncthreads();
    if (threadIdx.x == 0) {
        float s = 0.f;
        #pragma unroll
        for (int w = 0; w < 8; w++) s += red[w];
        red[0] = s;
    }
    __syncthreads();
    const float r = rsqrtf(red[0] / (float)N + EPS_RMS);
    const float ls = lsc ? lsc[0] : 1.f;
    const float* rp = resid ? resid + row * (size_t)N : nullptr;
    for (int j = threadIdx.x; j < N; j += 256) {
        float v = x[j] * r;
        if (scale) v *= scale[j];
        if (rp) v += rp[j];
        v *= ls;
        if (out) out[row * (size_t)N + j] = v;
        if (oh) {
            __nv_bfloat16 h, l; split2(v, h, l);
            oh[row * (size_t)N + j] = h; ol[row * (size_t)N + j] = l;
        }
    }
}

// ================= per-head RMSNorm (+ RoPE); optional bf16 hi/lo output =================
__global__ __launch_bounds__(128) void headnorm_rope_kernel(
    float* __restrict__ data, const float* __restrict__ scale,
    const int* __restrict__ positions, int nheads, int do_rope,
    __nv_bfloat16* __restrict__ oh, __nv_bfloat16* __restrict__ ol)
{
    __shared__ float red[4];
    __shared__ float sv[HD];
    const int d = threadIdx.x;
    const int idx = blockIdx.x;
    const int token = idx / nheads;
    float* p = data + (size_t)idx * HD;
    float v = p[d];
    float ss = v * v;
    int lane = d & 31, wid = d >> 5;
    #pragma unroll
    for (int o = 16; o > 0; o >>= 1) ss += __shfl_down_sync(0xffffffffu, ss, o);
    if (lane == 0) red[wid] = ss;
    __syncthreads();
    const float total = red[0] + red[1] + red[2] + red[3];
    const float r = rsqrtf(total * (1.0f / HD) + EPS_RMS);
    float nv = v * r;
    if (scale) nv *= scale[d];
    if (do_rope) {
        sv[d] = nv;
        __syncthreads();
        if (d < 64) {
            const int pos = positions[token];
            double freq = pow(10000.0, -((double)(2 * d) / 128.0));
            double ang = (double)pos * freq;
            double dsin, dcos;
            sincos(ang, &dsin, &dcos);
            float c = (float)dcos, s = (float)dsin;
            float x1 = sv[d], x2 = sv[d + 64];
            float o1 = x1 * c - x2 * s;
            float o2 = x2 * c + x1 * s;
            __nv_bfloat16 h1, l1, h2, l2;
            split2(o1, h1, l1); split2(o2, h2, l2);
            oh[(size_t)idx * HD + d]      = h1; ol[(size_t)idx * HD + d]      = l1;
            oh[(size_t)idx * HD + d + 64] = h2; ol[(size_t)idx * HD + d + 64] = l2;
        }
    } else {
        p[d] = nv;
    }
}

// ================= V transpose + split: v[b,s,hk,d] -> vt[b,hk,d,s] bf16 hi/lo =================
__global__ __launch_bounds__(256) void vtrans_kernel(
    const float* __restrict__ v, __nv_bfloat16* __restrict__ vth,
    __nv_bfloat16* __restrict__ vtl)
{
    __shared__ float tile[32][33];
    const int z = blockIdx.z;
    const int b = z >> 3, hk = z & 7;
    const int s0 = blockIdx.x * 32, d0 = blockIdx.y * 32;
    const int tx = threadIdx.x & 31, ty = threadIdx.x >> 5;
    #pragma unroll
    for (int r = ty; r < 32; r += 8)
        tile[r][tx] = v[(size_t)(b * SS + s0 + r) * (KVHN * HD) + hk * HD + d0 + tx];
    __syncthreads();
    #pragma unroll
    for (int r = ty; r < 32; r += 8) {
        float val = tile[tx][r];
        __nv_bfloat16 h, l; split2(val, h, l);
        const size_t off = ((size_t)(b * KVHN + hk) * HD + d0 + r) * SS + s0 + tx;
        vth[off] = h; vtl[off] = l;
    }
}

// ================= HMMA bf16x3 GEMM: C[M,N] = A[M,K] * B[N,K]^T =================
#define ROW2  80
#define APART (256 * ROW2)
#define BPART (128 * ROW2)
#define STG2  (2 * APART + 2 * BPART)
#define GSMEM2 (3 * STG2)

__global__ __launch_bounds__(512, 1) void gemm_mma(
    const __nv_bfloat16* __restrict__ Ah, const __nv_bfloat16* __restrict__ Al,
    const __nv_bfloat16* __restrict__ Bh, const __nv_bfloat16* __restrict__ Bl,
    float* __restrict__ C, int M, int N, int K)
{
    extern __shared__ __align__(128) char smem[];
    const uint32_t sb = smem_to_u32(smem);
    const int tid = threadIdx.x;
    const int wid = tid >> 5, lane = tid & 31;
    const int wm = wid >> 2, wn = wid & 3;
    const int m0 = blockIdx.y * 256, n0 = blockIdx.x * 128;

    const int arow = tid >> 1;
    const int acs  = (tid & 1) * 2;
    const int brow = tid >> 2;
    const int bcs  = tid & 3;
    const __nv_bfloat16* gAh = Ah + (size_t)(m0 + arow) * K + acs * 8;
    const __nv_bfloat16* gAl = Al + (size_t)(m0 + arow) * K + acs * 8;
    const __nv_bfloat16* gBh = Bh + (size_t)(n0 + brow) * K + bcs * 8;
    const __nv_bfloat16* gBl = Bl + (size_t)(n0 + brow) * K + bcs * 8;
    const uint32_t aS = (uint32_t)(arow * ROW2 + acs * 16);
    const uint32_t bS = (uint32_t)(brow * ROW2 + bcs * 16);

    const int nch = K / 32;

    auto issue = [&](int c) {
        const uint32_t st = sb + (uint32_t)(c % 3) * STG2;
        const size_t ko = (size_t)c * 32;
        CP_ASYNC16(st + aS,                 gAh + ko);
        CP_ASYNC16(st + aS + 16,            gAh + ko + 8);
        CP_ASYNC16(st + APART + aS,         gAl + ko);
        CP_ASYNC16(st + APART + aS + 16,    gAl + ko + 8);
        CP_ASYNC16(st + 2 * APART + bS,         gBh + ko);
        CP_ASYNC16(st + 2 * APART + BPART + bS, gBl + ko);
    };

    issue(0); CP_COMMIT();
    issue(1); CP_COMMIT();

    const uint32_t aOff = (uint32_t)((wm * 64 + (lane & 15)) * ROW2 + (lane >> 4) * 16);
    const uint32_t bOff = (uint32_t)((wn * 32 + ((lane & 7) | ((lane >> 4) << 3))) * ROW2
                                     + ((lane >> 3) & 1) * 16);

    float acc[4][4][4];
    #pragma unroll
    for (int i = 0; i < 4; i++)
        #pragma unroll
        for (int j = 0; j < 4; j++)
            #pragma unroll
            for (int q = 0; q < 4; q++) acc[i][j][q] = 0.f;

    for (int c = 0; c < nch; ++c) {
        if (c + 1 < nch) { CP_WAIT(1); } else { CP_WAIT(0); }
        __syncthreads();
        if (c + 2 < nch) { issue(c + 2); CP_COMMIT(); }

        const uint32_t st = sb + (uint32_t)(c % 3) * STG2;
        const uint32_t aH = st + aOff;
        const uint32_t aL = aH + APART;
        const uint32_t bH = st + 2 * APART + bOff;
        const uint32_t bL = bH + BPART;

        #pragma unroll
        for (int ks = 0; ks < 2; ks++) {
            uint32_t bh[2][4], bl[2][4];
            #pragma unroll
            for (int np = 0; np < 2; np++) {
                const uint32_t o = (uint32_t)(np * 16 * ROW2 + ks * 32);
                LDSM_X4(bh[np][0], bh[np][1], bh[np][2], bh[np][3], bH + o);
                LDSM_X4(bl[np][0], bl[np][1], bl[np][2], bl[np][3], bL + o);
            }
            #pragma unroll
            for (int mi = 0; mi < 4; mi++) {
                uint32_t ah[4], al[4];
                const uint32_t o = (uint32_t)(mi * 16 * ROW2 + ks * 32);
                LDSM_X4(ah[0], ah[1], ah[2], ah[3], aH + o);
                LDSM_X4(al[0], al[1], al[2], al[3], aL + o);
                #pragma unroll
                for (int np = 0; np < 2; np++)
                    #pragma unroll
                    for (int hf = 0; hf < 2; hf++)
                        MMA16816(acc[mi][np * 2 + hf], ah, bh[np][hf * 2], bh[np][hf * 2 + 1]);
                #pragma unroll
                for (int np = 0; np < 2; np++)
                    #pragma unroll
                    for (int hf = 0; hf < 2; hf++)
                        MMA16816(acc[mi][np * 2 + hf], ah, bl[np][hf * 2], bl[np][hf * 2 + 1]);
                #pragma unroll
                for (int np = 0; np < 2; np++)
                    #pragma unroll
                    for (int hf = 0; hf < 2; hf++)
                        MMA16816(acc[mi][np * 2 + hf], al, bh[np][hf * 2], bh[np][hf * 2 + 1]);
            }
        }
    }

    #pragma unroll
    for (int mi = 0; mi < 4; mi++) {
        const int r = m0 + wm * 64 + mi * 16 + (lane >> 2);
        #pragma unroll
        for (int ni = 0; ni < 4; ni++) {
            const int cc = n0 + wn * 32 + ni * 8 + (lane & 3) * 2;
            *(float2*)&C[(size_t)r * N + cc]       = make_float2(acc[mi][ni][0], acc[mi][ni][1]);
            *(float2*)&C[(size_t)(r + 8) * N + cc] = make_float2(acc[mi][ni][2], acc[mi][ni][3]);
        }
    }
}

// ================= fused flash attention (softcap + causal + online softmax) =================
// CTA = (i-tile of 128 queries, bh). 8 warps (2x4).
// All tiles are 128 rows x 128 bf16 = 256 B data, row stride 272 (FIXED from 144:
// rows were overlapping -> garbage).  P ALIASES the K buffers (K is dead after the
// S MMA; the maxbuf barrier separates last K read from first P write), keeping
// total smem at 213 KB (8 distinct buffers at stride 272 would be 278 KB > cap).
#define FROW  272
#define FTILE (128 * FROW)          // 34816
#define FQ_H  0
#define FQ_L  (FQ_H + FTILE)
#define FK_H  (FQ_L + FTILE)
#define FK_L  (FK_H + FTILE)
#define FV_H  (FK_L + FTILE)
#define FV_L  (FV_H + FTILE)
#define FP_H  FK_H                  // alias
#define FP_L  FK_L                  // alias
#define FRED  (FV_L + FTILE)        // 208896
#define FSMEM (FRED + 2 * 4 * 128 * 4)   // + maxbuf/sumbuf = 212992

__global__ __launch_bounds__(256, 1) void attn_fused(
    const __nv_bfloat16* __restrict__ qh, const __nv_bfloat16* __restrict__ ql,
    const __nv_bfloat16* __restrict__ kh, const __nv_bfloat16* __restrict__ kl,
    const __nv_bfloat16* __restrict__ vth, const __nv_bfloat16* __restrict__ vtl,
    __nv_bfloat16* __restrict__ Oh, __nv_bfloat16* __restrict__ Ol)
{
    extern __shared__ __align__(128) char smem[];
    const uint32_t sb = smem_to_u32(smem);
    const int bh = blockIdx.y;
    const int b = bh >> 4, h = bh & 15, hk = h >> 1;
    const int it = 7 - blockIdx.x;          // biggest CTAs first
    const int i0 = it * 128;
    const int tid = threadIdx.x;
    const int wid = tid >> 5, lane = tid & 31;
    const int wm = wid >> 2, wn = wid & 3;

    // loader mapping: row = tid>>1, half = tid&1 (128 B each; 2 threads cover a 256 B row)
    const int lrow = tid >> 1, half = tid & 1;
    const uint32_t sA = (uint32_t)(lrow * FROW + half * 128);
    const size_t qoff  = ((size_t)(b * SS + i0 + lrow) * HH + h) * HD + half * 64;
    const size_t vbase = ((size_t)(b * KVHN + hk) * HD + lrow) * SS + half * 64;

    // Q + K0 (one group)
    #pragma unroll
    for (int j = 0; j < 8; j++) {
        CP_ASYNC16(sb + FQ_H + sA + j * 16, qh + qoff + j * 8);
        CP_ASYNC16(sb + FQ_L + sA + j * 16, ql + qoff + j * 8);
    }
    {
        const size_t koff = ((size_t)(b * SS + lrow) * KVHN + hk) * HD + half * 64;
        #pragma unroll
        for (int j = 0; j < 8; j++) {
            CP_ASYNC16(sb + FK_H + sA + j * 16, kh + koff + j * 8);
            CP_ASYNC16(sb + FK_L + sA + j * 16, kl + koff + j * 8);
        }
    }
    CP_COMMIT();

    const uint32_t aOff = (uint32_t)((wm * 64 + (lane & 15)) * FROW + (lane >> 4) * 16);
    const uint32_t bOff = (uint32_t)((wn * 32 + ((lane & 7) | ((lane >> 4) << 3))) * FROW
                                     + ((lane >> 3) & 1) * 16);

    float accO[4][4][4];
    float m_run[4][2], l_run[4][2];
    #pragma unroll
    for (int i = 0; i < 4; i++) {
        m_run[i][0] = -1e30f; m_run[i][1] = -1e30f;
        l_run[i][0] = 0.f;    l_run[i][1] = 0.f;
        #pragma unroll
        for (int j = 0; j < 4; j++)
            #pragma unroll
            for (int q = 0; q < 4; q++) accO[i][j][q] = 0.f;
    }

    float* maxbuf = (float*)(smem + FRED);
    float* sumbuf = maxbuf + 4 * 128;
    const int rbase = wm * 64 + (lane >> 2);     // + mi*16 + rr*8

    for (int jt = 0; jt <= it; ++jt) {
        const int j0 = jt * 128;
        // issue V_jt (own group)
        #pragma unroll
        for (int j = 0; j < 8; j++) {
            CP_ASYNC16(sb + FV_H + sA + j * 16, vth + vbase + j0 + j * 8);
            CP_ASYNC16(sb + FV_L + sA + j * 16, vtl + vbase + j0 + j * 8);
        }
        CP_COMMIT();
        CP_WAIT(1);                // K_jt (and Q) ready
        __syncthreads();

        // ---- S = Q·K^T (bf16 x3) ----
        float accS[4][4][4];
        #pragma unroll
        for (int i = 0; i < 4; i++)
            #pragma unroll
            for (int j = 0; j < 4; j++)
                #pragma unroll
                for (int q = 0; q < 4; q++) accS[i][j][q] = 0.f;
        #pragma unroll
        for (int ks = 0; ks < 8; ks++) {
            const uint32_t kof = (uint32_t)(ks * 32);
            uint32_t bhf[2][4], blf[2][4];
            #pragma unroll
            for (int np = 0; np < 2; np++) {
                const uint32_t o = (uint32_t)(np * 16 * FROW) + kof;
                LDSM_X4(bhf[np][0], bhf[np][1], bhf[np][2], bhf[np][3], sb + FK_H + bOff + o);
                LDSM_X4(blf[np][0], blf[np][1], blf[np][2], blf[np][3], sb + FK_L + bOff + o);
            }
            #pragma unroll
            for (int mi = 0; mi < 4; mi++) {
                uint32_t ah[4], al[4];
                const uint32_t o = (uint32_t)(mi * 16 * FROW) + kof;
                LDSM_X4(ah[0], ah[1], ah[2], ah[3], sb + FQ_H + aOff + o);
                LDSM_X4(al[0], al[1], al[2], al[3], sb + FQ_L + aOff + o);
                #pragma unroll
                for (int np = 0; np < 2; np++)
                    #pragma unroll
                    for (int hf = 0; hf < 2; hf++)
                        MMA16816(accS[mi][np * 2 + hf], ah, bhf[np][hf * 2], bhf[np][hf * 2 + 1]);
                #pragma unroll
                for (int np = 0; np < 2; np++)
                    #pragma unroll
                    for (int hf = 0; hf < 2; hf++)
                        MMA16816(accS[mi][np * 2 + hf], ah, blf[np][hf * 2], blf[np][hf * 2 + 1]);
                #pragma unroll
                for (int np = 0; np < 2; np++)
                    #pragma unroll
                    for (int hf = 0; hf < 2; hf++)
                        MMA16816(accS[mi][np * 2 + hf], al, bhf[np][hf * 2], bhf[np][hf * 2 + 1]);
            }
        }

        // ---- softcap + causal mask + row max ----
        const bool diag = (jt == it);
        float mloc[4][2];
        #pragma unroll
        for (int mi = 0; mi < 4; mi++) {
            #pragma unroll
            for (int rr = 0; rr < 2; rr++) {
                const int rL = mi * 16 + rr * 8 + rbase;
                float mx = -3.4e38f;
                #pragma unroll
                for (int ni = 0; ni < 4; ni++) {
                    #pragma unroll
                    for (int c = 0; c < 2; c++) {
                        const int cL = wn * 32 + ni * 8 + (lane & 3) * 2 + c;
                        float s = tanhf(accS[mi][ni][rr * 2 + c] * 0.02f) * 50.f;
                        if (diag && cL > rL) s = KMASK;
                        accS[mi][ni][rr * 2 + c] = s;
                        mx = fmaxf(mx, s);
                    }
                }
                mloc[mi][rr] = mx;
            }
        }
        #pragma unroll
        for (int o = 1; o <= 2; o <<= 1)
            #pragma unroll
            for (int mi = 0; mi < 4; mi++)
                #pragma unroll
                for (int rr = 0; rr < 2; rr++)
                    mloc[mi][rr] = fmaxf(mloc[mi][rr], __shfl_xor_sync(0xffffffffu, mloc[mi][rr], o));
        if ((lane & 3) == 0)
            #pragma unroll
            for (int mi = 0; mi < 4; mi++)
                #pragma unroll
                for (int rr = 0; rr < 2; rr++)
                    maxbuf[wn * 128 + mi * 16 + rr * 8 + rbase] = mloc[mi][rr];
        __syncthreads();        // also separates last K read from P writes below (alias)

        // ---- m_new, alpha, exp, write P (into K buffers), row sums ----
        float alpha[4][2], mnew[4][2], sloc[4][2];
        #pragma unroll
        for (int mi = 0; mi < 4; mi++) {
            #pragma unroll
            for (int rr = 0; rr < 2; rr++) {
                const int r = mi * 16 + rr * 8 + rbase;
                float mt = fmaxf(fmaxf(maxbuf[r], maxbuf[128 + r]),
                                 fmaxf(maxbuf[256 + r], maxbuf[384 + r]));
                float mn = fmaxf(m_run[mi][rr], mt);
                alpha[mi][rr] = __expf(m_run[mi][rr] - mn);
                mnew[mi][rr] = mn;
                m_run[mi][rr] = mn;
                sloc[mi][rr] = 0.f;
            }
        }
        #pragma unroll
        for (int mi = 0; mi < 4; mi++) {
            #pragma unroll
            for (int rr = 0; rr < 2; rr++) {
                const int rL = mi * 16 + rr * 8 + rbase;
                #pragma unroll
                for (int ni = 0; ni < 4; ni++) {
                    float p0 = __expf(accS[mi][ni][rr * 2 + 0] - mnew[mi][rr]);
                    float p1 = __expf(accS[mi][ni][rr * 2 + 1] - mnew[mi][rr]);
                    sloc[mi][rr] += p0 + p1;
                    const int cL = wn * 32 + ni * 8 + (lane & 3) * 2;
                    __nv_bfloat162 hv, lv;
                    split2(p0, hv.x, lv.x); split2(p1, hv.y, lv.y);
                    *(__nv_bfloat162*)(smem + FP_H + rL * FROW + cL * 2) = hv;
                    *(__nv_bfloat162*)(smem + FP_L + rL * FROW + cL * 2) = lv;
                }
            }
        }
        #pragma unroll
        for (int o = 1; o <= 2; o <<= 1)
            #pragma unroll
            for (int mi = 0; mi < 4; mi++)
                #pragma unroll
                for (int rr = 0; rr < 2; rr++)
                    sloc[mi][rr] += __shfl_xor_sync(0xffffffffu, sloc[mi][rr], o);
        if ((lane & 3) == 0)
            #pragma unroll
            for (int mi = 0; mi < 4; mi++)
                #pragma unroll
                for (int rr = 0; rr < 2; rr++)
                    sumbuf[wn * 128 + mi * 16 + rr * 8 + rbase] = sloc[mi][rr];
        __syncthreads();        // P visible to all warps

        #pragma unroll
        for (int mi = 0; mi < 4; mi++) {
            #pragma unroll
            for (int rr = 0; rr < 2; rr++) {
                const int r = mi * 16 + rr * 8 + rbase;
                float st = sumbuf[r] + sumbuf[128 + r] + sumbuf[256 + r] + sumbuf[384 + r];
                l_run[mi][rr] = l_run[mi][rr] * alpha[mi][rr] + st;
                #pragma unroll
                for (int ni = 0; ni < 4; ni++) {
                    accO[mi][ni][rr * 2 + 0] *= alpha[mi][rr];
                    accO[mi][ni][rr * 2 + 1] *= alpha[mi][rr];
                }
            }
        }

        CP_WAIT(0);                 // V_jt landed (this thread's groups)
        __syncthreads();            // all threads' V deposits visible

        // ---- accO += P·V^T (bf16 x3) ----
        #pragma unroll
        for (int ks = 0; ks < 8; ks++) {
            const uint32_t kof = (uint32_t)(ks * 32);
            uint32_t bhf[2][4], blf[2][4];
            #pragma unroll
            for (int np = 0; np < 2; np++) {
                const uint32_t o = (uint32_t)(np * 16 * FROW) + kof;
                LDSM_X4(bhf[np][0], bhf[np][1], bhf[np][2], bhf[np][3], sb + FV_H + bOff + o);
                LDSM_X4(blf[np][0], blf[np][1], blf[np][2], blf[np][3], sb + FV_L + bOff + o);
            }
            #pragma unroll
            for (int mi = 0; mi < 4; mi++) {
                uint32_t ah[4], al[4];
                const uint32_t o = (uint32_t)(mi * 16 * FROW) + kof;
                LDSM_X4(ah[0], ah[1], ah[2], ah[3], sb + FP_H + aOff + o);
                LDSM_X4(al[0], al[1], al[2], al[3], sb + FP_L + aOff + o);
                #pragma unroll
                for (int np = 0; np < 2; np++)
                    #pragma unroll
                    for (int hf = 0; hf < 2; hf++)
                        MMA16816(accO[mi][np * 2 + hf], ah, bhf[np][hf * 2], bhf[np][hf * 2 + 1]);
                #pragma unroll
                for (int np = 0; np < 2; np++)
                    #pragma unroll
                    for (int hf = 0; hf < 2; hf++)
                        MMA16816(accO[mi][np * 2 + hf], ah, blf[np][hf * 2], blf[np][hf * 2 + 1]);
                #pragma unroll
                for (int np = 0; np < 2; np++)
                    #pragma unroll
                    for (int hf = 0; hf < 2; hf++)
                        MMA16816(accO[mi][np * 2 + hf], al, bhf[np][hf * 2], bhf[np][hf * 2 + 1]);
            }
        }
        __syncthreads();            // all P reads done before K_{jt+1} overwrites the buffer

        if (jt < it) {              // load next K into the (aliased) K/P buffer
            const size_t koff = ((size_t)(b * SS + j0 + 128 + lrow) * KVHN + hk) * HD + half * 64;
            #pragma unroll
            for (int j = 0; j < 8; j++) {
                CP_ASYNC16(sb + FK_H + sA + j * 16, kh + koff + j * 8);
                CP_ASYNC16(sb + FK_L + sA + j * 16, kl + koff + j * 8);
            }
            CP_COMMIT();
        }
    }

    // ---- epilogue: normalize and write bf16 hi/lo ----
    #pragma unroll
    for (int mi = 0; mi < 4; mi++) {
        #pragma unroll
        for (int rr = 0; rr < 2; rr++) {
            const float inv = 1.f / l_run[mi][rr];
            const int r = wm * 64 + mi * 16 + rr * 8 + (lane >> 2);
            const size_t rowoff = ((size_t)b * SS + i0 + r) * (HH * HD) + h * HD;
            #pragma unroll
            for (int ni = 0; ni < 4; ni++) {
                const int cc = wn * 32 + ni * 8 + (lane & 3) * 2;
                __nv_bfloat162 hv, lv;
                split2(accO[mi][ni][rr * 2 + 0] * inv, hv.x, lv.x);
                split2(accO[mi][ni][rr * 2 + 1] * inv, hv.y, lv.y);
                *(__nv_bfloat162*)(Oh + rowoff + cc) = hv;
                *(__nv_bfloat162*)(Ol + rowoff + cc) = lv;
            }
        }
    }
}

// ================= GeGLU -> bf16 hi/lo =================
__global__ __launch_bounds__(256) void geglu_kernel(
    const float* __restrict__ gate, const float* __restrict__ up,
    __nv_bfloat16* __restrict__ oh, __nv_bfloat16* __restrict__ ol, size_t n)
{
    size_t i = (size_t)blockIdx.x * 256 + threadIdx.x;
    if (i < n) {
        float x = gate[i];
        float t = 0.7978845608028654f * (x + 0.044715f * x * x * x);
        float g = 0.5f * x * (1.f + tanhf(t));
        float r = g * up[i];
        __nv_bfloat16 h, l; split2(r, h, l);
        oh[i] = h; ol[i] = l;
    }
}

// ================= launch =================
static inline void run_split(const float* w, __nv_bfloat16* h, __nv_bfloat16* l, size_t n) {
    int n4 = (int)(n / 4);
    split_kernel<<<(n4 + 255) / 256, 256>>>((const float4*)w, (__nv_bfloat162*)h,
                                            (__nv_bfloat162*)l, n4);
}

extern "C" void kernel_launch(void* const* d_in, const int* in_sizes, int n_in,
                              void* d_out, int out_size)
{
    const float* x          = (const float*)d_in[0];
    const int*   positions  = (const int*)  d_in[1];
    const float* wq         = (const float*)d_in[4];
    const float* wk         = (const float*)d_in[5];
    const float* wv         = (const float*)d_in[6];
    const float* wo         = (const float*)d_in[7];
    const float* q_scale    = (const float*)d_in[8];
    const float* k_scale    = (const float*)d_in[9];
    const float* pre_attn   = (const float*)d_in[10];
    const float* post_attn  = (const float*)d_in[11];
    const float* pre_ffn    = (const float*)d_in[12];
    const float* post_ffn   = (const float*)d_in[13];
    const float* w_gate     = (const float*)d_in[14];
    const float* w_up       = (const float*)d_in[15];
    const float* w_down     = (const float*)d_in[16];
    const float* layer_scal = (const float*)d_in[17];
    float* out = (float*)d_out;

    float *q_, *k_, *v_, *tmp_, *x2_, *gate_, *up_, *ffn_;
    __nv_bfloat16 *ah_, *al_, *qh_, *ql_, *kh_, *kl_, *vth_, *vtl_;
    __nv_bfloat16 *wqh, *wql, *wkh, *wkl, *wvh, *wvl, *woh, *wol, *wgh, *wgl, *wuh, *wul, *wdh, *wdl;
    cudaGetSymbolAddress((void**)&q_,   g_q);
    cudaGetSymbolAddress((void**)&k_,   g_k);
    cudaGetSymbolAddress((void**)&v_,   g_v);
    cudaGetSymbolAddress((void**)&tmp_, g_tmp);
    cudaGetSymbolAddress((void**)&x2_,  g_x2);
    cudaGetSymbolAddress((void**)&gate_,g_gate);
    cudaGetSymbolAddress((void**)&up_,  g_up);
    cudaGetSymbolAddress((void**)&ffn_, g_ffn);
    cudaGetSymbolAddress((void**)&ah_,  g_ah);
    cudaGetSymbolAddress((void**)&al_,  g_al);
    cudaGetSymbolAddress((void**)&qh_,  g_qh);  cudaGetSymbolAddress((void**)&ql_,  g_ql);
    cudaGetSymbolAddress((void**)&kh_,  g_kh);  cudaGetSymbolAddress((void**)&kl_,  g_kl);
    cudaGetSymbolAddress((void**)&vth_, g_vth); cudaGetSymbolAddress((void**)&vtl_, g_vtl);
    cudaGetSymbolAddress((void**)&wqh, g_wqh); cudaGetSymbolAddress((void**)&wql, g_wql);
    cudaGetSymbolAddress((void**)&wkh, g_wkh); cudaGetSymbolAddress((void**)&wkl, g_wkl);
    cudaGetSymbolAddress((void**)&wvh, g_wvh); cudaGetSymbolAddress((void**)&wvl, g_wvl);
    cudaGetSymbolAddress((void**)&woh, g_woh); cudaGetSymbolAddress((void**)&wol, g_wol);
    cudaGetSymbolAddress((void**)&wgh, g_wgh); cudaGetSymbolAddress((void**)&wgl, g_wgl);
    cudaGetSymbolAddress((void**)&wuh, g_wuh); cudaGetSymbolAddress((void**)&wul, g_wul);
    cudaGetSymbolAddress((void**)&wdh, g_wdh); cudaGetSymbolAddress((void**)&wdl, g_wdl);

    cudaFuncSetAttribute(gemm_mma,   cudaFuncAttributeMaxDynamicSharedMemorySize, GSMEM2);
    cudaFuncSetAttribute(attn_fused, cudaFuncAttributeMaxDynamicSharedMemorySize, FSMEM);

    // weight splits
    run_split(wq,     wqh, wql, (size_t)HH * HD * DD);
    run_split(wk,     wkh, wkl, (size_t)KVHN * HD * DD);
    run_split(wv,     wvh, wvl, (size_t)KVHN * HD * DD);
    run_split(wo,     woh, wol, (size_t)DD * HH * HD);
    run_split(w_gate, wgh, wgl, (size_t)FFN * DD);
    run_split(w_up,   wuh, wul, (size_t)FFN * DD);
    run_split(w_down, wdh, wdl, (size_t)DD * FFN);

    // ---- attention sub-block ----
    rmsnorm_kernel<<<MM, 256>>>(x, pre_attn, nullptr, nullptr, nullptr, ah_, al_, DD);
    gemm_mma<<<dim3((HH*HD)/128,   MM/256), 512, GSMEM2>>>(ah_, al_, wqh, wql, q_, MM, HH*HD,   DD);
    gemm_mma<<<dim3((KVHN*HD)/128, MM/256), 512, GSMEM2>>>(ah_, al_, wkh, wkl, k_, MM, KVHN*HD, DD);
    gemm_mma<<<dim3((KVHN*HD)/128, MM/256), 512, GSMEM2>>>(ah_, al_, wvh, wvl, v_, MM, KVHN*HD, DD);
    headnorm_rope_kernel<<<MM * HH,   128>>>(q_, q_scale, positions, HH,   1, qh_, ql_);
    headnorm_rope_kernel<<<MM * KVHN, 128>>>(k_, k_scale, positions, KVHN, 1, kh_, kl_);
    headnorm_rope_kernel<<<MM * KVHN, 128>>>(v_, nullptr, positions, KVHN, 0, nullptr, nullptr);
    vtrans_kernel<<<dim3(SS/32, HD/32, BB*KVHN), 256>>>(v_, vth_, vtl_);
    attn_fused<<<dim3(SS/128, BB*HH), 256, FSMEM>>>(qh_, ql_, kh_, kl_, vth_, vtl_, ah_, al_);
    gemm_mma<<<dim3(DD/128, MM/256), 512, GSMEM2>>>(ah_, al_, woh, wol, tmp_, MM, DD, HH*HD);
    rmsnorm_kernel<<<MM, 256>>>(tmp_, post_attn, x, nullptr, x2_, nullptr, nullptr, DD);

    // ---- FFN sub-block ----
    rmsnorm_kernel<<<MM, 256>>>(x2_, pre_ffn, nullptr, nullptr, nullptr, ah_, al_, DD);
    gemm_mma<<<dim3(FFN/128, MM/256), 512, GSMEM2>>>(ah_, al_, wgh, wgl, gate_, MM, FFN, DD);
    gemm_mma<<<dim3(FFN/128, MM/256), 512, GSMEM2>>>(ah_, al_, wuh, wul, up_,   MM, FFN, DD);
    size_t nact = (size_t)MM * FFN;
    geglu_kernel<<<(unsigned)((nact + 255) / 256), 256>>>(gate_, up_, ah_, al_, nact);
    gemm_mma<<<dim3(DD/128, MM/256), 512, GSMEM2>>>(ah_, al_, wdh, wdl, ffn_, MM, DD, FFN);
    rmsnorm_kernel<<<MM, 256>>>(ffn_, post_ffn, x2_, layer_scal, out, nullptr, nullptr, DD);
}

// round 13
// speedup vs baseline: 1.0957x; 1.0123x over previous
#include <cuda_runtime.h>
#include <cuda_bf16.h>
#include <cstdint>
#include <math.h>

#define BB 4
#define SS 1024
#define DD 2048
#define HH 16
#define KVHN 8
#define HD 128
#define FFN 8192
#define MM (BB*SS)
#define EPS_RMS 1e-6f
#define KMASK -1e30f

// ================= PTX helpers (base sm_103 ISA only) =================
__device__ __forceinline__ uint32_t smem_to_u32(const void* p) {
    uint32_t a;
    asm("{ .reg .u64 t; cvta.to.shared.u64 t, %1; cvt.u32.u64 %0, t; }" : "=r"(a) : "l"(p));
    return a;
}
#define CP_ASYNC16(sa, gp) \
    asm volatile("cp.async.cg.shared.global [%0], [%1], 16;" :: "r"(sa), "l"(gp) : "memory")
#define CP_COMMIT() asm volatile("cp.async.commit_group;" ::: "memory")
#define CP_WAIT(n)  asm volatile("cp.async.wait_group %0;" :: "n"(n) : "memory")

#define LDSM_X4(r0, r1, r2, r3, sa) \
    asm volatile("ldmatrix.sync.aligned.m8n8.x4.shared.b16 {%0,%1,%2,%3}, [%4];" \
                 : "=r"(r0), "=r"(r1), "=r"(r2), "=r"(r3) : "r"(sa))

#define MMA16816(d, a, b0, b1) \
    asm volatile("mma.sync.aligned.m16n8k16.row.col.f32.bf16.bf16.f32 " \
                 "{%0,%1,%2,%3}, {%4,%5,%6,%7}, {%8,%9}, {%0,%1,%2,%3};" \
                 : "+f"((d)[0]), "+f"((d)[1]), "+f"((d)[2]), "+f"((d)[3]) \
                 : "r"((a)[0]), "r"((a)[1]), "r"((a)[2]), "r"((a)[3]), "r"(b0), "r"(b1))

// ================= scratch =================
__device__ float g_q   [(size_t)MM*HH*HD];
__device__ float g_k   [(size_t)MM*KVHN*HD];
__device__ float g_v   [(size_t)MM*KVHN*HD];
__device__ float g_tmp [(size_t)MM*DD];
__device__ float g_x2  [(size_t)MM*DD];
__device__ float g_gate[(size_t)MM*FFN];
__device__ float g_ffn [(size_t)MM*DD];
__device__ __nv_bfloat16 g_ah[(size_t)MM*FFN];
__device__ __nv_bfloat16 g_al[(size_t)MM*FFN];
__device__ __nv_bfloat16 g_uh[(size_t)MM*FFN];
__device__ __nv_bfloat16 g_ul[(size_t)MM*FFN];
// attention bf16 operands
__device__ __nv_bfloat16 g_qh[(size_t)MM*HH*HD],   g_ql[(size_t)MM*HH*HD];
__device__ __nv_bfloat16 g_kh[(size_t)MM*KVHN*HD], g_kl[(size_t)MM*KVHN*HD];
__device__ __nv_bfloat16 g_vth[(size_t)MM*KVHN*HD],g_vtl[(size_t)MM*KVHN*HD];
// bf16 hi/lo weights
__device__ __nv_bfloat16 g_wqh[(size_t)HH*HD*DD],  g_wql[(size_t)HH*HD*DD];
__device__ __nv_bfloat16 g_wkh[(size_t)KVHN*HD*DD],g_wkl[(size_t)KVHN*HD*DD];
__device__ __nv_bfloat16 g_wvh[(size_t)KVHN*HD*DD],g_wvl[(size_t)KVHN*HD*DD];
__device__ __nv_bfloat16 g_woh[(size_t)DD*HH*HD],  g_wol[(size_t)DD*HH*HD];
__device__ __nv_bfloat16 g_wgh[(size_t)FFN*DD],    g_wgl[(size_t)FFN*DD];
__device__ __nv_bfloat16 g_wuh[(size_t)FFN*DD],    g_wul[(size_t)FFN*DD];
__device__ __nv_bfloat16 g_wdh[(size_t)DD*FFN],    g_wdl[(size_t)DD*FFN];

__device__ __forceinline__ void split2(float v, __nv_bfloat16& h, __nv_bfloat16& l) {
    h = __float2bfloat16(v);
    l = __float2bfloat16(v - __bfloat162float(h));
}
__device__ __forceinline__ float gelu_tanh(float x) {
    float t = 0.7978845608028654f * (x + 0.044715f * x * x * x);
    return 0.5f * x * (1.f + tanhf(t));
}

// ================= weight split =================
__global__ __launch_bounds__(256) void split_kernel(
    const float4* __restrict__ x, __nv_bfloat162* __restrict__ hi,
    __nv_bfloat162* __restrict__ lo, int n4)
{
    int i = blockIdx.x * 256 + threadIdx.x;
    if (i < n4) {
        float4 v = x[i];
        __nv_bfloat162 a, b, c, d;
        split2(v.x, a.x, c.x); split2(v.y, a.y, c.y);
        split2(v.z, b.x, d.x); split2(v.w, b.y, d.y);
        hi[2*i] = a; hi[2*i+1] = b; lo[2*i] = c; lo[2*i+1] = d;
    }
}

// ================= RMSNorm =================
__global__ __launch_bounds__(256) void rmsnorm_kernel(
    const float* __restrict__ in, const float* __restrict__ scale,
    const float* __restrict__ resid, const float* __restrict__ lsc,
    float* __restrict__ out, __nv_bfloat16* __restrict__ oh,
    __nv_bfloat16* __restrict__ ol, int N)
{
    __shared__ float red[8];
    const size_t row = blockIdx.x;
    const float* x = in + row * (size_t)N;
    float ss = 0.f;
    for (int j = threadIdx.x; j < N; j += 256) { float v = x[j]; ss = fmaf(v, v, ss); }
    int lane = threadIdx.x & 31, wid = threadIdx.x >> 5;
    #pragma unroll
    for (int o = 16; o > 0; o >>= 1) ss += __shfl_down_sync(0xffffffffu, ss, o);
    if (lane == 0) red[wid] = ss;
    __syncthreads();
    if (threadIdx.x == 0) {
        float s = 0.f;
        #pragma unroll
        for (int w = 0; w < 8; w++) s += red[w];
        red[0] = s;
    }
    __syncthreads();
    const float r = rsqrtf(red[0] / (float)N + EPS_RMS);
    const float ls = lsc ? lsc[0] : 1.f;
    const float* rp = resid ? resid + row * (size_t)N : nullptr;
    for (int j = threadIdx.x; j < N; j += 256) {
        float v = x[j] * r;
        if (scale) v *= scale[j];
        if (rp) v += rp[j];
        v *= ls;
        if (out) out[row * (size_t)N + j] = v;
        if (oh) {
            __nv_bfloat16 h, l; split2(v, h, l);
            oh[row * (size_t)N + j] = h; ol[row * (size_t)N + j] = l;
        }
    }
}

// ===== fused double RMSNorm: x2 = rms(tmp)*s1 + resid; oh/ol = split(rms(x2)*s2) =====
__global__ __launch_bounds__(256) void rmsnorm2_kernel(
    const float* __restrict__ tmp, const float* __restrict__ s1,
    const float* __restrict__ resid, const float* __restrict__ s2,
    float* __restrict__ x2, __nv_bfloat16* __restrict__ oh,
    __nv_bfloat16* __restrict__ ol)
{
    __shared__ float red[8];
    const size_t base = (size_t)blockIdx.x * DD;
    const int tid = threadIdx.x;
    const int lane = tid & 31, wid = tid >> 5;
    float t[8];
    float ss = 0.f;
    #pragma unroll
    for (int q = 0; q < 8; q++) {
        t[q] = tmp[base + q * 256 + tid];
        ss = fmaf(t[q], t[q], ss);
    }
    #pragma unroll
    for (int o = 16; o > 0; o >>= 1) ss += __shfl_down_sync(0xffffffffu, ss, o);
    if (lane == 0) red[wid] = ss;
    __syncthreads();
    if (tid == 0) {
        float s = 0.f;
        #pragma unroll
        for (int w = 0; w < 8; w++) s += red[w];
        red[0] = s;
    }
    __syncthreads();
    const float r1 = rsqrtf(red[0] / (float)DD + EPS_RMS);
    __syncthreads();   // all reads of red[0] done before reuse
    float v[8];
    float ss2 = 0.f;
    #pragma unroll
    for (int q = 0; q < 8; q++) {
        const int j = q * 256 + tid;
        v[q] = t[q] * r1 * s1[j] + resid[base + j];
        x2[base + j] = v[q];
        ss2 = fmaf(v[q], v[q], ss2);
    }
    #pragma unroll
    for (int o = 16; o > 0; o >>= 1) ss2 += __shfl_down_sync(0xffffffffu, ss2, o);
    if (lane == 0) red[wid] = ss2;
    __syncthreads();
    if (tid == 0) {
        float s = 0.f;
        #pragma unroll
        for (int w = 0; w < 8; w++) s += red[w];
        red[0] = s;
    }
    __syncthreads();
    const float r2 = rsqrtf(red[0] / (float)DD + EPS_RMS);
    #pragma unroll
    for (int q = 0; q < 8; q++) {
        const int j = q * 256 + tid;
        float o = v[q] * r2 * s2[j];
        __nv_bfloat16 h, l; split2(o, h, l);
        oh[base + j] = h; ol[base + j] = l;
    }
}

// ================= per-head RMSNorm (+ RoPE); optional bf16 hi/lo output =================
__global__ __launch_bounds__(128) void headnorm_rope_kernel(
    float* __restrict__ data, const float* __restrict__ scale,
    const int* __restrict__ positions, int nheads, int do_rope,
    __nv_bfloat16* __restrict__ oh, __nv_bfloat16* __restrict__ ol)
{
    __shared__ float red[4];
    __shared__ float sv[HD];
    const int d = threadIdx.x;
    const int idx = blockIdx.x;
    const int token = idx / nheads;
    float* p = data + (size_t)idx * HD;
    float v = p[d];
    float ss = v * v;
    int lane = d & 31, wid = d >> 5;
    #pragma unroll
    for (int o = 16; o > 0; o >>= 1) ss += __shfl_down_sync(0xffffffffu, ss, o);
    if (lane == 0) red[wid] = ss;
    __syncthreads();
    const float total = red[0] + red[1] + red[2] + red[3];
    const float r = rsqrtf(total * (1.0f / HD) + EPS_RMS);
    float nv = v * r;
    if (scale) nv *= scale[d];
    if (do_rope) {
        sv[d] = nv;
        __syncthreads();
        if (d < 64) {
            const int pos = positions[token];
            double freq = pow(10000.0, -((double)(2 * d) / 128.0));
            double ang = (double)pos * freq;
            double dsin, dcos;
            sincos(ang, &dsin, &dcos);
            float c = (float)dcos, s = (float)dsin;
            float x1 = sv[d], x2 = sv[d + 64];
            float o1 = x1 * c - x2 * s;
            float o2 = x2 * c + x1 * s;
            __nv_bfloat16 h1, l1, h2, l2;
            split2(o1, h1, l1); split2(o2, h2, l2);
            oh[(size_t)idx * HD + d]      = h1; ol[(size_t)idx * HD + d]      = l1;
            oh[(size_t)idx * HD + d + 64] = h2; ol[(size_t)idx * HD + d + 64] = l2;
        }
    } else {
        p[d] = nv;
    }
}

// ================= V transpose + split =================
__global__ __launch_bounds__(256) void vtrans_kernel(
    const float* __restrict__ v, __nv_bfloat16* __restrict__ vth,
    __nv_bfloat16* __restrict__ vtl)
{
    __shared__ float tile[32][33];
    const int z = blockIdx.z;
    const int b = z >> 3, hk = z & 7;
    const int s0 = blockIdx.x * 32, d0 = blockIdx.y * 32;
    const int tx = threadIdx.x & 31, ty = threadIdx.x >> 5;
    #pragma unroll
    for (int r = ty; r < 32; r += 8)
        tile[r][tx] = v[(size_t)(b * SS + s0 + r) * (KVHN * HD) + hk * HD + d0 + tx];
    __syncthreads();
    #pragma unroll
    for (int r = ty; r < 32; r += 8) {
        float val = tile[tx][r];
        __nv_bfloat16 h, l; split2(val, h, l);
        const size_t off = ((size_t)(b * KVHN + hk) * HD + d0 + r) * SS + s0 + tx;
        vth[off] = h; vtl[off] = l;
    }
}

// ================= HMMA bf16x3 GEMM core (shared mainloop macro) =================
#define ROW2  80
#define APART (256 * ROW2)
#define BPART (128 * ROW2)
#define STG2  (2 * APART + 2 * BPART)
#define GSMEM2 (3 * STG2)

#define GEMM_PROLOGUE_AND_MAINLOOP()                                              \
    extern __shared__ __align__(128) char smem[];                                 \
    const uint32_t sb = smem_to_u32(smem);                                        \
    const int tid = threadIdx.x;                                                  \
    const int wid = tid >> 5, lane = tid & 31;                                    \
    const int wm = wid >> 2, wn = wid & 3;                                        \
    const int m0 = blockIdx.y * 256, n0 = blockIdx.x * 128;                       \
    const int arow = tid >> 1;                                                    \
    const int acs  = (tid & 1) * 2;                                               \
    const int brow = tid >> 2;                                                    \
    const int bcs  = tid & 3;                                                     \
    const __nv_bfloat16* gAh = Ah + (size_t)(m0 + arow) * K + acs * 8;            \
    const __nv_bfloat16* gAl = Al + (size_t)(m0 + arow) * K + acs * 8;            \
    const __nv_bfloat16* gBh = Bh + (size_t)(n0 + brow) * K + bcs * 8;            \
    const __nv_bfloat16* gBl = Bl + (size_t)(n0 + brow) * K + bcs * 8;            \
    const uint32_t aS = (uint32_t)(arow * ROW2 + acs * 16);                       \
    const uint32_t bS = (uint32_t)(brow * ROW2 + bcs * 16);                       \
    const int nch = K / 32;                                                       \
    auto issue = [&](int c) {                                                     \
        const uint32_t st = sb + (uint32_t)(c % 3) * STG2;                        \
        const size_t ko = (size_t)c * 32;                                         \
        CP_ASYNC16(st + aS,                 gAh + ko);                            \
        CP_ASYNC16(st + aS + 16,            gAh + ko + 8);                        \
        CP_ASYNC16(st + APART + aS,         gAl + ko);                            \
        CP_ASYNC16(st + APART + aS + 16,    gAl + ko + 8);                        \
        CP_ASYNC16(st + 2 * APART + bS,         gBh + ko);                        \
        CP_ASYNC16(st + 2 * APART + BPART + bS, gBl + ko);                        \
    };                                                                            \
    issue(0); CP_COMMIT();                                                        \
    issue(1); CP_COMMIT();                                                        \
    const uint32_t aOff = (uint32_t)((wm * 64 + (lane & 15)) * ROW2 + (lane >> 4) * 16); \
    const uint32_t bOff = (uint32_t)((wn * 32 + ((lane & 7) | ((lane >> 4) << 3))) * ROW2 \
                                     + ((lane >> 3) & 1) * 16);                   \
    float acc[4][4][4];                                                           \
    _Pragma("unroll")                                                             \
    for (int i = 0; i < 4; i++)                                                   \
        _Pragma("unroll")                                                         \
        for (int j = 0; j < 4; j++)                                               \
            _Pragma("unroll")                                                     \
            for (int q = 0; q < 4; q++) acc[i][j][q] = 0.f;                       \
    for (int c = 0; c < nch; ++c) {                                               \
        if (c + 1 < nch) { CP_WAIT(1); } else { CP_WAIT(0); }                     \
        __syncthreads();                                                          \
        if (c + 2 < nch) { issue(c + 2); CP_COMMIT(); }                           \
        const uint32_t st = sb + (uint32_t)(c % 3) * STG2;                        \
        const uint32_t aH = st + aOff;                                            \
        const uint32_t aL = aH + APART;                                           \
        const uint32_t bH = st + 2 * APART + bOff;                                \
        const uint32_t bL = bH + BPART;                                           \
        _Pragma("unroll")                                                         \
        for (int ks = 0; ks < 2; ks++) {                                          \
            uint32_t bh[2][4], bl[2][4];                                          \
            _Pragma("unroll")                                                     \
            for (int np = 0; np < 2; np++) {                                      \
                const uint32_t o = (uint32_t)(np * 16 * ROW2 + ks * 32);          \
                LDSM_X4(bh[np][0], bh[np][1], bh[np][2], bh[np][3], bH + o);      \
                LDSM_X4(bl[np][0], bl[np][1], bl[np][2], bl[np][3], bL + o);      \
            }                                                                     \
            _Pragma("unroll")                                                     \
            for (int mi = 0; mi < 4; mi++) {                                      \
                uint32_t ah[4], al[4];                                            \
                const uint32_t o = (uint32_t)(mi * 16 * ROW2 + ks * 32);          \
                LDSM_X4(ah[0], ah[1], ah[2], ah[3], aH + o);                      \
                LDSM_X4(al[0], al[1], al[2], al[3], aL + o);                      \
                _Pragma("unroll")                                                 \
                for (int np = 0; np < 2; np++)                                    \
                    _Pragma("unroll")                                             \
                    for (int hf = 0; hf < 2; hf++)                                \
                        MMA16816(acc[mi][np * 2 + hf], ah, bh[np][hf * 2], bh[np][hf * 2 + 1]); \
                _Pragma("unroll")                                                 \
                for (int np = 0; np < 2; np++)                                    \
                    _Pragma("unroll")                                             \
                    for (int hf = 0; hf < 2; hf++)                                \
                        MMA16816(acc[mi][np * 2 + hf], ah, bl[np][hf * 2], bl[np][hf * 2 + 1]); \
                _Pragma("unroll")                                                 \
                for (int np = 0; np < 2; np++)                                    \
                    _Pragma("unroll")                                             \
                    for (int hf = 0; hf < 2; hf++)                                \
                        MMA16816(acc[mi][np * 2 + hf], al, bh[np][hf * 2], bh[np][hf * 2 + 1]); \
            }                                                                     \
        }                                                                         \
    }

__global__ __launch_bounds__(512, 1) void gemm_mma(
    const __nv_bfloat16* __restrict__ Ah, const __nv_bfloat16* __restrict__ Al,
    const __nv_bfloat16* __restrict__ Bh, const __nv_bfloat16* __restrict__ Bl,
    float* __restrict__ C, int M, int N, int K)
{
    GEMM_PROLOGUE_AND_MAINLOOP()
    #pragma unroll
    for (int mi = 0; mi < 4; mi++) {
        const int r = m0 + wm * 64 + mi * 16 + (lane >> 2);
        #pragma unroll
        for (int ni = 0; ni < 4; ni++) {
            const int cc = n0 + wn * 32 + ni * 8 + (lane & 3) * 2;
            *(float2*)&C[(size_t)r * N + cc]       = make_float2(acc[mi][ni][0], acc[mi][ni][1]);
            *(float2*)&C[(size_t)(r + 8) * N + cc] = make_float2(acc[mi][ni][2], acc[mi][ni][3]);
        }
    }
}

// up-GEMM with fused GeGLU epilogue: out = split(gelu(gate) * acc)
__global__ __launch_bounds__(512, 1) void gemm_mma_geglu(
    const __nv_bfloat16* __restrict__ Ah, const __nv_bfloat16* __restrict__ Al,
    const __nv_bfloat16* __restrict__ Bh, const __nv_bfloat16* __restrict__ Bl,
    const float* __restrict__ gate,
    __nv_bfloat16* __restrict__ Oh, __nv_bfloat16* __restrict__ Ol,
    int M, int N, int K)
{
    GEMM_PROLOGUE_AND_MAINLOOP()
    #pragma unroll
    for (int mi = 0; mi < 4; mi++) {
        #pragma unroll
        for (int rr = 0; rr < 2; rr++) {
            const int r = m0 + wm * 64 + mi * 16 + rr * 8 + (lane >> 2);
            #pragma unroll
            for (int ni = 0; ni < 4; ni++) {
                const int cc = n0 + wn * 32 + ni * 8 + (lane & 3) * 2;
                float2 g = *(const float2*)&gate[(size_t)r * N + cc];
                float r0 = gelu_tanh(g.x) * acc[mi][ni][rr * 2 + 0];
                float r1 = gelu_tanh(g.y) * acc[mi][ni][rr * 2 + 1];
                __nv_bfloat162 hv, lv;
                split2(r0, hv.x, lv.x); split2(r1, hv.y, lv.y);
                *(__nv_bfloat162*)(Oh + (size_t)r * N + cc) = hv;
                *(__nv_bfloat162*)(Ol + (size_t)r * N + cc) = lv;
            }
        }
    }
}

// ================= fused flash attention (unchanged from R11, passing) =================
#define FROW  272
#define FTILE (128 * FROW)
#define FQ_H  0
#define FQ_L  (FQ_H + FTILE)
#define FK_H  (FQ_L + FTILE)
#define FK_L  (FK_H + FTILE)
#define FV_H  (FK_L + FTILE)
#define FV_L  (FV_H + FTILE)
#define FP_H  FK_H
#define FP_L  FK_L
#define FRED  (FV_L + FTILE)
#define FSMEM (FRED + 2 * 4 * 128 * 4)

__global__ __launch_bounds__(256, 1) void attn_fused(
    const __nv_bfloat16* __restrict__ qh, const __nv_bfloat16* __restrict__ ql,
    const __nv_bfloat16* __restrict__ kh, const __nv_bfloat16* __restrict__ kl,
    const __nv_bfloat16* __restrict__ vth, const __nv_bfloat16* __restrict__ vtl,
    __nv_bfloat16* __restrict__ Oh, __nv_bfloat16* __restrict__ Ol)
{
    extern __shared__ __align__(128) char smem[];
    const uint32_t sb = smem_to_u32(smem);
    const int bh = blockIdx.y;
    const int b = bh >> 4, h = bh & 15, hk = h >> 1;
    const int it = 7 - blockIdx.x;
    const int i0 = it * 128;
    const int tid = threadIdx.x;
    const int wid = tid >> 5, lane = tid & 31;
    const int wm = wid >> 2, wn = wid & 3;

    const int lrow = tid >> 1, half = tid & 1;
    const uint32_t sA = (uint32_t)(lrow * FROW + half * 128);
    const size_t qoff  = ((size_t)(b * SS + i0 + lrow) * HH + h) * HD + half * 64;
    const size_t vbase = ((size_t)(b * KVHN + hk) * HD + lrow) * SS + half * 64;

    #pragma unroll
    for (int j = 0; j < 8; j++) {
        CP_ASYNC16(sb + FQ_H + sA + j * 16, qh + qoff + j * 8);
        CP_ASYNC16(sb + FQ_L + sA + j * 16, ql + qoff + j * 8);
    }
    {
        const size_t koff = ((size_t)(b * SS + lrow) * KVHN + hk) * HD + half * 64;
        #pragma unroll
        for (int j = 0; j < 8; j++) {
            CP_ASYNC16(sb + FK_H + sA + j * 16, kh + koff + j * 8);
            CP_ASYNC16(sb + FK_L + sA + j * 16, kl + koff + j * 8);
        }
    }
    CP_COMMIT();

    const uint32_t aOff = (uint32_t)((wm * 64 + (lane & 15)) * FROW + (lane >> 4) * 16);
    const uint32_t bOff = (uint32_t)((wn * 32 + ((lane & 7) | ((lane >> 4) << 3))) * FROW
                                     + ((lane >> 3) & 1) * 16);

    float accO[4][4][4];
    float m_run[4][2], l_run[4][2];
    #pragma unroll
    for (int i = 0; i < 4; i++) {
        m_run[i][0] = -1e30f; m_run[i][1] = -1e30f;
        l_run[i][0] = 0.f;    l_run[i][1] = 0.f;
        #pragma unroll
        for (int j = 0; j < 4; j++)
            #pragma unroll
            for (int q = 0; q < 4; q++) accO[i][j][q] = 0.f;
    }

    float* maxbuf = (float*)(smem + FRED);
    float* sumbuf = maxbuf + 4 * 128;
    const int rbase = wm * 64 + (lane >> 2);

    for (int jt = 0; jt <= it; ++jt) {
        const int j0 = jt * 128;
        #pragma unroll
        for (int j = 0; j < 8; j++) {
            CP_ASYNC16(sb + FV_H + sA + j * 16, vth + vbase + j0 + j * 8);
            CP_ASYNC16(sb + FV_L + sA + j * 16, vtl + vbase + j0 + j * 8);
        }
        CP_COMMIT();
        CP_WAIT(1);
        __syncthreads();

        float accS[4][4][4];
        #pragma unroll
        for (int i = 0; i < 4; i++)
            #pragma unroll
            for (int j = 0; j < 4; j++)
                #pragma unroll
                for (int q = 0; q < 4; q++) accS[i][j][q] = 0.f;
        #pragma unroll
        for (int ks = 0; ks < 8; ks++) {
            const uint32_t kof = (uint32_t)(ks * 32);
            uint32_t bhf[2][4], blf[2][4];
            #pragma unroll
            for (int np = 0; np < 2; np++) {
                const uint32_t o = (uint32_t)(np * 16 * FROW) + kof;
                LDSM_X4(bhf[np][0], bhf[np][1], bhf[np][2], bhf[np][3], sb + FK_H + bOff + o);
                LDSM_X4(blf[np][0], blf[np][1], blf[np][2], blf[np][3], sb + FK_L + bOff + o);
            }
            #pragma unroll
            for (int mi = 0; mi < 4; mi++) {
                uint32_t ah[4], al[4];
                const uint32_t o = (uint32_t)(mi * 16 * FROW) + kof;
                LDSM_X4(ah[0], ah[1], ah[2], ah[3], sb + FQ_H + aOff + o);
                LDSM_X4(al[0], al[1], al[2], al[3], sb + FQ_L + aOff + o);
                #pragma unroll
                for (int np = 0; np < 2; np++)
                    #pragma unroll
                    for (int hf = 0; hf < 2; hf++)
                        MMA16816(accS[mi][np * 2 + hf], ah, bhf[np][hf * 2], bhf[np][hf * 2 + 1]);
                #pragma unroll
                for (int np = 0; np < 2; np++)
                    #pragma unroll
                    for (int hf = 0; hf < 2; hf++)
                        MMA16816(accS[mi][np * 2 + hf], ah, blf[np][hf * 2], blf[np][hf * 2 + 1]);
                #pragma unroll
                for (int np = 0; np < 2; np++)
                    #pragma unroll
                    for (int hf = 0; hf < 2; hf++)
                        MMA16816(accS[mi][np * 2 + hf], al, bhf[np][hf * 2], bhf[np][hf * 2 + 1]);
            }
        }

        const bool diag = (jt == it);
        float mloc[4][2];
        #pragma unroll
        for (int mi = 0; mi < 4; mi++) {
            #pragma unroll
            for (int rr = 0; rr < 2; rr++) {
                const int rL = mi * 16 + rr * 8 + rbase;
                float mx = -3.4e38f;
                #pragma unroll
                for (int ni = 0; ni < 4; ni++) {
                    #pragma unroll
                    for (int c = 0; c < 2; c++) {
                        const int cL = wn * 32 + ni * 8 + (lane & 3) * 2 + c;
                        float s = tanhf(accS[mi][ni][rr * 2 + c] * 0.02f) * 50.f;
                        if (diag && cL > rL) s = KMASK;
                        accS[mi][ni][rr * 2 + c] = s;
                        mx = fmaxf(mx, s);
                    }
                }
                mloc[mi][rr] = mx;
            }
        }
        #pragma unroll
        for (int o = 1; o <= 2; o <<= 1)
            #pragma unroll
            for (int mi = 0; mi < 4; mi++)
                #pragma unroll
                for (int rr = 0; rr < 2; rr++)
                    mloc[mi][rr] = fmaxf(mloc[mi][rr], __shfl_xor_sync(0xffffffffu, mloc[mi][rr], o));
        if ((lane & 3) == 0)
            #pragma unroll
            for (int mi = 0; mi < 4; mi++)
                #pragma unroll
                for (int rr = 0; rr < 2; rr++)
                    maxbuf[wn * 128 + mi * 16 + rr * 8 + rbase] = mloc[mi][rr];
        __syncthreads();

        float alpha[4][2], mnew[4][2], sloc[4][2];
        #pragma unroll
        for (int mi = 0; mi < 4; mi++) {
            #pragma unroll
            for (int rr = 0; rr < 2; rr++) {
                const int r = mi * 16 + rr * 8 + rbase;
                float mt = fmaxf(fmaxf(maxbuf[r], maxbuf[128 + r]),
                                 fmaxf(maxbuf[256 + r], maxbuf[384 + r]));
                float mn = fmaxf(m_run[mi][rr], mt);
                alpha[mi][rr] = __expf(m_run[mi][rr] - mn);
                mnew[mi][rr] = mn;
                m_run[mi][rr] = mn;
                sloc[mi][rr] = 0.f;
            }
        }
        #pragma unroll
        for (int mi = 0; mi < 4; mi++) {
            #pragma unroll
            for (int rr = 0; rr < 2; rr++) {
                const int rL = mi * 16 + rr * 8 + rbase;
                #pragma unroll
                for (int ni = 0; ni < 4; ni++) {
                    float p0 = __expf(accS[mi][ni][rr * 2 + 0] - mnew[mi][rr]);
                    float p1 = __expf(accS[mi][ni][rr * 2 + 1] - mnew[mi][rr]);
                    sloc[mi][rr] += p0 + p1;
                    const int cL = wn * 32 + ni * 8 + (lane & 3) * 2;
                    __nv_bfloat162 hv, lv;
                    split2(p0, hv.x, lv.x); split2(p1, hv.y, lv.y);
                    *(__nv_bfloat162*)(smem + FP_H + rL * FROW + cL * 2) = hv;
                    *(__nv_bfloat162*)(smem + FP_L + rL * FROW + cL * 2) = lv;
                }
            }
        }
        #pragma unroll
        for (int o = 1; o <= 2; o <<= 1)
            #pragma unroll
            for (int mi = 0; mi < 4; mi++)
                #pragma unroll
                for (int rr = 0; rr < 2; rr++)
                    sloc[mi][rr] += __shfl_xor_sync(0xffffffffu, sloc[mi][rr], o);
        if ((lane & 3) == 0)
            #pragma unroll
            for (int mi = 0; mi < 4; mi++)
                #pragma unroll
                for (int rr = 0; rr < 2; rr++)
                    sumbuf[wn * 128 + mi * 16 + rr * 8 + rbase] = sloc[mi][rr];
        __syncthreads();

        #pragma unroll
        for (int mi = 0; mi < 4; mi++) {
            #pragma unroll
            for (int rr = 0; rr < 2; rr++) {
                const int r = mi * 16 + rr * 8 + rbase;
                float st = sumbuf[r] + sumbuf[128 + r] + sumbuf[256 + r] + sumbuf[384 + r];
                l_run[mi][rr] = l_run[mi][rr] * alpha[mi][rr] + st;
                #pragma unroll
                for (int ni = 0; ni < 4; ni++) {
                    accO[mi][ni][rr * 2 + 0] *= alpha[mi][rr];
                    accO[mi][ni][rr * 2 + 1] *= alpha[mi][rr];
                }
            }
        }

        CP_WAIT(0);
        __syncthreads();

        #pragma unroll
        for (int ks = 0; ks < 8; ks++) {
            const uint32_t kof = (uint32_t)(ks * 32);
            uint32_t bhf[2][4], blf[2][4];
            #pragma unroll
            for (int np = 0; np < 2; np++) {
                const uint32_t o = (uint32_t)(np * 16 * FROW) + kof;
                LDSM_X4(bhf[np][0], bhf[np][1], bhf[np][2], bhf[np][3], sb + FV_H + bOff + o);
                LDSM_X4(blf[np][0], blf[np][1], blf[np][2], blf[np][3], sb + FV_L + bOff + o);
            }
            #pragma unroll
            for (int mi = 0; mi < 4; mi++) {
                uint32_t ah[4], al[4];
                const uint32_t o = (uint32_t)(mi * 16 * FROW) + kof;
                LDSM_X4(ah[0], ah[1], ah[2], ah[3], sb + FP_H + aOff + o);
                LDSM_X4(al[0], al[1], al[2], al[3], sb + FP_L + aOff + o);
                #pragma unroll
                for (int np = 0; np < 2; np++)
                    #pragma unroll
                    for (int hf = 0; hf < 2; hf++)
                        MMA16816(accO[mi][np * 2 + hf], ah, bhf[np][hf * 2], bhf[np][hf * 2 + 1]);
                #pragma unroll
                for (int np = 0; np < 2; np++)
                    #pragma unroll
                    for (int hf = 0; hf < 2; hf++)
                        MMA16816(accO[mi][np * 2 + hf], ah, blf[np][hf * 2], blf[np][hf * 2 + 1]);
                #pragma unroll
                for (int np = 0; np < 2; np++)
                    #pragma unroll
                    for (int hf = 0; hf < 2; hf++)
                        MMA16816(accO[mi][np * 2 + hf], al, bhf[np][hf * 2], bhf[np][hf * 2 + 1]);
            }
        }
        __syncthreads();

        if (jt < it) {
            const size_t koff = ((size_t)(b * SS + j0 + 128 + lrow) * KVHN + hk) * HD + half * 64;
            #pragma unroll
            for (int j = 0; j < 8; j++) {
                CP_ASYNC16(sb + FK_H + sA + j * 16, kh + koff + j * 8);
                CP_ASYNC16(sb + FK_L + sA + j * 16, kl + koff + j * 8);
            }
            CP_COMMIT();
        }
    }

    #pragma unroll
    for (int mi = 0; mi < 4; mi++) {
        #pragma unroll
        for (int rr = 0; rr < 2; rr++) {
            const float inv = 1.f / l_run[mi][rr];
            const int r = wm * 64 + mi * 16 + rr * 8 + (lane >> 2);
            const size_t rowoff = ((size_t)b * SS + i0 + r) * (HH * HD) + h * HD;
            #pragma unroll
            for (int ni = 0; ni < 4; ni++) {
                const int cc = wn * 32 + ni * 8 + (lane & 3) * 2;
                __nv_bfloat162 hv, lv;
                split2(accO[mi][ni][rr * 2 + 0] * inv, hv.x, lv.x);
                split2(accO[mi][ni][rr * 2 + 1] * inv, hv.y, lv.y);
                *(__nv_bfloat162*)(Oh + rowoff + cc) = hv;
                *(__nv_bfloat162*)(Ol + rowoff + cc) = lv;
            }
        }
    }
}

// ================= launch =================
static inline void run_split(const float* w, __nv_bfloat16* h, __nv_bfloat16* l, size_t n) {
    int n4 = (int)(n / 4);
    split_kernel<<<(n4 + 255) / 256, 256>>>((const float4*)w, (__nv_bfloat162*)h,
                                            (__nv_bfloat162*)l, n4);
}

extern "C" void kernel_launch(void* const* d_in, const int* in_sizes, int n_in,
                              void* d_out, int out_size)
{
    const float* x          = (const float*)d_in[0];
    const int*   positions  = (const int*)  d_in[1];
    const float* wq         = (const float*)d_in[4];
    const float* wk         = (const float*)d_in[5];
    const float* wv         = (const float*)d_in[6];
    const float* wo         = (const float*)d_in[7];
    const float* q_scale    = (const float*)d_in[8];
    const float* k_scale    = (const float*)d_in[9];
    const float* pre_attn   = (const float*)d_in[10];
    const float* post_attn  = (const float*)d_in[11];
    const float* pre_ffn    = (const float*)d_in[12];
    const float* post_ffn   = (const float*)d_in[13];
    const float* w_gate     = (const float*)d_in[14];
    const float* w_up       = (const float*)d_in[15];
    const float* w_down     = (const float*)d_in[16];
    const float* layer_scal = (const float*)d_in[17];
    float* out = (float*)d_out;

    float *q_, *k_, *v_, *tmp_, *x2_, *gate_, *ffn_;
    __nv_bfloat16 *ah_, *al_, *uh_, *ul_, *qh_, *ql_, *kh_, *kl_, *vth_, *vtl_;
    __nv_bfloat16 *wqh, *wql, *wkh, *wkl, *wvh, *wvl, *woh, *wol, *wgh, *wgl, *wuh, *wul, *wdh, *wdl;
    cudaGetSymbolAddress((void**)&q_,   g_q);
    cudaGetSymbolAddress((void**)&k_,   g_k);
    cudaGetSymbolAddress((void**)&v_,   g_v);
    cudaGetSymbolAddress((void**)&tmp_, g_tmp);
    cudaGetSymbolAddress((void**)&x2_,  g_x2);
    cudaGetSymbolAddress((void**)&gate_,g_gate);
    cudaGetSymbolAddress((void**)&ffn_, g_ffn);
    cudaGetSymbolAddress((void**)&ah_,  g_ah);
    cudaGetSymbolAddress((void**)&al_,  g_al);
    cudaGetSymbolAddress((void**)&uh_,  g_uh);
    cudaGetSymbolAddress((void**)&ul_,  g_ul);
    cudaGetSymbolAddress((void**)&qh_,  g_qh);  cudaGetSymbolAddress((void**)&ql_,  g_ql);
    cudaGetSymbolAddress((void**)&kh_,  g_kh);  cudaGetSymbolAddress((void**)&kl_,  g_kl);
    cudaGetSymbolAddress((void**)&vth_, g_vth); cudaGetSymbolAddress((void**)&vtl_, g_vtl);
    cudaGetSymbolAddress((void**)&wqh, g_wqh); cudaGetSymbolAddress((void**)&wql, g_wql);
    cudaGetSymbolAddress((void**)&wkh, g_wkh); cudaGetSymbolAddress((void**)&wkl, g_wkl);
    cudaGetSymbolAddress((void**)&wvh, g_wvh); cudaGetSymbolAddress((void**)&wvl, g_wvl);
    cudaGetSymbolAddress((void**)&woh, g_woh); cudaGetSymbolAddress((void**)&wol, g_wol);
    cudaGetSymbolAddress((void**)&wgh, g_wgh); cudaGetSymbolAddress((void**)&wgl, g_wgl);
    cudaGetSymbolAddress((void**)&wuh, g_wuh); cudaGetSymbolAddress((void**)&wul, g_wul);
    cudaGetSymbolAddress((void**)&wdh, g_wdh); cudaGetSymbolAddress((void**)&wdl, g_wdl);

    cudaFuncSetAttribute(gemm_mma,       cudaFuncAttributeMaxDynamicSharedMemorySize, GSMEM2);
    cudaFuncSetAttribute(gemm_mma_geglu, cudaFuncAttributeMaxDynamicSharedMemorySize, GSMEM2);
    cudaFuncSetAttribute(attn_fused,     cudaFuncAttributeMaxDynamicSharedMemorySize, FSMEM);

    // weight splits
    run_split(wq,     wqh, wql, (size_t)HH * HD * DD);
    run_split(wk,     wkh, wkl, (size_t)KVHN * HD * DD);
    run_split(wv,     wvh, wvl, (size_t)KVHN * HD * DD);
    run_split(wo,     woh, wol, (size_t)DD * HH * HD);
    run_split(w_gate, wgh, wgl, (size_t)FFN * DD);
    run_split(w_up,   wuh, wul, (size_t)FFN * DD);
    run_split(w_down, wdh, wdl, (size_t)DD * FFN);

    // ---- attention sub-block ----
    rmsnorm_kernel<<<MM, 256>>>(x, pre_attn, nullptr, nullptr, nullptr, ah_, al_, DD);
    gemm_mma<<<dim3((HH*HD)/128,   MM/256), 512, GSMEM2>>>(ah_, al_, wqh, wql, q_, MM, HH*HD,   DD);
    gemm_mma<<<dim3((KVHN*HD)/128, MM/256), 512, GSMEM2>>>(ah_, al_, wkh, wkl, k_, MM, KVHN*HD, DD);
    gemm_mma<<<dim3((KVHN*HD)/128, MM/256), 512, GSMEM2>>>(ah_, al_, wvh, wvl, v_, MM, KVHN*HD, DD);
    headnorm_rope_kernel<<<MM * HH,   128>>>(q_, q_scale, positions, HH,   1, qh_, ql_);
    headnorm_rope_kernel<<<MM * KVHN, 128>>>(k_, k_scale, positions, KVHN, 1, kh_, kl_);
    headnorm_rope_kernel<<<MM * KVHN, 128>>>(v_, nullptr, positions, KVHN, 0, nullptr, nullptr);
    vtrans_kernel<<<dim3(SS/32, HD/32, BB*KVHN), 256>>>(v_, vth_, vtl_);
    attn_fused<<<dim3(SS/128, BB*HH), 256, FSMEM>>>(qh_, ql_, kh_, kl_, vth_, vtl_, ah_, al_);
    gemm_mma<<<dim3(DD/128, MM/256), 512, GSMEM2>>>(ah_, al_, woh, wol, tmp_, MM, DD, HH*HD);

    // fused: x2 = rms(tmp)*post_attn + x;  ah/al = split(rms(x2)*pre_ffn)
    rmsnorm2_kernel<<<MM, 256>>>(tmp_, post_attn, x, pre_ffn, x2_, ah_, al_);

    // ---- FFN sub-block ----
    gemm_mma<<<dim3(FFN/128, MM/256), 512, GSMEM2>>>(ah_, al_, wgh, wgl, gate_, MM, FFN, DD);
    gemm_mma_geglu<<<dim3(FFN/128, MM/256), 512, GSMEM2>>>(ah_, al_, wuh, wul, gate_,
                                                           uh_, ul_, MM, FFN, DD);
    gemm_mma<<<dim3(DD/128, MM/256), 512, GSMEM2>>>(uh_, ul_, wdh, wdl, ffn_, MM, DD, FFN);
    rmsnorm_kernel<<<MM, 256>>>(ffn_, post_ffn, x2_, layer_scal, out, nullptr, nullptr, DD);
}

// round 14
// speedup vs baseline: 1.3456x; 1.2281x over previous
#include <cuda_runtime.h>
#include <cuda_bf16.h>
#include <cstdint>
#include <math.h>

#define BB 4
#define SS 1024
#define DD 2048
#define HH 16
#define KVHN 8
#define HD 128
#define FFN 8192
#define MM (BB*SS)
#define EPS_RMS 1e-6f
#define KMASK -1e30f

// ================= PTX helpers (base sm_103 ISA only) =================
__device__ __forceinline__ uint32_t smem_to_u32(const void* p) {
    uint32_t a;
    asm("{ .reg .u64 t; cvta.to.shared.u64 t, %1; cvt.u32.u64 %0, t; }" : "=r"(a) : "l"(p));
    return a;
}
#define CP_ASYNC16(sa, gp) \
    asm volatile("cp.async.cg.shared.global [%0], [%1], 16;" :: "r"(sa), "l"(gp) : "memory")
#define CP_COMMIT() asm volatile("cp.async.commit_group;" ::: "memory")
#define CP_WAIT(n)  asm volatile("cp.async.wait_group %0;" :: "n"(n) : "memory")

#define LDSM_X4(r0, r1, r2, r3, sa) \
    asm volatile("ldmatrix.sync.aligned.m8n8.x4.shared.b16 {%0,%1,%2,%3}, [%4];" \
                 : "=r"(r0), "=r"(r1), "=r"(r2), "=r"(r3) : "r"(sa))

#define MMA16816(d, a, b0, b1) \
    asm volatile("mma.sync.aligned.m16n8k16.row.col.f32.bf16.bf16.f32 " \
                 "{%0,%1,%2,%3}, {%4,%5,%6,%7}, {%8,%9}, {%0,%1,%2,%3};" \
                 : "+f"((d)[0]), "+f"((d)[1]), "+f"((d)[2]), "+f"((d)[3]) \
                 : "r"((a)[0]), "r"((a)[1]), "r"((a)[2]), "r"((a)[3]), "r"(b0), "r"(b1))

// ================= scratch =================
__device__ float g_q   [(size_t)MM*HH*HD];
__device__ float g_k   [(size_t)MM*KVHN*HD];
__device__ float g_v   [(size_t)MM*KVHN*HD];
__device__ float g_tmp [(size_t)MM*DD];
__device__ float g_x2  [(size_t)MM*DD];
__device__ float g_gate[(size_t)MM*FFN];
__device__ float g_ffn [(size_t)MM*DD];
__device__ __nv_bfloat16 g_ah[(size_t)MM*FFN];
__device__ __nv_bfloat16 g_al[(size_t)MM*FFN];
__device__ __nv_bfloat16 g_uh[(size_t)MM*FFN];
__device__ __nv_bfloat16 g_ul[(size_t)MM*FFN];
// attention bf16 operands
__device__ __nv_bfloat16 g_qh[(size_t)MM*HH*HD],   g_ql[(size_t)MM*HH*HD];
__device__ __nv_bfloat16 g_kh[(size_t)MM*KVHN*HD], g_kl[(size_t)MM*KVHN*HD];
__device__ __nv_bfloat16 g_vth[(size_t)MM*KVHN*HD],g_vtl[(size_t)MM*KVHN*HD];
// RoPE cos/sin table [token][64]
__device__ float g_ropec[(size_t)MM*64];
__device__ float g_ropes[(size_t)MM*64];
// bf16 hi/lo weights
__device__ __nv_bfloat16 g_wqh[(size_t)HH*HD*DD],  g_wql[(size_t)HH*HD*DD];
__device__ __nv_bfloat16 g_wkh[(size_t)KVHN*HD*DD],g_wkl[(size_t)KVHN*HD*DD];
__device__ __nv_bfloat16 g_wvh[(size_t)KVHN*HD*DD],g_wvl[(size_t)KVHN*HD*DD];
__device__ __nv_bfloat16 g_woh[(size_t)DD*HH*HD],  g_wol[(size_t)DD*HH*HD];
__device__ __nv_bfloat16 g_wgh[(size_t)FFN*DD],    g_wgl[(size_t)FFN*DD];
__device__ __nv_bfloat16 g_wuh[(size_t)FFN*DD],    g_wul[(size_t)FFN*DD];
__device__ __nv_bfloat16 g_wdh[(size_t)DD*FFN],    g_wdl[(size_t)DD*FFN];

__device__ __forceinline__ void split2(float v, __nv_bfloat16& h, __nv_bfloat16& l) {
    h = __float2bfloat16(v);
    l = __float2bfloat16(v - __bfloat162float(h));
}
__device__ __forceinline__ float gelu_tanh(float x) {
    float t = 0.7978845608028654f * (x + 0.044715f * x * x * x);
    return 0.5f * x * (1.f + tanhf(t));
}

// ================= weight split (vectorized: 8 elems/thread, 16B stores) =================
__global__ __launch_bounds__(256) void split_kernel(
    const float4* __restrict__ x, uint4* __restrict__ hi,
    uint4* __restrict__ lo, int n8)
{
    int i = blockIdx.x * 256 + threadIdx.x;
    if (i < n8) {
        float4 a = x[2 * i], b = x[2 * i + 1];
        __nv_bfloat162 h0, h1, h2, h3, l0, l1, l2, l3;
        split2(a.x, h0.x, l0.x); split2(a.y, h0.y, l0.y);
        split2(a.z, h1.x, l1.x); split2(a.w, h1.y, l1.y);
        split2(b.x, h2.x, l2.x); split2(b.y, h2.y, l2.y);
        split2(b.z, h3.x, l3.x); split2(b.w, h3.y, l3.y);
        uint4 hv, lv;
        hv.x = *(uint32_t*)&h0; hv.y = *(uint32_t*)&h1;
        hv.z = *(uint32_t*)&h2; hv.w = *(uint32_t*)&h3;
        lv.x = *(uint32_t*)&l0; lv.y = *(uint32_t*)&l1;
        lv.z = *(uint32_t*)&l2; lv.w = *(uint32_t*)&l3;
        hi[i] = hv; lo[i] = lv;
    }
}

// ================= RoPE cos/sin table (fp64 once per token x freq) =================
__global__ __launch_bounds__(64) void rope_table_kernel(
    const int* __restrict__ positions, float* __restrict__ rc, float* __restrict__ rs)
{
    const int token = blockIdx.x;
    const int d = threadIdx.x;
    const int pos = positions[token];
    double freq = pow(10000.0, -((double)(2 * d) / 128.0));
    double ang = (double)pos * freq;
    double dsin, dcos;
    sincos(ang, &dsin, &dcos);
    rc[token * 64 + d] = (float)dcos;
    rs[token * 64 + d] = (float)dsin;
}

// ================= RMSNorm =================
__global__ __launch_bounds__(256) void rmsnorm_kernel(
    const float* __restrict__ in, const float* __restrict__ scale,
    const float* __restrict__ resid, const float* __restrict__ lsc,
    float* __restrict__ out, __nv_bfloat16* __restrict__ oh,
    __nv_bfloat16* __restrict__ ol, int N)
{
    __shared__ float red[8];
    const size_t row = blockIdx.x;
    const float* x = in + row * (size_t)N;
    float ss = 0.f;
    for (int j = threadIdx.x; j < N; j += 256) { float v = x[j]; ss = fmaf(v, v, ss); }
    int lane = threadIdx.x & 31, wid = threadIdx.x >> 5;
    #pragma unroll
    for (int o = 16; o > 0; o >>= 1) ss += __shfl_down_sync(0xffffffffu, ss, o);
    if (lane == 0) red[wid] = ss;
    __syncthreads();
    if (threadIdx.x == 0) {
        float s = 0.f;
        #pragma unroll
        for (int w = 0; w < 8; w++) s += red[w];
        red[0] = s;
    }
    __syncthreads();
    const float r = rsqrtf(red[0] / (float)N + EPS_RMS);
    const float ls = lsc ? lsc[0] : 1.f;
    const float* rp = resid ? resid + row * (size_t)N : nullptr;
    for (int j = threadIdx.x; j < N; j += 256) {
        float v = x[j] * r;
        if (scale) v *= scale[j];
        if (rp) v += rp[j];
        v *= ls;
        if (out) out[row * (size_t)N + j] = v;
        if (oh) {
            __nv_bfloat16 h, l; split2(v, h, l);
            oh[row * (size_t)N + j] = h; ol[row * (size_t)N + j] = l;
        }
    }
}

// ===== fused double RMSNorm: x2 = rms(tmp)*s1 + resid; oh/ol = split(rms(x2)*s2) =====
__global__ __launch_bounds__(256) void rmsnorm2_kernel(
    const float* __restrict__ tmp, const float* __restrict__ s1,
    const float* __restrict__ resid, const float* __restrict__ s2,
    float* __restrict__ x2, __nv_bfloat16* __restrict__ oh,
    __nv_bfloat16* __restrict__ ol)
{
    __shared__ float red[8];
    const size_t base = (size_t)blockIdx.x * DD;
    const int tid = threadIdx.x;
    const int lane = tid & 31, wid = tid >> 5;
    float t[8];
    float ss = 0.f;
    #pragma unroll
    for (int q = 0; q < 8; q++) {
        t[q] = tmp[base + q * 256 + tid];
        ss = fmaf(t[q], t[q], ss);
    }
    #pragma unroll
    for (int o = 16; o > 0; o >>= 1) ss += __shfl_down_sync(0xffffffffu, ss, o);
    if (lane == 0) red[wid] = ss;
    __syncthreads();
    if (tid == 0) {
        float s = 0.f;
        #pragma unroll
        for (int w = 0; w < 8; w++) s += red[w];
        red[0] = s;
    }
    __syncthreads();
    const float r1 = rsqrtf(red[0] / (float)DD + EPS_RMS);
    __syncthreads();
    float v[8];
    float ss2 = 0.f;
    #pragma unroll
    for (int q = 0; q < 8; q++) {
        const int j = q * 256 + tid;
        v[q] = t[q] * r1 * s1[j] + resid[base + j];
        x2[base + j] = v[q];
        ss2 = fmaf(v[q], v[q], ss2);
    }
    #pragma unroll
    for (int o = 16; o > 0; o >>= 1) ss2 += __shfl_down_sync(0xffffffffu, ss2, o);
    if (lane == 0) red[wid] = ss2;
    __syncthreads();
    if (tid == 0) {
        float s = 0.f;
        #pragma unroll
        for (int w = 0; w < 8; w++) s += red[w];
        red[0] = s;
    }
    __syncthreads();
    const float r2 = rsqrtf(red[0] / (float)DD + EPS_RMS);
    #pragma unroll
    for (int q = 0; q < 8; q++) {
        const int j = q * 256 + tid;
        float o = v[q] * r2 * s2[j];
        __nv_bfloat16 h, l; split2(o, h, l);
        oh[base + j] = h; ol[base + j] = l;
    }
}

// ================= per-head RMSNorm (+ RoPE via table) =================
__global__ __launch_bounds__(128) void headnorm_rope_kernel(
    float* __restrict__ data, const float* __restrict__ scale,
    const float* __restrict__ ropec, const float* __restrict__ ropes,
    int nheads, int do_rope,
    __nv_bfloat16* __restrict__ oh, __nv_bfloat16* __restrict__ ol)
{
    __shared__ float red[4];
    __shared__ float sv[HD];
    const int d = threadIdx.x;
    const int idx = blockIdx.x;
    const int token = idx / nheads;
    float* p = data + (size_t)idx * HD;
    float v = p[d];
    float ss = v * v;
    int lane = d & 31, wid = d >> 5;
    #pragma unroll
    for (int o = 16; o > 0; o >>= 1) ss += __shfl_down_sync(0xffffffffu, ss, o);
    if (lane == 0) red[wid] = ss;
    __syncthreads();
    const float total = red[0] + red[1] + red[2] + red[3];
    const float r = rsqrtf(total * (1.0f / HD) + EPS_RMS);
    float nv = v * r;
    if (scale) nv *= scale[d];
    if (do_rope) {
        sv[d] = nv;
        __syncthreads();
        if (d < 64) {
            const float c = ropec[token * 64 + d];
            const float s = ropes[token * 64 + d];
            float x1 = sv[d], x2 = sv[d + 64];
            float o1 = x1 * c - x2 * s;
            float o2 = x2 * c + x1 * s;
            __nv_bfloat16 h1, l1, h2, l2;
            split2(o1, h1, l1); split2(o2, h2, l2);
            oh[(size_t)idx * HD + d]      = h1; ol[(size_t)idx * HD + d]      = l1;
            oh[(size_t)idx * HD + d + 64] = h2; ol[(size_t)idx * HD + d + 64] = l2;
        }
    } else {
        p[d] = nv;
    }
}

// ================= V transpose + split =================
__global__ __launch_bounds__(256) void vtrans_kernel(
    const float* __restrict__ v, __nv_bfloat16* __restrict__ vth,
    __nv_bfloat16* __restrict__ vtl)
{
    __shared__ float tile[32][33];
    const int z = blockIdx.z;
    const int b = z >> 3, hk = z & 7;
    const int s0 = blockIdx.x * 32, d0 = blockIdx.y * 32;
    const int tx = threadIdx.x & 31, ty = threadIdx.x >> 5;
    #pragma unroll
    for (int r = ty; r < 32; r += 8)
        tile[r][tx] = v[(size_t)(b * SS + s0 + r) * (KVHN * HD) + hk * HD + d0 + tx];
    __syncthreads();
    #pragma unroll
    for (int r = ty; r < 32; r += 8) {
        float val = tile[tx][r];
        __nv_bfloat16 h, l; split2(val, h, l);
        const size_t off = ((size_t)(b * KVHN + hk) * HD + d0 + r) * SS + s0 + tx;
        vth[off] = h; vtl[off] = l;
    }
}

// ================= HMMA bf16x3 GEMM core (shared mainloop macro) =================
#define ROW2  80
#define APART (256 * ROW2)
#define BPART (128 * ROW2)
#define STG2  (2 * APART + 2 * BPART)
#define GSMEM2 (3 * STG2)

#define GEMM_PROLOGUE_AND_MAINLOOP()                                              \
    extern __shared__ __align__(128) char smem[];                                 \
    const uint32_t sb = smem_to_u32(smem);                                        \
    const int tid = threadIdx.x;                                                  \
    const int wid = tid >> 5, lane = tid & 31;                                    \
    const int wm = wid >> 2, wn = wid & 3;                                        \
    const int m0 = blockIdx.y * 256, n0 = blockIdx.x * 128;                       \
    const int arow = tid >> 1;                                                    \
    const int acs  = (tid & 1) * 2;                                               \
    const int brow = tid >> 2;                                                    \
    const int bcs  = tid & 3;                                                     \
    const __nv_bfloat16* gAh = Ah + (size_t)(m0 + arow) * K + acs * 8;            \
    const __nv_bfloat16* gAl = Al + (size_t)(m0 + arow) * K + acs * 8;            \
    const __nv_bfloat16* gBh = Bh + (size_t)(n0 + brow) * K + bcs * 8;            \
    const __nv_bfloat16* gBl = Bl + (size_t)(n0 + brow) * K + bcs * 8;            \
    const uint32_t aS = (uint32_t)(arow * ROW2 + acs * 16);                       \
    const uint32_t bS = (uint32_t)(brow * ROW2 + bcs * 16);                       \
    const int nch = K / 32;                                                       \
    auto issue = [&](int c) {                                                     \
        const uint32_t st = sb + (uint32_t)(c % 3) * STG2;                        \
        const size_t ko = (size_t)c * 32;                                         \
        CP_ASYNC16(st + aS,                 gAh + ko);                            \
        CP_ASYNC16(st + aS + 16,            gAh + ko + 8);                        \
        CP_ASYNC16(st + APART + aS,         gAl + ko);                            \
        CP_ASYNC16(st + APART + aS + 16,    gAl + ko + 8);                        \
        CP_ASYNC16(st + 2 * APART + bS,         gBh + ko);                        \
        CP_ASYNC16(st + 2 * APART + BPART + bS, gBl + ko);                        \
    };                                                                            \
    issue(0); CP_COMMIT();                                                        \
    issue(1); CP_COMMIT();                                                        \
    const uint32_t aOff = (uint32_t)((wm * 64 + (lane & 15)) * ROW2 + (lane >> 4) * 16); \
    const uint32_t bOff = (uint32_t)((wn * 32 + ((lane & 7) | ((lane >> 4) << 3))) * ROW2 \
                                     + ((lane >> 3) & 1) * 16);                   \
    float acc[4][4][4];                                                           \
    _Pragma("unroll")                                                             \
    for (int i = 0; i < 4; i++)                                                   \
        _Pragma("unroll")                                                         \
        for (int j = 0; j < 4; j++)                                               \
            _Pragma("unroll")                                                     \
            for (int q = 0; q < 4; q++) acc[i][j][q] = 0.f;                       \
    for (int c = 0; c < nch; ++c) {                                               \
        if (c + 1 < nch) { CP_WAIT(1); } else { CP_WAIT(0); }                     \
        __syncthreads();                                                          \
        if (c + 2 < nch) { issue(c + 2); CP_COMMIT(); }                           \
        const uint32_t st = sb + (uint32_t)(c % 3) * STG2;                        \
        const uint32_t aH = st + aOff;                                            \
        const uint32_t aL = aH + APART;                                           \
        const uint32_t bH = st + 2 * APART + bOff;                                \
        const uint32_t bL = bH + BPART;                                           \
        _Pragma("unroll")                                                         \
        for (int ks = 0; ks < 2; ks++) {                                          \
            uint32_t bh[2][4], bl[2][4];                                          \
            _Pragma("unroll")                                                     \
            for (int np = 0; np < 2; np++) {                                      \
                const uint32_t o = (uint32_t)(np * 16 * ROW2 + ks * 32);          \
                LDSM_X4(bh[np][0], bh[np][1], bh[np][2], bh[np][3], bH + o);      \
                LDSM_X4(bl[np][0], bl[np][1], bl[np][2], bl[np][3], bL + o);      \
            }                                                                     \
            _Pragma("unroll")                                                     \
            for (int mi = 0; mi < 4; mi++) {                                      \
                uint32_t ah[4], al[4];                                            \
                const uint32_t o = (uint32_t)(mi * 16 * ROW2 + ks * 32);          \
                LDSM_X4(ah[0], ah[1], ah[2], ah[3], aH + o);                      \
                LDSM_X4(al[0], al[1], al[2], al[3], aL + o);                      \
                _Pragma("unroll")                                                 \
                for (int np = 0; np < 2; np++)                                    \
                    _Pragma("unroll")                                             \
                    for (int hf = 0; hf < 2; hf++)                                \
                        MMA16816(acc[mi][np * 2 + hf], ah, bh[np][hf * 2], bh[np][hf * 2 + 1]); \
                _Pragma("unroll")                                                 \
                for (int np = 0; np < 2; np++)                                    \
                    _Pragma("unroll")                                             \
                    for (int hf = 0; hf < 2; hf++)                                \
                        MMA16816(acc[mi][np * 2 + hf], ah, bl[np][hf * 2], bl[np][hf * 2 + 1]); \
                _Pragma("unroll")                                                 \
                for (int np = 0; np < 2; np++)                                    \
                    _Pragma("unroll")                                             \
                    for (int hf = 0; hf < 2; hf++)                                \
                        MMA16816(acc[mi][np * 2 + hf], al, bh[np][hf * 2], bh[np][hf * 2 + 1]); \
            }                                                                     \
        }                                                                         \
    }

__global__ __launch_bounds__(512, 1) void gemm_mma(
    const __nv_bfloat16* __restrict__ Ah, const __nv_bfloat16* __restrict__ Al,
    const __nv_bfloat16* __restrict__ Bh, const __nv_bfloat16* __restrict__ Bl,
    float* __restrict__ C, int M, int N, int K)
{
    GEMM_PROLOGUE_AND_MAINLOOP()
    #pragma unroll
    for (int mi = 0; mi < 4; mi++) {
        const int r = m0 + wm * 64 + mi * 16 + (lane >> 2);
        #pragma unroll
        for (int ni = 0; ni < 4; ni++) {
            const int cc = n0 + wn * 32 + ni * 8 + (lane & 3) * 2;
            *(float2*)&C[(size_t)r * N + cc]       = make_float2(acc[mi][ni][0], acc[mi][ni][1]);
            *(float2*)&C[(size_t)(r + 8) * N + cc] = make_float2(acc[mi][ni][2], acc[mi][ni][3]);
        }
    }
}

// up-GEMM with fused GeGLU epilogue: out = split(gelu(gate) * acc)
__global__ __launch_bounds__(512, 1) void gemm_mma_geglu(
    const __nv_bfloat16* __restrict__ Ah, const __nv_bfloat16* __restrict__ Al,
    const __nv_bfloat16* __restrict__ Bh, const __nv_bfloat16* __restrict__ Bl,
    const float* __restrict__ gate,
    __nv_bfloat16* __restrict__ Oh, __nv_bfloat16* __restrict__ Ol,
    int M, int N, int K)
{
    GEMM_PROLOGUE_AND_MAINLOOP()
    #pragma unroll
    for (int mi = 0; mi < 4; mi++) {
        #pragma unroll
        for (int rr = 0; rr < 2; rr++) {
            const int r = m0 + wm * 64 + mi * 16 + rr * 8 + (lane >> 2);
            #pragma unroll
            for (int ni = 0; ni < 4; ni++) {
                const int cc = n0 + wn * 32 + ni * 8 + (lane & 3) * 2;
                float2 g = *(const float2*)&gate[(size_t)r * N + cc];
                float r0 = gelu_tanh(g.x) * acc[mi][ni][rr * 2 + 0];
                float r1 = gelu_tanh(g.y) * acc[mi][ni][rr * 2 + 1];
                __nv_bfloat162 hv, lv;
                split2(r0, hv.x, lv.x); split2(r1, hv.y, lv.y);
                *(__nv_bfloat162*)(Oh + (size_t)r * N + cc) = hv;
                *(__nv_bfloat162*)(Ol + (size_t)r * N + cc) = lv;
            }
        }
    }
}

// ================= fused flash attention =================
#define FROW  272
#define FTILE (128 * FROW)
#define FQ_H  0
#define FQ_L  (FQ_H + FTILE)
#define FK_H  (FQ_L + FTILE)
#define FK_L  (FK_H + FTILE)
#define FV_H  (FK_L + FTILE)
#define FV_L  (FV_H + FTILE)
#define FP_H  FK_H
#define FP_L  FK_L
#define FRED  (FV_L + FTILE)
#define FSMEM (FRED + 2 * 4 * 128 * 4)

__global__ __launch_bounds__(256, 1) void attn_fused(
    const __nv_bfloat16* __restrict__ qh, const __nv_bfloat16* __restrict__ ql,
    const __nv_bfloat16* __restrict__ kh, const __nv_bfloat16* __restrict__ kl,
    const __nv_bfloat16* __restrict__ vth, const __nv_bfloat16* __restrict__ vtl,
    __nv_bfloat16* __restrict__ Oh, __nv_bfloat16* __restrict__ Ol)
{
    extern __shared__ __align__(128) char smem[];
    const uint32_t sb = smem_to_u32(smem);
    const int bh = blockIdx.y;
    const int b = bh >> 4, h = bh & 15, hk = h >> 1;
    const int it = 7 - blockIdx.x;
    const int i0 = it * 128;
    const int tid = threadIdx.x;
    const int wid = tid >> 5, lane = tid & 31;
    const int wm = wid >> 2, wn = wid & 3;

    const int lrow = tid >> 1, half = tid & 1;
    const uint32_t sA = (uint32_t)(lrow * FROW + half * 128);
    const size_t qoff  = ((size_t)(b * SS + i0 + lrow) * HH + h) * HD + half * 64;
    const size_t vbase = ((size_t)(b * KVHN + hk) * HD + lrow) * SS + half * 64;

    #pragma unroll
    for (int j = 0; j < 8; j++) {
        CP_ASYNC16(sb + FQ_H + sA + j * 16, qh + qoff + j * 8);
        CP_ASYNC16(sb + FQ_L + sA + j * 16, ql + qoff + j * 8);
    }
    {
        const size_t koff = ((size_t)(b * SS + lrow) * KVHN + hk) * HD + half * 64;
        #pragma unroll
        for (int j = 0; j < 8; j++) {
            CP_ASYNC16(sb + FK_H + sA + j * 16, kh + koff + j * 8);
            CP_ASYNC16(sb + FK_L + sA + j * 16, kl + koff + j * 8);
        }
    }
    CP_COMMIT();

    const uint32_t aOff = (uint32_t)((wm * 64 + (lane & 15)) * FROW + (lane >> 4) * 16);
    const uint32_t bOff = (uint32_t)((wn * 32 + ((lane & 7) | ((lane >> 4) << 3))) * FROW
                                     + ((lane >> 3) & 1) * 16);

    float accO[4][4][4];
    float m_run[4][2], l_run[4][2];
    #pragma unroll
    for (int i = 0; i < 4; i++) {
        m_run[i][0] = -1e30f; m_run[i][1] = -1e30f;
        l_run[i][0] = 0.f;    l_run[i][1] = 0.f;
        #pragma unroll
        for (int j = 0; j < 4; j++)
            #pragma unroll
            for (int q = 0; q < 4; q++) accO[i][j][q] = 0.f;
    }

    float* maxbuf = (float*)(smem + FRED);
    float* sumbuf = maxbuf + 4 * 128;
    const int rbase = wm * 64 + (lane >> 2);

    for (int jt = 0; jt <= it; ++jt) {
        const int j0 = jt * 128;
        #pragma unroll
        for (int j = 0; j < 8; j++) {
            CP_ASYNC16(sb + FV_H + sA + j * 16, vth + vbase + j0 + j * 8);
            CP_ASYNC16(sb + FV_L + sA + j * 16, vtl + vbase + j0 + j * 8);
        }
        CP_COMMIT();
        CP_WAIT(1);
        __syncthreads();

        float accS[4][4][4];
        #pragma unroll
        for (int i = 0; i < 4; i++)
            #pragma unroll
            for (int j = 0; j < 4; j++)
                #pragma unroll
                for (int q = 0; q < 4; q++) accS[i][j][q] = 0.f;
        #pragma unroll
        for (int ks = 0; ks < 8; ks++) {
            const uint32_t kof = (uint32_t)(ks * 32);
            uint32_t bhf[2][4], blf[2][4];
            #pragma unroll
            for (int np = 0; np < 2; np++) {
                const uint32_t o = (uint32_t)(np * 16 * FROW) + kof;
                LDSM_X4(bhf[np][0], bhf[np][1], bhf[np][2], bhf[np][3], sb + FK_H + bOff + o);
                LDSM_X4(blf[np][0], blf[np][1], blf[np][2], blf[np][3], sb + FK_L + bOff + o);
            }
            #pragma unroll
            for (int mi = 0; mi < 4; mi++) {
                uint32_t ah[4], al[4];
                const uint32_t o = (uint32_t)(mi * 16 * FROW) + kof;
                LDSM_X4(ah[0], ah[1], ah[2], ah[3], sb + FQ_H + aOff + o);
                LDSM_X4(al[0], al[1], al[2], al[3], sb + FQ_L + aOff + o);
                #pragma unroll
                for (int np = 0; np < 2; np++)
                    #pragma unroll
                    for (int hf = 0; hf < 2; hf++)
                        MMA16816(accS[mi][np * 2 + hf], ah, bhf[np][hf * 2], bhf[np][hf * 2 + 1]);
                #pragma unroll
                for (int np = 0; np < 2; np++)
                    #pragma unroll
                    for (int hf = 0; hf < 2; hf++)
                        MMA16816(accS[mi][np * 2 + hf], ah, blf[np][hf * 2], blf[np][hf * 2 + 1]);
                #pragma unroll
                for (int np = 0; np < 2; np++)
                    #pragma unroll
                    for (int hf = 0; hf < 2; hf++)
                        MMA16816(accS[mi][np * 2 + hf], al, bhf[np][hf * 2], bhf[np][hf * 2 + 1]);
            }
        }

        const bool diag = (jt == it);
        float mloc[4][2];
        #pragma unroll
        for (int mi = 0; mi < 4; mi++) {
            #pragma unroll
            for (int rr = 0; rr < 2; rr++) {
                const int rL = mi * 16 + rr * 8 + rbase;
                float mx = -3.4e38f;
                #pragma unroll
                for (int ni = 0; ni < 4; ni++) {
                    #pragma unroll
                    for (int c = 0; c < 2; c++) {
                        const int cL = wn * 32 + ni * 8 + (lane & 3) * 2 + c;
                        float s = tanhf(accS[mi][ni][rr * 2 + c] * 0.02f) * 50.f;
                        if (diag && cL > rL) s = KMASK;
                        accS[mi][ni][rr * 2 + c] = s;
                        mx = fmaxf(mx, s);
                    }
                }
                mloc[mi][rr] = mx;
            }
        }
        #pragma unroll
        for (int o = 1; o <= 2; o <<= 1)
            #pragma unroll
            for (int mi = 0; mi < 4; mi++)
                #pragma unroll
                for (int rr = 0; rr < 2; rr++)
                    mloc[mi][rr] = fmaxf(mloc[mi][rr], __shfl_xor_sync(0xffffffffu, mloc[mi][rr], o));
        if ((lane & 3) == 0)
            #pragma unroll
            for (int mi = 0; mi < 4; mi++)
                #pragma unroll
                for (int rr = 0; rr < 2; rr++)
                    maxbuf[wn * 128 + mi * 16 + rr * 8 + rbase] = mloc[mi][rr];
        __syncthreads();

        float alpha[4][2], mnew[4][2], sloc[4][2];
        #pragma unroll
        for (int mi = 0; mi < 4; mi++) {
            #pragma unroll
            for (int rr = 0; rr < 2; rr++) {
                const int r = mi * 16 + rr * 8 + rbase;
                float mt = fmaxf(fmaxf(maxbuf[r], maxbuf[128 + r]),
                                 fmaxf(maxbuf[256 + r], maxbuf[384 + r]));
                float mn = fmaxf(m_run[mi][rr], mt);
                alpha[mi][rr] = __expf(m_run[mi][rr] - mn);
                mnew[mi][rr] = mn;
                m_run[mi][rr] = mn;
                sloc[mi][rr] = 0.f;
            }
        }
        #pragma unroll
        for (int mi = 0; mi < 4; mi++) {
            #pragma unroll
            for (int rr = 0; rr < 2; rr++) {
                const int rL = mi * 16 + rr * 8 + rbase;
                #pragma unroll
                for (int ni = 0; ni < 4; ni++) {
                    float p0 = __expf(accS[mi][ni][rr * 2 + 0] - mnew[mi][rr]);
                    float p1 = __expf(accS[mi][ni][rr * 2 + 1] - mnew[mi][rr]);
                    sloc[mi][rr] += p0 + p1;
                    const int cL = wn * 32 + ni * 8 + (lane & 3) * 2;
                    __nv_bfloat162 hv, lv;
                    split2(p0, hv.x, lv.x); split2(p1, hv.y, lv.y);
                    *(__nv_bfloat162*)(smem + FP_H + rL * FROW + cL * 2) = hv;
                    *(__nv_bfloat162*)(smem + FP_L + rL * FROW + cL * 2) = lv;
                }
            }
        }
        #pragma unroll
        for (int o = 1; o <= 2; o <<= 1)
            #pragma unroll
            for (int mi = 0; mi < 4; mi++)
                #pragma unroll
                for (int rr = 0; rr < 2; rr++)
                    sloc[mi][rr] += __shfl_xor_sync(0xffffffffu, sloc[mi][rr], o);
        if ((lane & 3) == 0)
            #pragma unroll
            for (int mi = 0; mi < 4; mi++)
                #pragma unroll
                for (int rr = 0; rr < 2; rr++)
                    sumbuf[wn * 128 + mi * 16 + rr * 8 + rbase] = sloc[mi][rr];
        __syncthreads();

        #pragma unroll
        for (int mi = 0; mi < 4; mi++) {
            #pragma unroll
            for (int rr = 0; rr < 2; rr++) {
                const int r = mi * 16 + rr * 8 + rbase;
                float st = sumbuf[r] + sumbuf[128 + r] + sumbuf[256 + r] + sumbuf[384 + r];
                l_run[mi][rr] = l_run[mi][rr] * alpha[mi][rr] + st;
                #pragma unroll
                for (int ni = 0; ni < 4; ni++) {
                    accO[mi][ni][rr * 2 + 0] *= alpha[mi][rr];
                    accO[mi][ni][rr * 2 + 1] *= alpha[mi][rr];
                }
            }
        }

        CP_WAIT(0);
        __syncthreads();

        #pragma unroll
        for (int ks = 0; ks < 8; ks++) {
            const uint32_t kof = (uint32_t)(ks * 32);
            uint32_t bhf[2][4], blf[2][4];
            #pragma unroll
            for (int np = 0; np < 2; np++) {
                const uint32_t o = (uint32_t)(np * 16 * FROW) + kof;
                LDSM_X4(bhf[np][0], bhf[np][1], bhf[np][2], bhf[np][3], sb + FV_H + bOff + o);
                LDSM_X4(blf[np][0], blf[np][1], blf[np][2], blf[np][3], sb + FV_L + bOff + o);
            }
            #pragma unroll
            for (int mi = 0; mi < 4; mi++) {
                uint32_t ah[4], al[4];
                const uint32_t o = (uint32_t)(mi * 16 * FROW) + kof;
                LDSM_X4(ah[0], ah[1], ah[2], ah[3], sb + FP_H + aOff + o);
                LDSM_X4(al[0], al[1], al[2], al[3], sb + FP_L + aOff + o);
                #pragma unroll
                for (int np = 0; np < 2; np++)
                    #pragma unroll
                    for (int hf = 0; hf < 2; hf++)
                        MMA16816(accO[mi][np * 2 + hf], ah, bhf[np][hf * 2], bhf[np][hf * 2 + 1]);
                #pragma unroll
                for (int np = 0; np < 2; np++)
                    #pragma unroll
                    for (int hf = 0; hf < 2; hf++)
                        MMA16816(accO[mi][np * 2 + hf], ah, blf[np][hf * 2], blf[np][hf * 2 + 1]);
                #pragma unroll
                for (int np = 0; np < 2; np++)
                    #pragma unroll
                    for (int hf = 0; hf < 2; hf++)
                        MMA16816(accO[mi][np * 2 + hf], al, bhf[np][hf * 2], bhf[np][hf * 2 + 1]);
            }
        }
        __syncthreads();

        if (jt < it) {
            const size_t koff = ((size_t)(b * SS + j0 + 128 + lrow) * KVHN + hk) * HD + half * 64;
            #pragma unroll
            for (int j = 0; j < 8; j++) {
                CP_ASYNC16(sb + FK_H + sA + j * 16, kh + koff + j * 8);
                CP_ASYNC16(sb + FK_L + sA + j * 16, kl + koff + j * 8);
            }
            CP_COMMIT();
        }
    }

    #pragma unroll
    for (int mi = 0; mi < 4; mi++) {
        #pragma unroll
        for (int rr = 0; rr < 2; rr++) {
            const float inv = 1.f / l_run[mi][rr];
            const int r = wm * 64 + mi * 16 + rr * 8 + (lane >> 2);
            const size_t rowoff = ((size_t)b * SS + i0 + r) * (HH * HD) + h * HD;
            #pragma unroll
            for (int ni = 0; ni < 4; ni++) {
                const int cc = wn * 32 + ni * 8 + (lane & 3) * 2;
                __nv_bfloat162 hv, lv;
                split2(accO[mi][ni][rr * 2 + 0] * inv, hv.x, lv.x);
                split2(accO[mi][ni][rr * 2 + 1] * inv, hv.y, lv.y);
                *(__nv_bfloat162*)(Oh + rowoff + cc) = hv;
                *(__nv_bfloat162*)(Ol + rowoff + cc) = lv;
            }
        }
    }
}

// ================= launch =================
static inline void run_split(const float* w, __nv_bfloat16* h, __nv_bfloat16* l, size_t n) {
    int n8 = (int)(n / 8);
    split_kernel<<<(n8 + 255) / 256, 256>>>((const float4*)w, (uint4*)h, (uint4*)l, n8);
}

extern "C" void kernel_launch(void* const* d_in, const int* in_sizes, int n_in,
                              void* d_out, int out_size)
{
    const float* x          = (const float*)d_in[0];
    const int*   positions  = (const int*)  d_in[1];
    const float* wq         = (const float*)d_in[4];
    const float* wk         = (const float*)d_in[5];
    const float* wv         = (const float*)d_in[6];
    const float* wo         = (const float*)d_in[7];
    const float* q_scale    = (const float*)d_in[8];
    const float* k_scale    = (const float*)d_in[9];
    const float* pre_attn   = (const float*)d_in[10];
    const float* post_attn  = (const float*)d_in[11];
    const float* pre_ffn    = (const float*)d_in[12];
    const float* post_ffn   = (const float*)d_in[13];
    const float* w_gate     = (const float*)d_in[14];
    const float* w_up       = (const float*)d_in[15];
    const float* w_down     = (const float*)d_in[16];
    const float* layer_scal = (const float*)d_in[17];
    float* out = (float*)d_out;

    float *q_, *k_, *v_, *tmp_, *x2_, *gate_, *ffn_, *rc_, *rs_;
    __nv_bfloat16 *ah_, *al_, *uh_, *ul_, *qh_, *ql_, *kh_, *kl_, *vth_, *vtl_;
    __nv_bfloat16 *wqh, *wql, *wkh, *wkl, *wvh, *wvl, *woh, *wol, *wgh, *wgl, *wuh, *wul, *wdh, *wdl;
    cudaGetSymbolAddress((void**)&q_,   g_q);
    cudaGetSymbolAddress((void**)&k_,   g_k);
    cudaGetSymbolAddress((void**)&v_,   g_v);
    cudaGetSymbolAddress((void**)&tmp_, g_tmp);
    cudaGetSymbolAddress((void**)&x2_,  g_x2);
    cudaGetSymbolAddress((void**)&gate_,g_gate);
    cudaGetSymbolAddress((void**)&ffn_, g_ffn);
    cudaGetSymbolAddress((void**)&rc_,  g_ropec);
    cudaGetSymbolAddress((void**)&rs_,  g_ropes);
    cudaGetSymbolAddress((void**)&ah_,  g_ah);
    cudaGetSymbolAddress((void**)&al_,  g_al);
    cudaGetSymbolAddress((void**)&uh_,  g_uh);
    cudaGetSymbolAddress((void**)&ul_,  g_ul);
    cudaGetSymbolAddress((void**)&qh_,  g_qh);  cudaGetSymbolAddress((void**)&ql_,  g_ql);
    cudaGetSymbolAddress((void**)&kh_,  g_kh);  cudaGetSymbolAddress((void**)&kl_,  g_kl);
    cudaGetSymbolAddress((void**)&vth_, g_vth); cudaGetSymbolAddress((void**)&vtl_, g_vtl);
    cudaGetSymbolAddress((void**)&wqh, g_wqh); cudaGetSymbolAddress((void**)&wql, g_wql);
    cudaGetSymbolAddress((void**)&wkh, g_wkh); cudaGetSymbolAddress((void**)&wkl, g_wkl);
    cudaGetSymbolAddress((void**)&wvh, g_wvh); cudaGetSymbolAddress((void**)&wvl, g_wvl);
    cudaGetSymbolAddress((void**)&woh, g_woh); cudaGetSymbolAddress((void**)&wol, g_wol);
    cudaGetSymbolAddress((void**)&wgh, g_wgh); cudaGetSymbolAddress((void**)&wgl, g_wgl);
    cudaGetSymbolAddress((void**)&wuh, g_wuh); cudaGetSymbolAddress((void**)&wul, g_wul);
    cudaGetSymbolAddress((void**)&wdh, g_wdh); cudaGetSymbolAddress((void**)&wdl, g_wdl);

    cudaFuncSetAttribute(gemm_mma,       cudaFuncAttributeMaxDynamicSharedMemorySize, GSMEM2);
    cudaFuncSetAttribute(gemm_mma_geglu, cudaFuncAttributeMaxDynamicSharedMemorySize, GSMEM2);
    cudaFuncSetAttribute(attn_fused,     cudaFuncAttributeMaxDynamicSharedMemorySize, FSMEM);

    // weight splits + rope table
    run_split(wq,     wqh, wql, (size_t)HH * HD * DD);
    run_split(wk,     wkh, wkl, (size_t)KVHN * HD * DD);
    run_split(wv,     wvh, wvl, (size_t)KVHN * HD * DD);
    run_split(wo,     woh, wol, (size_t)DD * HH * HD);
    run_split(w_gate, wgh, wgl, (size_t)FFN * DD);
    run_split(w_up,   wuh, wul, (size_t)FFN * DD);
    run_split(w_down, wdh, wdl, (size_t)DD * FFN);
    rope_table_kernel<<<MM, 64>>>(positions, rc_, rs_);

    // ---- attention sub-block ----
    rmsnorm_kernel<<<MM, 256>>>(x, pre_attn, nullptr, nullptr, nullptr, ah_, al_, DD);
    gemm_mma<<<dim3((HH*HD)/128,   MM/256), 512, GSMEM2>>>(ah_, al_, wqh, wql, q_, MM, HH*HD,   DD);
    gemm_mma<<<dim3((KVHN*HD)/128, MM/256), 512, GSMEM2>>>(ah_, al_, wkh, wkl, k_, MM, KVHN*HD, DD);
    gemm_mma<<<dim3((KVHN*HD)/128, MM/256), 512, GSMEM2>>>(ah_, al_, wvh, wvl, v_, MM, KVHN*HD, DD);
    headnorm_rope_kernel<<<MM * HH,   128>>>(q_, q_scale, rc_, rs_, HH,   1, qh_, ql_);
    headnorm_rope_kernel<<<MM * KVHN, 128>>>(k_, k_scale, rc_, rs_, KVHN, 1, kh_, kl_);
    headnorm_rope_kernel<<<MM * KVHN, 128>>>(v_, nullptr, rc_, rs_, KVHN, 0, nullptr, nullptr);
    vtrans_kernel<<<dim3(SS/32, HD/32, BB*KVHN), 256>>>(v_, vth_, vtl_);
    attn_fused<<<dim3(SS/128, BB*HH), 256, FSMEM>>>(qh_, ql_, kh_, kl_, vth_, vtl_, ah_, al_);
    gemm_mma<<<dim3(DD/128, MM/256), 512, GSMEM2>>>(ah_, al_, woh, wol, tmp_, MM, DD, HH*HD);

    // fused: x2 = rms(tmp)*post_attn + x;  ah/al = split(rms(x2)*pre_ffn)
    rmsnorm2_kernel<<<MM, 256>>>(tmp_, post_attn, x, pre_ffn, x2_, ah_, al_);

    // ---- FFN sub-block ----
    gemm_mma<<<dim3(FFN/128, MM/256), 512, GSMEM2>>>(ah_, al_, wgh, wgl, gate_, MM, FFN, DD);
    gemm_mma_geglu<<<dim3(FFN/128, MM/256), 512, GSMEM2>>>(ah_, al_, wuh, wul, gate_,
                                                           uh_, ul_, MM, FFN, DD);
    gemm_mma<<<dim3(DD/128, MM/256), 512, GSMEM2>>>(uh_, ul_, wdh, wdl, ffn_, MM, DD, FFN);
    rmsnorm_kernel<<<MM, 256>>>(ffn_, post_ffn, x2_, layer_scal, out, nullptr, nullptr, DD);
}

// round 15
// speedup vs baseline: 1.3540x; 1.0063x over previous
#include <cuda_runtime.h>
#include <cuda_bf16.h>
#include <cstdint>
#include <math.h>

#define BB 4
#define SS 1024
#define DD 2048
#define HH 16
#define KVHN 8
#define HD 128
#define FFN 8192
#define MM (BB*SS)
#define EPS_RMS 1e-6f
#define KMASK -1e30f

// ================= PTX helpers (base sm_103 ISA only) =================
__device__ __forceinline__ uint32_t smem_to_u32(const void* p) {
    uint32_t a;
    asm("{ .reg .u64 t; cvta.to.shared.u64 t, %1; cvt.u32.u64 %0, t; }" : "=r"(a) : "l"(p));
    return a;
}
#define CP_ASYNC16(sa, gp) \
    asm volatile("cp.async.cg.shared.global [%0], [%1], 16;" :: "r"(sa), "l"(gp) : "memory")
#define CP_COMMIT() asm volatile("cp.async.commit_group;" ::: "memory")
#define CP_WAIT(n)  asm volatile("cp.async.wait_group %0;" :: "n"(n) : "memory")

#define LDSM_X4(r0, r1, r2, r3, sa) \
    asm volatile("ldmatrix.sync.aligned.m8n8.x4.shared.b16 {%0,%1,%2,%3}, [%4];" \
                 : "=r"(r0), "=r"(r1), "=r"(r2), "=r"(r3) : "r"(sa))

#define MMA16816(d, a, b0, b1) \
    asm volatile("mma.sync.aligned.m16n8k16.row.col.f32.bf16.bf16.f32 " \
                 "{%0,%1,%2,%3}, {%4,%5,%6,%7}, {%8,%9}, {%0,%1,%2,%3};" \
                 : "+f"((d)[0]), "+f"((d)[1]), "+f"((d)[2]), "+f"((d)[3]) \
                 : "r"((a)[0]), "r"((a)[1]), "r"((a)[2]), "r"((a)[3]), "r"(b0), "r"(b1))

// ================= scratch =================
__device__ float g_q   [(size_t)MM*HH*HD];
__device__ float g_k   [(size_t)MM*KVHN*HD];
__device__ float g_v   [(size_t)MM*KVHN*HD];
__device__ float g_tmp [(size_t)MM*DD];
__device__ float g_x2  [(size_t)MM*DD];
__device__ float g_ffn [(size_t)MM*DD];
__device__ __nv_bfloat16 g_ah[(size_t)MM*FFN];
__device__ __nv_bfloat16 g_al[(size_t)MM*FFN];
__device__ __nv_bfloat16 g_uh[(size_t)MM*FFN];
__device__ __nv_bfloat16 g_ul[(size_t)MM*FFN];
// attention bf16 operands
__device__ __nv_bfloat16 g_qh[(size_t)MM*HH*HD],   g_ql[(size_t)MM*HH*HD];
__device__ __nv_bfloat16 g_kh[(size_t)MM*KVHN*HD], g_kl[(size_t)MM*KVHN*HD];
__device__ __nv_bfloat16 g_vth[(size_t)MM*KVHN*HD],g_vtl[(size_t)MM*KVHN*HD];
// RoPE cos/sin table [token][64]
__device__ float g_ropec[(size_t)MM*64];
__device__ float g_ropes[(size_t)MM*64];
// bf16 hi/lo weights
__device__ __nv_bfloat16 g_wqh[(size_t)HH*HD*DD],  g_wql[(size_t)HH*HD*DD];
__device__ __nv_bfloat16 g_wkh[(size_t)KVHN*HD*DD],g_wkl[(size_t)KVHN*HD*DD];
__device__ __nv_bfloat16 g_wvh[(size_t)KVHN*HD*DD],g_wvl[(size_t)KVHN*HD*DD];
__device__ __nv_bfloat16 g_woh[(size_t)DD*HH*HD],  g_wol[(size_t)DD*HH*HD];
__device__ __nv_bfloat16 g_wgh[(size_t)FFN*DD],    g_wgl[(size_t)FFN*DD];
__device__ __nv_bfloat16 g_wuh[(size_t)FFN*DD],    g_wul[(size_t)FFN*DD];
__device__ __nv_bfloat16 g_wdh[(size_t)DD*FFN],    g_wdl[(size_t)DD*FFN];

__device__ __forceinline__ void split2(float v, __nv_bfloat16& h, __nv_bfloat16& l) {
    h = __float2bfloat16(v);
    l = __float2bfloat16(v - __bfloat162float(h));
}
__device__ __forceinline__ float gelu_tanh(float x) {
    float t = 0.7978845608028654f * (x + 0.044715f * x * x * x);
    return 0.5f * x * (1.f + tanhf(t));
}

// ================= weight split (vectorized) =================
__global__ __launch_bounds__(256) void split_kernel(
    const float4* __restrict__ x, uint4* __restrict__ hi,
    uint4* __restrict__ lo, int n8)
{
    int i = blockIdx.x * 256 + threadIdx.x;
    if (i < n8) {
        float4 a = x[2 * i], b = x[2 * i + 1];
        __nv_bfloat162 h0, h1, h2, h3, l0, l1, l2, l3;
        split2(a.x, h0.x, l0.x); split2(a.y, h0.y, l0.y);
        split2(a.z, h1.x, l1.x); split2(a.w, h1.y, l1.y);
        split2(b.x, h2.x, l2.x); split2(b.y, h2.y, l2.y);
        split2(b.z, h3.x, l3.x); split2(b.w, h3.y, l3.y);
        uint4 hv, lv;
        hv.x = *(uint32_t*)&h0; hv.y = *(uint32_t*)&h1;
        hv.z = *(uint32_t*)&h2; hv.w = *(uint32_t*)&h3;
        lv.x = *(uint32_t*)&l0; lv.y = *(uint32_t*)&l1;
        lv.z = *(uint32_t*)&l2; lv.w = *(uint32_t*)&l3;
        hi[i] = hv; lo[i] = lv;
    }
}

// ================= RoPE cos/sin table =================
__global__ __launch_bounds__(64) void rope_table_kernel(
    const int* __restrict__ positions, float* __restrict__ rc, float* __restrict__ rs)
{
    const int token = blockIdx.x;
    const int d = threadIdx.x;
    const int pos = positions[token];
    double freq = pow(10000.0, -((double)(2 * d) / 128.0));
    double ang = (double)pos * freq;
    double dsin, dcos;
    sincos(ang, &dsin, &dcos);
    rc[token * 64 + d] = (float)dcos;
    rs[token * 64 + d] = (float)dsin;
}

// ================= RMSNorm =================
__global__ __launch_bounds__(256) void rmsnorm_kernel(
    const float* __restrict__ in, const float* __restrict__ scale,
    const float* __restrict__ resid, const float* __restrict__ lsc,
    float* __restrict__ out, __nv_bfloat16* __restrict__ oh,
    __nv_bfloat16* __restrict__ ol, int N)
{
    __shared__ float red[8];
    const size_t row = blockIdx.x;
    const float* x = in + row * (size_t)N;
    float ss = 0.f;
    for (int j = threadIdx.x; j < N; j += 256) { float v = x[j]; ss = fmaf(v, v, ss); }
    int lane = threadIdx.x & 31, wid = threadIdx.x >> 5;
    #pragma unroll
    for (int o = 16; o > 0; o >>= 1) ss += __shfl_down_sync(0xffffffffu, ss, o);
    if (lane == 0) red[wid] = ss;
    __syncthreads();
    if (threadIdx.x == 0) {
        float s = 0.f;
        #pragma unroll
        for (int w = 0; w < 8; w++) s += red[w];
        red[0] = s;
    }
    __syncthreads();
    const float r = rsqrtf(red[0] / (float)N + EPS_RMS);
    const float ls = lsc ? lsc[0] : 1.f;
    const float* rp = resid ? resid + row * (size_t)N : nullptr;
    for (int j = threadIdx.x; j < N; j += 256) {
        float v = x[j] * r;
        if (scale) v *= scale[j];
        if (rp) v += rp[j];
        v *= ls;
        if (out) out[row * (size_t)N + j] = v;
        if (oh) {
            __nv_bfloat16 h, l; split2(v, h, l);
            oh[row * (size_t)N + j] = h; ol[row * (size_t)N + j] = l;
        }
    }
}

// ===== fused double RMSNorm =====
__global__ __launch_bounds__(256) void rmsnorm2_kernel(
    const float* __restrict__ tmp, const float* __restrict__ s1,
    const float* __restrict__ resid, const float* __restrict__ s2,
    float* __restrict__ x2, __nv_bfloat16* __restrict__ oh,
    __nv_bfloat16* __restrict__ ol)
{
    __shared__ float red[8];
    const size_t base = (size_t)blockIdx.x * DD;
    const int tid = threadIdx.x;
    const int lane = tid & 31, wid = tid >> 5;
    float t[8];
    float ss = 0.f;
    #pragma unroll
    for (int q = 0; q < 8; q++) {
        t[q] = tmp[base + q * 256 + tid];
        ss = fmaf(t[q], t[q], ss);
    }
    #pragma unroll
    for (int o = 16; o > 0; o >>= 1) ss += __shfl_down_sync(0xffffffffu, ss, o);
    if (lane == 0) red[wid] = ss;
    __syncthreads();
    if (tid == 0) {
        float s = 0.f;
        #pragma unroll
        for (int w = 0; w < 8; w++) s += red[w];
        red[0] = s;
    }
    __syncthreads();
    const float r1 = rsqrtf(red[0] / (float)DD + EPS_RMS);
    __syncthreads();
    float v[8];
    float ss2 = 0.f;
    #pragma unroll
    for (int q = 0; q < 8; q++) {
        const int j = q * 256 + tid;
        v[q] = t[q] * r1 * s1[j] + resid[base + j];
        x2[base + j] = v[q];
        ss2 = fmaf(v[q], v[q], ss2);
    }
    #pragma unroll
    for (int o = 16; o > 0; o >>= 1) ss2 += __shfl_down_sync(0xffffffffu, ss2, o);
    if (lane == 0) red[wid] = ss2;
    __syncthreads();
    if (tid == 0) {
        float s = 0.f;
        #pragma unroll
        for (int w = 0; w < 8; w++) s += red[w];
        red[0] = s;
    }
    __syncthreads();
    const float r2 = rsqrtf(red[0] / (float)DD + EPS_RMS);
    #pragma unroll
    for (int q = 0; q < 8; q++) {
        const int j = q * 256 + tid;
        float o = v[q] * r2 * s2[j];
        __nv_bfloat16 h, l; split2(o, h, l);
        oh[base + j] = h; ol[base + j] = l;
    }
}

// ================= per-head RMSNorm (+ RoPE via table) =================
__global__ __launch_bounds__(128) void headnorm_rope_kernel(
    float* __restrict__ data, const float* __restrict__ scale,
    const float* __restrict__ ropec, const float* __restrict__ ropes,
    int nheads, int do_rope,
    __nv_bfloat16* __restrict__ oh, __nv_bfloat16* __restrict__ ol)
{
    __shared__ float red[4];
    __shared__ float sv[HD];
    const int d = threadIdx.x;
    const int idx = blockIdx.x;
    const int token = idx / nheads;
    float* p = data + (size_t)idx * HD;
    float v = p[d];
    float ss = v * v;
    int lane = d & 31, wid = d >> 5;
    #pragma unroll
    for (int o = 16; o > 0; o >>= 1) ss += __shfl_down_sync(0xffffffffu, ss, o);
    if (lane == 0) red[wid] = ss;
    __syncthreads();
    const float total = red[0] + red[1] + red[2] + red[3];
    const float r = rsqrtf(total * (1.0f / HD) + EPS_RMS);
    float nv = v * r;
    if (scale) nv *= scale[d];
    if (do_rope) {
        sv[d] = nv;
        __syncthreads();
        if (d < 64) {
            const float c = ropec[token * 64 + d];
            const float s = ropes[token * 64 + d];
            float x1 = sv[d], x2 = sv[d + 64];
            float o1 = x1 * c - x2 * s;
            float o2 = x2 * c + x1 * s;
            __nv_bfloat16 h1, l1, h2, l2;
            split2(o1, h1, l1); split2(o2, h2, l2);
            oh[(size_t)idx * HD + d]      = h1; ol[(size_t)idx * HD + d]      = l1;
            oh[(size_t)idx * HD + d + 64] = h2; ol[(size_t)idx * HD + d + 64] = l2;
        }
    } else {
        p[d] = nv;
    }
}

// ================= V transpose + split =================
__global__ __launch_bounds__(256) void vtrans_kernel(
    const float* __restrict__ v, __nv_bfloat16* __restrict__ vth,
    __nv_bfloat16* __restrict__ vtl)
{
    __shared__ float tile[32][33];
    const int z = blockIdx.z;
    const int b = z >> 3, hk = z & 7;
    const int s0 = blockIdx.x * 32, d0 = blockIdx.y * 32;
    const int tx = threadIdx.x & 31, ty = threadIdx.x >> 5;
    #pragma unroll
    for (int r = ty; r < 32; r += 8)
        tile[r][tx] = v[(size_t)(b * SS + s0 + r) * (KVHN * HD) + hk * HD + d0 + tx];
    __syncthreads();
    #pragma unroll
    for (int r = ty; r < 32; r += 8) {
        float val = tile[tx][r];
        __nv_bfloat16 h, l; split2(val, h, l);
        const size_t off = ((size_t)(b * KVHN + hk) * HD + d0 + r) * SS + s0 + tx;
        vth[off] = h; vtl[off] = l;
    }
}

// ================= HMMA bf16x3 GEMM core (256-row tile, shared macro) =================
#define ROW2  80
#define APART (256 * ROW2)
#define BPART (128 * ROW2)
#define STG2  (2 * APART + 2 * BPART)
#define GSMEM2 (3 * STG2)

#define GEMM_PROLOGUE_AND_MAINLOOP()                                              \
    extern __shared__ __align__(128) char smem[];                                 \
    const uint32_t sb = smem_to_u32(smem);                                        \
    const int tid = threadIdx.x;                                                  \
    const int wid = tid >> 5, lane = tid & 31;                                    \
    const int wm = wid >> 2, wn = wid & 3;                                        \
    const int m0 = blockIdx.y * 256, n0 = blockIdx.x * 128;                       \
    const int arow = tid >> 1;                                                    \
    const int acs  = (tid & 1) * 2;                                               \
    const int brow = tid >> 2;                                                    \
    const int bcs  = tid & 3;                                                     \
    const __nv_bfloat16* gAh = Ah + (size_t)(m0 + arow) * K + acs * 8;            \
    const __nv_bfloat16* gAl = Al + (size_t)(m0 + arow) * K + acs * 8;            \
    const __nv_bfloat16* gBh = Bh + (size_t)(n0 + brow) * K + bcs * 8;            \
    const __nv_bfloat16* gBl = Bl + (size_t)(n0 + brow) * K + bcs * 8;            \
    const uint32_t aS = (uint32_t)(arow * ROW2 + acs * 16);                       \
    const uint32_t bS = (uint32_t)(brow * ROW2 + bcs * 16);                       \
    const int nch = K / 32;                                                       \
    auto issue = [&](int c) {                                                     \
        const uint32_t st = sb + (uint32_t)(c % 3) * STG2;                        \
        const size_t ko = (size_t)c * 32;                                         \
        CP_ASYNC16(st + aS,                 gAh + ko);                            \
        CP_ASYNC16(st + aS + 16,            gAh + ko + 8);                        \
        CP_ASYNC16(st + APART + aS,         gAl + ko);                            \
        CP_ASYNC16(st + APART + aS + 16,    gAl + ko + 8);                        \
        CP_ASYNC16(st + 2 * APART + bS,         gBh + ko);                        \
        CP_ASYNC16(st + 2 * APART + BPART + bS, gBl + ko);                        \
    };                                                                            \
    issue(0); CP_COMMIT();                                                        \
    issue(1); CP_COMMIT();                                                        \
    const uint32_t aOff = (uint32_t)((wm * 64 + (lane & 15)) * ROW2 + (lane >> 4) * 16); \
    const uint32_t bOff = (uint32_t)((wn * 32 + ((lane & 7) | ((lane >> 4) << 3))) * ROW2 \
                                     + ((lane >> 3) & 1) * 16);                   \
    float acc[4][4][4];                                                           \
    _Pragma("unroll")                                                             \
    for (int i = 0; i < 4; i++)                                                   \
        _Pragma("unroll")                                                         \
        for (int j = 0; j < 4; j++)                                               \
            _Pragma("unroll")                                                     \
            for (int q = 0; q < 4; q++) acc[i][j][q] = 0.f;                       \
    for (int c = 0; c < nch; ++c) {                                               \
        if (c + 1 < nch) { CP_WAIT(1); } else { CP_WAIT(0); }                     \
        __syncthreads();                                                          \
        if (c + 2 < nch) { issue(c + 2); CP_COMMIT(); }                           \
        const uint32_t st = sb + (uint32_t)(c % 3) * STG2;                        \
        const uint32_t aH = st + aOff;                                            \
        const uint32_t aL = aH + APART;                                           \
        const uint32_t bH = st + 2 * APART + bOff;                                \
        const uint32_t bL = bH + BPART;                                           \
        _Pragma("unroll")                                                         \
        for (int ks = 0; ks < 2; ks++) {                                          \
            uint32_t bh[2][4], bl[2][4];                                          \
            _Pragma("unroll")                                                     \
            for (int np = 0; np < 2; np++) {                                      \
                const uint32_t o = (uint32_t)(np * 16 * ROW2 + ks * 32);          \
                LDSM_X4(bh[np][0], bh[np][1], bh[np][2], bh[np][3], bH + o);      \
                LDSM_X4(bl[np][0], bl[np][1], bl[np][2], bl[np][3], bL + o);      \
            }                                                                     \
            _Pragma("unroll")                                                     \
            for (int mi = 0; mi < 4; mi++) {                                      \
                uint32_t ah[4], al[4];                                            \
                const uint32_t o = (uint32_t)(mi * 16 * ROW2 + ks * 32);          \
                LDSM_X4(ah[0], ah[1], ah[2], ah[3], aH + o);                      \
                LDSM_X4(al[0], al[1], al[2], al[3], aL + o);                      \
                _Pragma("unroll")                                                 \
                for (int np = 0; np < 2; np++)                                    \
                    _Pragma("unroll")                                             \
                    for (int hf = 0; hf < 2; hf++)                                \
                        MMA16816(acc[mi][np * 2 + hf], ah, bh[np][hf * 2], bh[np][hf * 2 + 1]); \
                _Pragma("unroll")                                                 \
                for (int np = 0; np < 2; np++)                                    \
                    _Pragma("unroll")                                             \
                    for (int hf = 0; hf < 2; hf++)                                \
                        MMA16816(acc[mi][np * 2 + hf], ah, bl[np][hf * 2], bl[np][hf * 2 + 1]); \
                _Pragma("unroll")                                                 \
                for (int np = 0; np < 2; np++)                                    \
                    _Pragma("unroll")                                             \
                    for (int hf = 0; hf < 2; hf++)                                \
                        MMA16816(acc[mi][np * 2 + hf], al, bh[np][hf * 2], bh[np][hf * 2 + 1]); \
            }                                                                     \
        }                                                                         \
    }

__global__ __launch_bounds__(512, 1) void gemm_mma(
    const __nv_bfloat16* __restrict__ Ah, const __nv_bfloat16* __restrict__ Al,
    const __nv_bfloat16* __restrict__ Bh, const __nv_bfloat16* __restrict__ Bl,
    float* __restrict__ C, int M, int N, int K)
{
    GEMM_PROLOGUE_AND_MAINLOOP()
    #pragma unroll
    for (int mi = 0; mi < 4; mi++) {
        const int r = m0 + wm * 64 + mi * 16 + (lane >> 2);
        #pragma unroll
        for (int ni = 0; ni < 4; ni++) {
            const int cc = n0 + wn * 32 + ni * 8 + (lane & 3) * 2;
            *(float2*)&C[(size_t)r * N + cc]       = make_float2(acc[mi][ni][0], acc[mi][ni][1]);
            *(float2*)&C[(size_t)(r + 8) * N + cc] = make_float2(acc[mi][ni][2], acc[mi][ni][3]);
        }
    }
}

// ===== dual-B FFN GEMM: gate & up in one kernel, GeGLU in registers =====
// CTA 128x128, 256 threads (2x4 warps, warp tile 64x32), K-chunk 32, 3-stage.
// Stage: A hi/lo (2 x 10240) + Bg hi/lo + Bu hi/lo (4 x 10240) = 61440 B.
#define FAP  (128 * ROW2)               // 10240
#define FSTG (6 * FAP)                  // 61440
#define GSMEMF (3 * FSTG)               // 184320

__global__ __launch_bounds__(256, 1) void gemm_mma_ffn(
    const __nv_bfloat16* __restrict__ Ah, const __nv_bfloat16* __restrict__ Al,
    const __nv_bfloat16* __restrict__ Bgh, const __nv_bfloat16* __restrict__ Bgl,
    const __nv_bfloat16* __restrict__ Buh, const __nv_bfloat16* __restrict__ Bul,
    __nv_bfloat16* __restrict__ Oh, __nv_bfloat16* __restrict__ Ol,
    int M, int N, int K)
{
    extern __shared__ __align__(128) char smem[];
    const uint32_t sb = smem_to_u32(smem);
    const int tid = threadIdx.x;
    const int wid = tid >> 5, lane = tid & 31;
    const int wm = wid >> 2, wn = wid & 3;          // 2 x 4 warp grid
    const int m0 = blockIdx.y * 128, n0 = blockIdx.x * 128;

    // loaders: A rows via tid>>1 (2 chunks); B rows via tid>>2, each thread 2 rows (brow, brow+64)
    const int arow = tid >> 1;
    const int acs  = (tid & 1) * 2;
    const int brow = tid >> 2;                      // 0..63
    const int bcs  = tid & 3;
    const __nv_bfloat16* gA[2]  = { Ah  + (size_t)(m0 + arow) * K + acs * 8,
                                    Al  + (size_t)(m0 + arow) * K + acs * 8 };
    const __nv_bfloat16* gB[4]  = { Bgh + (size_t)(n0 + brow) * K + bcs * 8,
                                    Bgl + (size_t)(n0 + brow) * K + bcs * 8,
                                    Buh + (size_t)(n0 + brow) * K + bcs * 8,
                                    Bul + (size_t)(n0 + brow) * K + bcs * 8 };
    const size_t brow2 = (size_t)64 * K;            // +64 rows in gmem
    const uint32_t aS = (uint32_t)(arow * ROW2 + acs * 16);
    const uint32_t bS = (uint32_t)(brow * ROW2 + bcs * 16);

    const int nch = K / 32;

    auto issue = [&](int c) {
        const uint32_t st = sb + (uint32_t)(c % 3) * FSTG;
        const size_t ko = (size_t)c * 32;
        CP_ASYNC16(st + aS,              gA[0] + ko);
        CP_ASYNC16(st + aS + 16,         gA[0] + ko + 8);
        CP_ASYNC16(st + FAP + aS,        gA[1] + ko);
        CP_ASYNC16(st + FAP + aS + 16,   gA[1] + ko + 8);
        #pragma unroll
        for (int p = 0; p < 4; p++) {
            const uint32_t bo = st + (uint32_t)(2 + p) * FAP;
            CP_ASYNC16(bo + bS,             gB[p] + ko);
            CP_ASYNC16(bo + bS + 64 * ROW2, gB[p] + brow2 + ko);
        }
    };

    issue(0); CP_COMMIT();
    issue(1); CP_COMMIT();

    const uint32_t aOff = (uint32_t)((wm * 64 + (lane & 15)) * ROW2 + (lane >> 4) * 16);
    const uint32_t bOff = (uint32_t)((wn * 32 + ((lane & 7) | ((lane >> 4) << 3))) * ROW2
                                     + ((lane >> 3) & 1) * 16);

    float accg[4][4][4], accu[4][4][4];
    #pragma unroll
    for (int i = 0; i < 4; i++)
        #pragma unroll
        for (int j = 0; j < 4; j++)
            #pragma unroll
            for (int q = 0; q < 4; q++) { accg[i][j][q] = 0.f; accu[i][j][q] = 0.f; }

    for (int c = 0; c < nch; ++c) {
        if (c + 1 < nch) { CP_WAIT(1); } else { CP_WAIT(0); }
        __syncthreads();
        if (c + 2 < nch) { issue(c + 2); CP_COMMIT(); }

        const uint32_t st = sb + (uint32_t)(c % 3) * FSTG;
        const uint32_t aH  = st + aOff;
        const uint32_t aL  = aH + FAP;
        const uint32_t bgH = st + 2 * FAP + bOff;
        const uint32_t bgL = bgH + FAP;
        const uint32_t buH = bgL + FAP;
        const uint32_t buL = buH + FAP;

        #pragma unroll
        for (int ks = 0; ks < 2; ks++) {
            uint32_t gh[2][4], gl[2][4], uh[2][4], ul[2][4];
            #pragma unroll
            for (int np = 0; np < 2; np++) {
                const uint32_t o = (uint32_t)(np * 16 * ROW2 + ks * 32);
                LDSM_X4(gh[np][0], gh[np][1], gh[np][2], gh[np][3], bgH + o);
                LDSM_X4(gl[np][0], gl[np][1], gl[np][2], gl[np][3], bgL + o);
                LDSM_X4(uh[np][0], uh[np][1], uh[np][2], uh[np][3], buH + o);
                LDSM_X4(ul[np][0], ul[np][1], ul[np][2], ul[np][3], buL + o);
            }
            #pragma unroll
            for (int mi = 0; mi < 4; mi++) {
                uint32_t ah[4], al[4];
                const uint32_t o = (uint32_t)(mi * 16 * ROW2 + ks * 32);
                LDSM_X4(ah[0], ah[1], ah[2], ah[3], aH + o);
                LDSM_X4(al[0], al[1], al[2], al[3], aL + o);
                // gate: hh, hl, lh
                #pragma unroll
                for (int np = 0; np < 2; np++)
                    #pragma unroll
                    for (int hf = 0; hf < 2; hf++)
                        MMA16816(accg[mi][np * 2 + hf], ah, gh[np][hf * 2], gh[np][hf * 2 + 1]);
                #pragma unroll
                for (int np = 0; np < 2; np++)
                    #pragma unroll
                    for (int hf = 0; hf < 2; hf++)
                        MMA16816(accg[mi][np * 2 + hf], ah, gl[np][hf * 2], gl[np][hf * 2 + 1]);
                #pragma unroll
                for (int np = 0; np < 2; np++)
                    #pragma unroll
                    for (int hf = 0; hf < 2; hf++)
                        MMA16816(accg[mi][np * 2 + hf], al, gh[np][hf * 2], gh[np][hf * 2 + 1]);
                // up: hh, hl, lh
                #pragma unroll
                for (int np = 0; np < 2; np++)
                    #pragma unroll
                    for (int hf = 0; hf < 2; hf++)
                        MMA16816(accu[mi][np * 2 + hf], ah, uh[np][hf * 2], uh[np][hf * 2 + 1]);
                #pragma unroll
                for (int np = 0; np < 2; np++)
                    #pragma unroll
                    for (int hf = 0; hf < 2; hf++)
                        MMA16816(accu[mi][np * 2 + hf], ah, ul[np][hf * 2], ul[np][hf * 2 + 1]);
                #pragma unroll
                for (int np = 0; np < 2; np++)
                    #pragma unroll
                    for (int hf = 0; hf < 2; hf++)
                        MMA16816(accu[mi][np * 2 + hf], al, uh[np][hf * 2], uh[np][hf * 2 + 1]);
            }
        }
    }

    // epilogue: geglu in registers -> bf16 hi/lo
    #pragma unroll
    for (int mi = 0; mi < 4; mi++) {
        #pragma unroll
        for (int rr = 0; rr < 2; rr++) {
            const int r = m0 + wm * 64 + mi * 16 + rr * 8 + (lane >> 2);
            #pragma unroll
            for (int ni = 0; ni < 4; ni++) {
                const int cc = n0 + wn * 32 + ni * 8 + (lane & 3) * 2;
                float r0 = gelu_tanh(accg[mi][ni][rr * 2 + 0]) * accu[mi][ni][rr * 2 + 0];
                float r1 = gelu_tanh(accg[mi][ni][rr * 2 + 1]) * accu[mi][ni][rr * 2 + 1];
                __nv_bfloat162 hv, lv;
                split2(r0, hv.x, lv.x); split2(r1, hv.y, lv.y);
                *(__nv_bfloat162*)(Oh + (size_t)r * N + cc) = hv;
                *(__nv_bfloat162*)(Ol + (size_t)r * N + cc) = lv;
            }
        }
    }
}

// ================= fused flash attention =================
#define FROW  272
#define FTILE (128 * FROW)
#define FQ_H  0
#define FQ_L  (FQ_H + FTILE)
#define FK_H  (FQ_L + FTILE)
#define FK_L  (FK_H + FTILE)
#define FV_H  (FK_L + FTILE)
#define FV_L  (FV_H + FTILE)
#define FP_H  FK_H
#define FP_L  FK_L
#define FRED  (FV_L + FTILE)
#define FSMEM (FRED + 2 * 4 * 128 * 4)

__global__ __launch_bounds__(256, 1) void attn_fused(
    const __nv_bfloat16* __restrict__ qh, const __nv_bfloat16* __restrict__ ql,
    const __nv_bfloat16* __restrict__ kh, const __nv_bfloat16* __restrict__ kl,
    const __nv_bfloat16* __restrict__ vth, const __nv_bfloat16* __restrict__ vtl,
    __nv_bfloat16* __restrict__ Oh, __nv_bfloat16* __restrict__ Ol)
{
    extern __shared__ __align__(128) char smem[];
    const uint32_t sb = smem_to_u32(smem);
    const int bh = blockIdx.y;
    const int b = bh >> 4, h = bh & 15, hk = h >> 1;
    const int it = 7 - blockIdx.x;
    const int i0 = it * 128;
    const int tid = threadIdx.x;
    const int wid = tid >> 5, lane = tid & 31;
    const int wm = wid >> 2, wn = wid & 3;

    const int lrow = tid >> 1, half = tid & 1;
    const uint32_t sA = (uint32_t)(lrow * FROW + half * 128);
    const size_t qoff  = ((size_t)(b * SS + i0 + lrow) * HH + h) * HD + half * 64;
    const size_t vbase = ((size_t)(b * KVHN + hk) * HD + lrow) * SS + half * 64;

    #pragma unroll
    for (int j = 0; j < 8; j++) {
        CP_ASYNC16(sb + FQ_H + sA + j * 16, qh + qoff + j * 8);
        CP_ASYNC16(sb + FQ_L + sA + j * 16, ql + qoff + j * 8);
    }
    {
        const size_t koff = ((size_t)(b * SS + lrow) * KVHN + hk) * HD + half * 64;
        #pragma unroll
        for (int j = 0; j < 8; j++) {
            CP_ASYNC16(sb + FK_H + sA + j * 16, kh + koff + j * 8);
            CP_ASYNC16(sb + FK_L + sA + j * 16, kl + koff + j * 8);
        }
    }
    CP_COMMIT();

    const uint32_t aOff = (uint32_t)((wm * 64 + (lane & 15)) * FROW + (lane >> 4) * 16);
    const uint32_t bOff = (uint32_t)((wn * 32 + ((lane & 7) | ((lane >> 4) << 3))) * FROW
                                     + ((lane >> 3) & 1) * 16);

    float accO[4][4][4];
    float m_run[4][2], l_run[4][2];
    #pragma unroll
    for (int i = 0; i < 4; i++) {
        m_run[i][0] = -1e30f; m_run[i][1] = -1e30f;
        l_run[i][0] = 0.f;    l_run[i][1] = 0.f;
        #pragma unroll
        for (int j = 0; j < 4; j++)
            #pragma unroll
            for (int q = 0; q < 4; q++) accO[i][j][q] = 0.f;
    }

    float* maxbuf = (float*)(smem + FRED);
    float* sumbuf = maxbuf + 4 * 128;
    const int rbase = wm * 64 + (lane >> 2);

    for (int jt = 0; jt <= it; ++jt) {
        const int j0 = jt * 128;
        #pragma unroll
        for (int j = 0; j < 8; j++) {
            CP_ASYNC16(sb + FV_H + sA + j * 16, vth + vbase + j0 + j * 8);
            CP_ASYNC16(sb + FV_L + sA + j * 16, vtl + vbase + j0 + j * 8);
        }
        CP_COMMIT();
        CP_WAIT(1);
        __syncthreads();

        float accS[4][4][4];
        #pragma unroll
        for (int i = 0; i < 4; i++)
            #pragma unroll
            for (int j = 0; j < 4; j++)
                #pragma unroll
                for (int q = 0; q < 4; q++) accS[i][j][q] = 0.f;
        #pragma unroll
        for (int ks = 0; ks < 8; ks++) {
            const uint32_t kof = (uint32_t)(ks * 32);
            uint32_t bhf[2][4], blf[2][4];
            #pragma unroll
            for (int np = 0; np < 2; np++) {
                const uint32_t o = (uint32_t)(np * 16 * FROW) + kof;
                LDSM_X4(bhf[np][0], bhf[np][1], bhf[np][2], bhf[np][3], sb + FK_H + bOff + o);
                LDSM_X4(blf[np][0], blf[np][1], blf[np][2], blf[np][3], sb + FK_L + bOff + o);
            }
            #pragma unroll
            for (int mi = 0; mi < 4; mi++) {
                uint32_t ah[4], al[4];
                const uint32_t o = (uint32_t)(mi * 16 * FROW) + kof;
                LDSM_X4(ah[0], ah[1], ah[2], ah[3], sb + FQ_H + aOff + o);
                LDSM_X4(al[0], al[1], al[2], al[3], sb + FQ_L + aOff + o);
                #pragma unroll
                for (int np = 0; np < 2; np++)
                    #pragma unroll
                    for (int hf = 0; hf < 2; hf++)
                        MMA16816(accS[mi][np * 2 + hf], ah, bhf[np][hf * 2], bhf[np][hf * 2 + 1]);
                #pragma unroll
                for (int np = 0; np < 2; np++)
                    #pragma unroll
                    for (int hf = 0; hf < 2; hf++)
                        MMA16816(accS[mi][np * 2 + hf], ah, blf[np][hf * 2], blf[np][hf * 2 + 1]);
                #pragma unroll
                for (int np = 0; np < 2; np++)
                    #pragma unroll
                    for (int hf = 0; hf < 2; hf++)
                        MMA16816(accS[mi][np * 2 + hf], al, bhf[np][hf * 2], bhf[np][hf * 2 + 1]);
            }
        }

        const bool diag = (jt == it);
        float mloc[4][2];
        #pragma unroll
        for (int mi = 0; mi < 4; mi++) {
            #pragma unroll
            for (int rr = 0; rr < 2; rr++) {
                const int rL = mi * 16 + rr * 8 + rbase;
                float mx = -3.4e38f;
                #pragma unroll
                for (int ni = 0; ni < 4; ni++) {
                    #pragma unroll
                    for (int c = 0; c < 2; c++) {
                        const int cL = wn * 32 + ni * 8 + (lane & 3) * 2 + c;
                        float s = tanhf(accS[mi][ni][rr * 2 + c] * 0.02f) * 50.f;
                        if (diag && cL > rL) s = KMASK;
                        accS[mi][ni][rr * 2 + c] = s;
                        mx = fmaxf(mx, s);
                    }
                }
                mloc[mi][rr] = mx;
            }
        }
        #pragma unroll
        for (int o = 1; o <= 2; o <<= 1)
            #pragma unroll
            for (int mi = 0; mi < 4; mi++)
                #pragma unroll
                for (int rr = 0; rr < 2; rr++)
                    mloc[mi][rr] = fmaxf(mloc[mi][rr], __shfl_xor_sync(0xffffffffu, mloc[mi][rr], o));
        if ((lane & 3) == 0)
            #pragma unroll
            for (int mi = 0; mi < 4; mi++)
                #pragma unroll
                for (int rr = 0; rr < 2; rr++)
                    maxbuf[wn * 128 + mi * 16 + rr * 8 + rbase] = mloc[mi][rr];
        __syncthreads();

        float alpha[4][2], mnew[4][2], sloc[4][2];
        #pragma unroll
        for (int mi = 0; mi < 4; mi++) {
            #pragma unroll
            for (int rr = 0; rr < 2; rr++) {
                const int r = mi * 16 + rr * 8 + rbase;
                float mt = fmaxf(fmaxf(maxbuf[r], maxbuf[128 + r]),
                                 fmaxf(maxbuf[256 + r], maxbuf[384 + r]));
                float mn = fmaxf(m_run[mi][rr], mt);
                alpha[mi][rr] = __expf(m_run[mi][rr] - mn);
                mnew[mi][rr] = mn;
                m_run[mi][rr] = mn;
                sloc[mi][rr] = 0.f;
            }
        }
        #pragma unroll
        for (int mi = 0; mi < 4; mi++) {
            #pragma unroll
            for (int rr = 0; rr < 2; rr++) {
                const int rL = mi * 16 + rr * 8 + rbase;
                #pragma unroll
                for (int ni = 0; ni < 4; ni++) {
                    float p0 = __expf(accS[mi][ni][rr * 2 + 0] - mnew[mi][rr]);
                    float p1 = __expf(accS[mi][ni][rr * 2 + 1] - mnew[mi][rr]);
                    sloc[mi][rr] += p0 + p1;
                    const int cL = wn * 32 + ni * 8 + (lane & 3) * 2;
                    __nv_bfloat162 hv, lv;
                    split2(p0, hv.x, lv.x); split2(p1, hv.y, lv.y);
                    *(__nv_bfloat162*)(smem + FP_H + rL * FROW + cL * 2) = hv;
                    *(__nv_bfloat162*)(smem + FP_L + rL * FROW + cL * 2) = lv;
                }
            }
        }
        #pragma unroll
        for (int o = 1; o <= 2; o <<= 1)
            #pragma unroll
            for (int mi = 0; mi < 4; mi++)
                #pragma unroll
                for (int rr = 0; rr < 2; rr++)
                    sloc[mi][rr] += __shfl_xor_sync(0xffffffffu, sloc[mi][rr], o);
        if ((lane & 3) == 0)
            #pragma unroll
            for (int mi = 0; mi < 4; mi++)
                #pragma unroll
                for (int rr = 0; rr < 2; rr++)
                    sumbuf[wn * 128 + mi * 16 + rr * 8 + rbase] = sloc[mi][rr];
        __syncthreads();

        #pragma unroll
        for (int mi = 0; mi < 4; mi++) {
            #pragma unroll
            for (int rr = 0; rr < 2; rr++) {
                const int r = mi * 16 + rr * 8 + rbase;
                float st = sumbuf[r] + sumbuf[128 + r] + sumbuf[256 + r] + sumbuf[384 + r];
                l_run[mi][rr] = l_run[mi][rr] * alpha[mi][rr] + st;
                #pragma unroll
                for (int ni = 0; ni < 4; ni++) {
                    accO[mi][ni][rr * 2 + 0] *= alpha[mi][rr];
                    accO[mi][ni][rr * 2 + 1] *= alpha[mi][rr];
                }
            }
        }

        CP_WAIT(0);
        __syncthreads();

        #pragma unroll
        for (int ks = 0; ks < 8; ks++) {
            const uint32_t kof = (uint32_t)(ks * 32);
            uint32_t bhf[2][4], blf[2][4];
            #pragma unroll
            for (int np = 0; np < 2; np++) {
                const uint32_t o = (uint32_t)(np * 16 * FROW) + kof;
                LDSM_X4(bhf[np][0], bhf[np][1], bhf[np][2], bhf[np][3], sb + FV_H + bOff + o);
                LDSM_X4(blf[np][0], blf[np][1], blf[np][2], blf[np][3], sb + FV_L + bOff + o);
            }
            #pragma unroll
            for (int mi = 0; mi < 4; mi++) {
                uint32_t ah[4], al[4];
                const uint32_t o = (uint32_t)(mi * 16 * FROW) + kof;
                LDSM_X4(ah[0], ah[1], ah[2], ah[3], sb + FP_H + aOff + o);
                LDSM_X4(al[0], al[1], al[2], al[3], sb + FP_L + aOff + o);
                #pragma unroll
                for (int np = 0; np < 2; np++)
                    #pragma unroll
                    for (int hf = 0; hf < 2; hf++)
                        MMA16816(accO[mi][np * 2 + hf], ah, bhf[np][hf * 2], bhf[np][hf * 2 + 1]);
                #pragma unroll
                for (int np = 0; np < 2; np++)
                    #pragma unroll
                    for (int hf = 0; hf < 2; hf++)
                        MMA16816(accO[mi][np * 2 + hf], ah, blf[np][hf * 2], blf[np][hf * 2 + 1]);
                #pragma unroll
                for (int np = 0; np < 2; np++)
                    #pragma unroll
                    for (int hf = 0; hf < 2; hf++)
                        MMA16816(accO[mi][np * 2 + hf], al, bhf[np][hf * 2], bhf[np][hf * 2 + 1]);
            }
        }
        __syncthreads();

        if (jt < it) {
            const size_t koff = ((size_t)(b * SS + j0 + 128 + lrow) * KVHN + hk) * HD + half * 64;
            #pragma unroll
            for (int j = 0; j < 8; j++) {
                CP_ASYNC16(sb + FK_H + sA + j * 16, kh + koff + j * 8);
                CP_ASYNC16(sb + FK_L + sA + j * 16, kl + koff + j * 8);
            }
            CP_COMMIT();
        }
    }

    #pragma unroll
    for (int mi = 0; mi < 4; mi++) {
        #pragma unroll
        for (int rr = 0; rr < 2; rr++) {
            const float inv = 1.f / l_run[mi][rr];
            const int r = wm * 64 + mi * 16 + rr * 8 + (lane >> 2);
            const size_t rowoff = ((size_t)b * SS + i0 + r) * (HH * HD) + h * HD;
            #pragma unroll
            for (int ni = 0; ni < 4; ni++) {
                const int cc = wn * 32 + ni * 8 + (lane & 3) * 2;
                __nv_bfloat162 hv, lv;
                split2(accO[mi][ni][rr * 2 + 0] * inv, hv.x, lv.x);
                split2(accO[mi][ni][rr * 2 + 1] * inv, hv.y, lv.y);
                *(__nv_bfloat162*)(Oh + rowoff + cc) = hv;
                *(__nv_bfloat162*)(Ol + rowoff + cc) = lv;
            }
        }
    }
}

// ================= launch =================
static inline void run_split(const float* w, __nv_bfloat16* h, __nv_bfloat16* l, size_t n) {
    int n8 = (int)(n / 8);
    split_kernel<<<(n8 + 255) / 256, 256>>>((const float4*)w, (uint4*)h, (uint4*)l, n8);
}

extern "C" void kernel_launch(void* const* d_in, const int* in_sizes, int n_in,
                              void* d_out, int out_size)
{
    const float* x          = (const float*)d_in[0];
    const int*   positions  = (const int*)  d_in[1];
    const float* wq         = (const float*)d_in[4];
    const float* wk         = (const float*)d_in[5];
    const float* wv         = (const float*)d_in[6];
    const float* wo         = (const float*)d_in[7];
    const float* q_scale    = (const float*)d_in[8];
    const float* k_scale    = (const float*)d_in[9];
    const float* pre_attn   = (const float*)d_in[10];
    const float* post_attn  = (const float*)d_in[11];
    const float* pre_ffn    = (const float*)d_in[12];
    const float* post_ffn   = (const float*)d_in[13];
    const float* w_gate     = (const float*)d_in[14];
    const float* w_up       = (const float*)d_in[15];
    const float* w_down     = (const float*)d_in[16];
    const float* layer_scal = (const float*)d_in[17];
    float* out = (float*)d_out;

    float *q_, *k_, *v_, *tmp_, *x2_, *ffn_, *rc_, *rs_;
    __nv_bfloat16 *ah_, *al_, *uh_, *ul_, *qh_, *ql_, *kh_, *kl_, *vth_, *vtl_;
    __nv_bfloat16 *wqh, *wql, *wkh, *wkl, *wvh, *wvl, *woh, *wol, *wgh, *wgl, *wuh, *wul, *wdh, *wdl;
    cudaGetSymbolAddress((void**)&q_,   g_q);
    cudaGetSymbolAddress((void**)&k_,   g_k);
    cudaGetSymbolAddress((void**)&v_,   g_v);
    cudaGetSymbolAddress((void**)&tmp_, g_tmp);
    cudaGetSymbolAddress((void**)&x2_,  g_x2);
    cudaGetSymbolAddress((void**)&ffn_, g_ffn);
    cudaGetSymbolAddress((void**)&rc_,  g_ropec);
    cudaGetSymbolAddress((void**)&rs_,  g_ropes);
    cudaGetSymbolAddress((void**)&ah_,  g_ah);
    cudaGetSymbolAddress((void**)&al_,  g_al);
    cudaGetSymbolAddress((void**)&uh_,  g_uh);
    cudaGetSymbolAddress((void**)&ul_,  g_ul);
    cudaGetSymbolAddress((void**)&qh_,  g_qh);  cudaGetSymbolAddress((void**)&ql_,  g_ql);
    cudaGetSymbolAddress((void**)&kh_,  g_kh);  cudaGetSymbolAddress((void**)&kl_,  g_kl);
    cudaGetSymbolAddress((void**)&vth_, g_vth); cudaGetSymbolAddress((void**)&vtl_, g_vtl);
    cudaGetSymbolAddress((void**)&wqh, g_wqh); cudaGetSymbolAddress((void**)&wql, g_wql);
    cudaGetSymbolAddress((void**)&wkh, g_wkh); cudaGetSymbolAddress((void**)&wkl, g_wkl);
    cudaGetSymbolAddress((void**)&wvh, g_wvh); cudaGetSymbolAddress((void**)&wvl, g_wvl);
    cudaGetSymbolAddress((void**)&woh, g_woh); cudaGetSymbolAddress((void**)&wol, g_wol);
    cudaGetSymbolAddress((void**)&wgh, g_wgh); cudaGetSymbolAddress((void**)&wgl, g_wgl);
    cudaGetSymbolAddress((void**)&wuh, g_wuh); cudaGetSymbolAddress((void**)&wul, g_wul);
    cudaGetSymbolAddress((void**)&wdh, g_wdh); cudaGetSymbolAddress((void**)&wdl, g_wdl);

    cudaFuncSetAttribute(gemm_mma,     cudaFuncAttributeMaxDynamicSharedMemorySize, GSMEM2);
    cudaFuncSetAttribute(gemm_mma_ffn, cudaFuncAttributeMaxDynamicSharedMemorySize, GSMEMF);
    cudaFuncSetAttribute(attn_fused,   cudaFuncAttributeMaxDynamicSharedMemorySize, FSMEM);

    // weight splits + rope table
    run_split(wq,     wqh, wql, (size_t)HH * HD * DD);
    run_split(wk,     wkh, wkl, (size_t)KVHN * HD * DD);
    run_split(wv,     wvh, wvl, (size_t)KVHN * HD * DD);
    run_split(wo,     woh, wol, (size_t)DD * HH * HD);
    run_split(w_gate, wgh, wgl, (size_t)FFN * DD);
    run_split(w_up,   wuh, wul, (size_t)FFN * DD);
    run_split(w_down, wdh, wdl, (size_t)DD * FFN);
    rope_table_kernel<<<MM, 64>>>(positions, rc_, rs_);

    // ---- attention sub-block ----
    rmsnorm_kernel<<<MM, 256>>>(x, pre_attn, nullptr, nullptr, nullptr, ah_, al_, DD);
    gemm_mma<<<dim3((HH*HD)/128,   MM/256), 512, GSMEM2>>>(ah_, al_, wqh, wql, q_, MM, HH*HD,   DD);
    gemm_mma<<<dim3((KVHN*HD)/128, MM/256), 512, GSMEM2>>>(ah_, al_, wkh, wkl, k_, MM, KVHN*HD, DD);
    gemm_mma<<<dim3((KVHN*HD)/128, MM/256), 512, GSMEM2>>>(ah_, al_, wvh, wvl, v_, MM, KVHN*HD, DD);
    headnorm_rope_kernel<<<MM * HH,   128>>>(q_, q_scale, rc_, rs_, HH,   1, qh_, ql_);
    headnorm_rope_kernel<<<MM * KVHN, 128>>>(k_, k_scale, rc_, rs_, KVHN, 1, kh_, kl_);
    headnorm_rope_kernel<<<MM * KVHN, 128>>>(v_, nullptr, rc_, rs_, KVHN, 0, nullptr, nullptr);
    vtrans_kernel<<<dim3(SS/32, HD/32, BB*KVHN), 256>>>(v_, vth_, vtl_);
    attn_fused<<<dim3(SS/128, BB*HH), 256, FSMEM>>>(qh_, ql_, kh_, kl_, vth_, vtl_, ah_, al_);
    gemm_mma<<<dim3(DD/128, MM/256), 512, GSMEM2>>>(ah_, al_, woh, wol, tmp_, MM, DD, HH*HD);

    // fused: x2 = rms(tmp)*post_attn + x;  ah/al = split(rms(x2)*pre_ffn)
    rmsnorm2_kernel<<<MM, 256>>>(tmp_, post_attn, x, pre_ffn, x2_, ah_, al_);

    // ---- FFN sub-block: gate+up+GeGLU in one dual-B GEMM ----
    gemm_mma_ffn<<<dim3(FFN/128, MM/128), 256, GSMEMF>>>(ah_, al_, wgh, wgl, wuh, wul,
                                                         uh_, ul_, MM, FFN, DD);
    gemm_mma<<<dim3(DD/128, MM/256), 512, GSMEM2>>>(uh_, ul_, wdh, wdl, ffn_, MM, DD, FFN);
    rmsnorm_kernel<<<MM, 256>>>(ffn_, post_ffn, x2_, layer_scal, out, nullptr, nullptr, DD);
}

// round 16
// speedup vs baseline: 1.3571x; 1.0023x over previous
#include <cuda_runtime.h>
#include <cuda_bf16.h>
#include <cstdint>
#include <math.h>

#define BB 4
#define SS 1024
#define DD 2048
#define HH 16
#define KVHN 8
#define HD 128
#define FFN 8192
#define MM (BB*SS)
#define EPS_RMS 1e-6f
#define KMASK -1e30f

// ================= PTX helpers (base sm_103 ISA only) =================
__device__ __forceinline__ uint32_t smem_to_u32(const void* p) {
    uint32_t a;
    asm("{ .reg .u64 t; cvta.to.shared.u64 t, %1; cvt.u32.u64 %0, t; }" : "=r"(a) : "l"(p));
    return a;
}
#define CP_ASYNC16(sa, gp) \
    asm volatile("cp.async.cg.shared.global [%0], [%1], 16;" :: "r"(sa), "l"(gp) : "memory")
#define CP_COMMIT() asm volatile("cp.async.commit_group;" ::: "memory")
#define CP_WAIT(n)  asm volatile("cp.async.wait_group %0;" :: "n"(n) : "memory")

#define LDSM_X4(r0, r1, r2, r3, sa) \
    asm volatile("ldmatrix.sync.aligned.m8n8.x4.shared.b16 {%0,%1,%2,%3}, [%4];" \
                 : "=r"(r0), "=r"(r1), "=r"(r2), "=r"(r3) : "r"(sa))

#define MMA16816(d, a, b0, b1) \
    asm volatile("mma.sync.aligned.m16n8k16.row.col.f32.bf16.bf16.f32 " \
                 "{%0,%1,%2,%3}, {%4,%5,%6,%7}, {%8,%9}, {%0,%1,%2,%3};" \
                 : "+f"((d)[0]), "+f"((d)[1]), "+f"((d)[2]), "+f"((d)[3]) \
                 : "r"((a)[0]), "r"((a)[1]), "r"((a)[2]), "r"((a)[3]), "r"(b0), "r"(b1))

// ================= scratch =================
__device__ float g_tmp [(size_t)MM*DD];
__device__ float g_x2  [(size_t)MM*DD];
__device__ float g_ffn [(size_t)MM*DD];
__device__ __nv_bfloat16 g_ah[(size_t)MM*FFN];
__device__ __nv_bfloat16 g_al[(size_t)MM*FFN];
__device__ __nv_bfloat16 g_uh[(size_t)MM*FFN];
__device__ __nv_bfloat16 g_ul[(size_t)MM*FFN];
// attention bf16 operands
__device__ __nv_bfloat16 g_qh[(size_t)MM*HH*HD],   g_ql[(size_t)MM*HH*HD];
__device__ __nv_bfloat16 g_kh[(size_t)MM*KVHN*HD], g_kl[(size_t)MM*KVHN*HD];
__device__ __nv_bfloat16 g_vth[(size_t)MM*KVHN*HD],g_vtl[(size_t)MM*KVHN*HD];
// RoPE cos/sin table [token][64]
__device__ float g_ropec[(size_t)MM*64];
__device__ float g_ropes[(size_t)MM*64];
// bf16 hi/lo weights
__device__ __nv_bfloat16 g_wqh[(size_t)HH*HD*DD],  g_wql[(size_t)HH*HD*DD];
__device__ __nv_bfloat16 g_wkh[(size_t)KVHN*HD*DD],g_wkl[(size_t)KVHN*HD*DD];
__device__ __nv_bfloat16 g_wvh[(size_t)KVHN*HD*DD],g_wvl[(size_t)KVHN*HD*DD];
__device__ __nv_bfloat16 g_woh[(size_t)DD*HH*HD],  g_wol[(size_t)DD*HH*HD];
__device__ __nv_bfloat16 g_wgh[(size_t)FFN*DD],    g_wgl[(size_t)FFN*DD];
__device__ __nv_bfloat16 g_wuh[(size_t)FFN*DD],    g_wul[(size_t)FFN*DD];
__device__ __nv_bfloat16 g_wdh[(size_t)DD*FFN],    g_wdl[(size_t)DD*FFN];

__device__ __forceinline__ void split2(float v, __nv_bfloat16& h, __nv_bfloat16& l) {
    h = __float2bfloat16(v);
    l = __float2bfloat16(v - __bfloat162float(h));
}
__device__ __forceinline__ float gelu_tanh(float x) {
    float t = 0.7978845608028654f * (x + 0.044715f * x * x * x);
    return 0.5f * x * (1.f + tanhf(t));
}

// ================= weight split (vectorized) =================
__global__ __launch_bounds__(256) void split_kernel(
    const float4* __restrict__ x, uint4* __restrict__ hi,
    uint4* __restrict__ lo, int n8)
{
    int i = blockIdx.x * 256 + threadIdx.x;
    if (i < n8) {
        float4 a = x[2 * i], b = x[2 * i + 1];
        __nv_bfloat162 h0, h1, h2, h3, l0, l1, l2, l3;
        split2(a.x, h0.x, l0.x); split2(a.y, h0.y, l0.y);
        split2(a.z, h1.x, l1.x); split2(a.w, h1.y, l1.y);
        split2(b.x, h2.x, l2.x); split2(b.y, h2.y, l2.y);
        split2(b.z, h3.x, l3.x); split2(b.w, h3.y, l3.y);
        uint4 hv, lv;
        hv.x = *(uint32_t*)&h0; hv.y = *(uint32_t*)&h1;
        hv.z = *(uint32_t*)&h2; hv.w = *(uint32_t*)&h3;
        lv.x = *(uint32_t*)&l0; lv.y = *(uint32_t*)&l1;
        lv.z = *(uint32_t*)&l2; lv.w = *(uint32_t*)&l3;
        hi[i] = hv; lo[i] = lv;
    }
}

// ================= RoPE cos/sin table =================
__global__ __launch_bounds__(64) void rope_table_kernel(
    const int* __restrict__ positions, float* __restrict__ rc, float* __restrict__ rs)
{
    const int token = blockIdx.x;
    const int d = threadIdx.x;
    const int pos = positions[token];
    double freq = pow(10000.0, -((double)(2 * d) / 128.0));
    double ang = (double)pos * freq;
    double dsin, dcos;
    sincos(ang, &dsin, &dcos);
    rc[token * 64 + d] = (float)dcos;
    rs[token * 64 + d] = (float)dsin;
}

// ================= RMSNorm =================
__global__ __launch_bounds__(256) void rmsnorm_kernel(
    const float* __restrict__ in, const float* __restrict__ scale,
    const float* __restrict__ resid, const float* __restrict__ lsc,
    float* __restrict__ out, __nv_bfloat16* __restrict__ oh,
    __nv_bfloat16* __restrict__ ol, int N)
{
    __shared__ float red[8];
    const size_t row = blockIdx.x;
    const float* x = in + row * (size_t)N;
    float ss = 0.f;
    for (int j = threadIdx.x; j < N; j += 256) { float v = x[j]; ss = fmaf(v, v, ss); }
    int lane = threadIdx.x & 31, wid = threadIdx.x >> 5;
    #pragma unroll
    for (int o = 16; o > 0; o >>= 1) ss += __shfl_down_sync(0xffffffffu, ss, o);
    if (lane == 0) red[wid] = ss;
    __syncthreads();
    if (threadIdx.x == 0) {
        float s = 0.f;
        #pragma unroll
        for (int w = 0; w < 8; w++) s += red[w];
        red[0] = s;
    }
    __syncthreads();
    const float r = rsqrtf(red[0] / (float)N + EPS_RMS);
    const float ls = lsc ? lsc[0] : 1.f;
    const float* rp = resid ? resid + row * (size_t)N : nullptr;
    for (int j = threadIdx.x; j < N; j += 256) {
        float v = x[j] * r;
        if (scale) v *= scale[j];
        if (rp) v += rp[j];
        v *= ls;
        if (out) out[row * (size_t)N + j] = v;
        if (oh) {
            __nv_bfloat16 h, l; split2(v, h, l);
            oh[row * (size_t)N + j] = h; ol[row * (size_t)N + j] = l;
        }
    }
}

// ===== fused double RMSNorm =====
__global__ __launch_bounds__(256) void rmsnorm2_kernel(
    const float* __restrict__ tmp, const float* __restrict__ s1,
    const float* __restrict__ resid, const float* __restrict__ s2,
    float* __restrict__ x2, __nv_bfloat16* __restrict__ oh,
    __nv_bfloat16* __restrict__ ol)
{
    __shared__ float red[8];
    const size_t base = (size_t)blockIdx.x * DD;
    const int tid = threadIdx.x;
    const int lane = tid & 31, wid = tid >> 5;
    float t[8];
    float ss = 0.f;
    #pragma unroll
    for (int q = 0; q < 8; q++) {
        t[q] = tmp[base + q * 256 + tid];
        ss = fmaf(t[q], t[q], ss);
    }
    #pragma unroll
    for (int o = 16; o > 0; o >>= 1) ss += __shfl_down_sync(0xffffffffu, ss, o);
    if (lane == 0) red[wid] = ss;
    __syncthreads();
    if (tid == 0) {
        float s = 0.f;
        #pragma unroll
        for (int w = 0; w < 8; w++) s += red[w];
        red[0] = s;
    }
    __syncthreads();
    const float r1 = rsqrtf(red[0] / (float)DD + EPS_RMS);
    __syncthreads();
    float v[8];
    float ss2 = 0.f;
    #pragma unroll
    for (int q = 0; q < 8; q++) {
        const int j = q * 256 + tid;
        v[q] = t[q] * r1 * s1[j] + resid[base + j];
        x2[base + j] = v[q];
        ss2 = fmaf(v[q], v[q], ss2);
    }
    #pragma unroll
    for (int o = 16; o > 0; o >>= 1) ss2 += __shfl_down_sync(0xffffffffu, ss2, o);
    if (lane == 0) red[wid] = ss2;
    __syncthreads();
    if (tid == 0) {
        float s = 0.f;
        #pragma unroll
        for (int w = 0; w < 8; w++) s += red[w];
        red[0] = s;
    }
    __syncthreads();
    const float r2 = rsqrtf(red[0] / (float)DD + EPS_RMS);
    #pragma unroll
    for (int q = 0; q < 8; q++) {
        const int j = q * 256 + tid;
        float o = v[q] * r2 * s2[j];
        __nv_bfloat16 h, l; split2(o, h, l);
        oh[base + j] = h; ol[base + j] = l;
    }
}

// ================= HMMA bf16x3 GEMM core (256-row tile, shared macro) =================
#define ROW2  80
#define APART (256 * ROW2)
#define BPART (128 * ROW2)
#define STG2  (2 * APART + 2 * BPART)
#define GSMEM2 (3 * STG2)

#define GEMM_PROLOGUE_AND_MAINLOOP()                                              \
    extern __shared__ __align__(128) char smem[];                                 \
    const uint32_t sb = smem_to_u32(smem);                                        \
    const int tid = threadIdx.x;                                                  \
    const int wid = tid >> 5, lane = tid & 31;                                    \
    const int wm = wid >> 2, wn = wid & 3;                                        \
    const int m0 = blockIdx.y * 256, n0 = blockIdx.x * 128;                       \
    const int arow = tid >> 1;                                                    \
    const int acs  = (tid & 1) * 2;                                               \
    const int brow = tid >> 2;                                                    \
    const int bcs  = tid & 3;                                                     \
    const __nv_bfloat16* gAh = Ah + (size_t)(m0 + arow) * K + acs * 8;            \
    const __nv_bfloat16* gAl = Al + (size_t)(m0 + arow) * K + acs * 8;            \
    const __nv_bfloat16* gBh = Bh + (size_t)(n0 + brow) * K + bcs * 8;            \
    const __nv_bfloat16* gBl = Bl + (size_t)(n0 + brow) * K + bcs * 8;            \
    const uint32_t aS = (uint32_t)(arow * ROW2 + acs * 16);                       \
    const uint32_t bS = (uint32_t)(brow * ROW2 + bcs * 16);                       \
    const int nch = K / 32;                                                       \
    auto issue = [&](int c) {                                                     \
        const uint32_t st = sb + (uint32_t)(c % 3) * STG2;                        \
        const size_t ko = (size_t)c * 32;                                         \
        CP_ASYNC16(st + aS,                 gAh + ko);                            \
        CP_ASYNC16(st + aS + 16,            gAh + ko + 8);                        \
        CP_ASYNC16(st + APART + aS,         gAl + ko);                            \
        CP_ASYNC16(st + APART + aS + 16,    gAl + ko + 8);                        \
        CP_ASYNC16(st + 2 * APART + bS,         gBh + ko);                        \
        CP_ASYNC16(st + 2 * APART + BPART + bS, gBl + ko);                        \
    };                                                                            \
    issue(0); CP_COMMIT();                                                        \
    issue(1); CP_COMMIT();                                                        \
    const uint32_t aOff = (uint32_t)((wm * 64 + (lane & 15)) * ROW2 + (lane >> 4) * 16); \
    const uint32_t bOff = (uint32_t)((wn * 32 + ((lane & 7) | ((lane >> 4) << 3))) * ROW2 \
                                     + ((lane >> 3) & 1) * 16);                   \
    float acc[4][4][4];                                                           \
    _Pragma("unroll")                                                             \
    for (int i = 0; i < 4; i++)                                                   \
        _Pragma("unroll")                                                         \
        for (int j = 0; j < 4; j++)                                               \
            _Pragma("unroll")                                                     \
            for (int q = 0; q < 4; q++) acc[i][j][q] = 0.f;                       \
    for (int c = 0; c < nch; ++c) {                                               \
        if (c + 1 < nch) { CP_WAIT(1); } else { CP_WAIT(0); }                     \
        __syncthreads();                                                          \
        if (c + 2 < nch) { issue(c + 2); CP_COMMIT(); }                           \
        const uint32_t st = sb + (uint32_t)(c % 3) * STG2;                        \
        const uint32_t aH = st + aOff;                                            \
        const uint32_t aL = aH + APART;                                           \
        const uint32_t bH = st + 2 * APART + bOff;                                \
        const uint32_t bL = bH + BPART;                                           \
        _Pragma("unroll")                                                         \
        for (int ks = 0; ks < 2; ks++) {                                          \
            uint32_t bh[2][4], bl[2][4];                                          \
            _Pragma("unroll")                                                     \
            for (int np = 0; np < 2; np++) {                                      \
                const uint32_t o = (uint32_t)(np * 16 * ROW2 + ks * 32);          \
                LDSM_X4(bh[np][0], bh[np][1], bh[np][2], bh[np][3], bH + o);      \
                LDSM_X4(bl[np][0], bl[np][1], bl[np][2], bl[np][3], bL + o);      \
            }                                                                     \
            _Pragma("unroll")                                                     \
            for (int mi = 0; mi < 4; mi++) {                                      \
                uint32_t ah[4], al[4];                                            \
                const uint32_t o = (uint32_t)(mi * 16 * ROW2 + ks * 32);          \
                LDSM_X4(ah[0], ah[1], ah[2], ah[3], aH + o);                      \
                LDSM_X4(al[0], al[1], al[2], al[3], aL + o);                      \
                _Pragma("unroll")                                                 \
                for (int np = 0; np < 2; np++)                                    \
                    _Pragma("unroll")                                             \
                    for (int hf = 0; hf < 2; hf++)                                \
                        MMA16816(acc[mi][np * 2 + hf], ah, bh[np][hf * 2], bh[np][hf * 2 + 1]); \
                _Pragma("unroll")                                                 \
                for (int np = 0; np < 2; np++)                                    \
                    _Pragma("unroll")                                             \
                    for (int hf = 0; hf < 2; hf++)                                \
                        MMA16816(acc[mi][np * 2 + hf], ah, bl[np][hf * 2], bl[np][hf * 2 + 1]); \
                _Pragma("unroll")                                                 \
                for (int np = 0; np < 2; np++)                                    \
                    _Pragma("unroll")                                             \
                    for (int hf = 0; hf < 2; hf++)                                \
                        MMA16816(acc[mi][np * 2 + hf], al, bh[np][hf * 2], bh[np][hf * 2 + 1]); \
            }                                                                     \
        }                                                                         \
    }

__global__ __launch_bounds__(512, 1) void gemm_mma(
    const __nv_bfloat16* __restrict__ Ah, const __nv_bfloat16* __restrict__ Al,
    const __nv_bfloat16* __restrict__ Bh, const __nv_bfloat16* __restrict__ Bl,
    float* __restrict__ C, int M, int N, int K)
{
    GEMM_PROLOGUE_AND_MAINLOOP()
    #pragma unroll
    for (int mi = 0; mi < 4; mi++) {
        const int r = m0 + wm * 64 + mi * 16 + (lane >> 2);
        #pragma unroll
        for (int ni = 0; ni < 4; ni++) {
            const int cc = n0 + wn * 32 + ni * 8 + (lane & 3) * 2;
            *(float2*)&C[(size_t)r * N + cc]       = make_float2(acc[mi][ni][0], acc[mi][ni][1]);
            *(float2*)&C[(size_t)(r + 8) * N + cc] = make_float2(acc[mi][ni][2], acc[mi][ni][3]);
        }
    }
}

// ===== QKV GEMM with fused head-RMSNorm (+ optional RoPE / V-transpose) epilogue =====
// N-tile (128) == one head. mode 0: rope -> Oh/Ol [token][nheads][HD].
// mode 2: v path, no scale/rope, transposed store to vt[(b*KVHN+head)*HD+d][s].
__global__ __launch_bounds__(512, 1) void gemm_mma_qkv(
    const __nv_bfloat16* __restrict__ Ah, const __nv_bfloat16* __restrict__ Al,
    const __nv_bfloat16* __restrict__ Bh, const __nv_bfloat16* __restrict__ Bl,
    const float* __restrict__ scale,
    const float* __restrict__ rc, const float* __restrict__ rs,
    __nv_bfloat16* __restrict__ Oh, __nv_bfloat16* __restrict__ Ol,
    int nheads, int mode, int M, int N, int K)
{
    GEMM_PROLOGUE_AND_MAINLOOP()
    __syncthreads();   // mainloop smem reads done; reuse smem for epilogue
    float* buf = (float*)smem;                    // [256][130] fp32
    float* red = (float*)(smem + 256 * 130 * 4);  // [4][256]
    const int head = n0 >> 7;
    const int qrow = lane >> 2;

    // 1) per-row sum of squares (quad shuffle + cross-warp smem)
    #pragma unroll
    for (int mi = 0; mi < 4; mi++) {
        #pragma unroll
        for (int rr = 0; rr < 2; rr++) {
            float ssq = 0.f;
            #pragma unroll
            for (int ni = 0; ni < 4; ni++) {
                float a0 = acc[mi][ni][rr * 2], a1 = acc[mi][ni][rr * 2 + 1];
                ssq = fmaf(a0, a0, ssq); ssq = fmaf(a1, a1, ssq);
            }
            ssq += __shfl_xor_sync(0xffffffffu, ssq, 1);
            ssq += __shfl_xor_sync(0xffffffffu, ssq, 2);
            if ((lane & 3) == 0)
                red[wn * 256 + wm * 64 + mi * 16 + rr * 8 + qrow] = ssq;
        }
    }
    __syncthreads();

    // 2) normalize (+scale); v: direct transposed store; q/k: stage to buf
    #pragma unroll
    for (int mi = 0; mi < 4; mi++) {
        #pragma unroll
        for (int rr = 0; rr < 2; rr++) {
            const int r = wm * 64 + mi * 16 + rr * 8 + qrow;
            const float tot = red[r] + red[256 + r] + red[512 + r] + red[768 + r];
            const float rn = rsqrtf(tot * (1.f / 128.f) + EPS_RMS);
            const int token = m0 + r;
            #pragma unroll
            for (int ni = 0; ni < 4; ni++) {
                const int col = wn * 32 + ni * 8 + (lane & 3) * 2;
                float v0 = acc[mi][ni][rr * 2]     * rn;
                float v1 = acc[mi][ni][rr * 2 + 1] * rn;
                if (scale) { v0 *= scale[col]; v1 *= scale[col + 1]; }
                if (mode == 2) {
                    const int bq = token >> 10, s = token & (SS - 1);
                    const size_t base = (size_t)(bq * KVHN + head) * HD;
                    __nv_bfloat16 h0, l0, h1, l1;
                    split2(v0, h0, l0); split2(v1, h1, l1);
                    Oh[(base + col)     * SS + s] = h0; Ol[(base + col)     * SS + s] = l0;
                    Oh[(base + col + 1) * SS + s] = h1; Ol[(base + col + 1) * SS + s] = l1;
                } else {
                    buf[r * 130 + col]     = v0;
                    buf[r * 130 + col + 1] = v1;
                }
            }
        }
    }
    if (mode == 2) return;
    __syncthreads();

    // 3) RoPE via table + split + store
    #pragma unroll
    for (int mi = 0; mi < 4; mi++) {
        #pragma unroll
        for (int rr = 0; rr < 2; rr++) {
            const int r = wm * 64 + mi * 16 + rr * 8 + qrow;
            const int token = m0 + r;
            const size_t rowoff = ((size_t)token * nheads + head) * HD;
            #pragma unroll
            for (int ni = 0; ni < 4; ni++) {
                const int col = wn * 32 + ni * 8 + (lane & 3) * 2;
                __nv_bfloat162 hv, lv;
                #pragma unroll
                for (int c = 0; c < 2; c++) {
                    const int cc = col + c;
                    const float xv = buf[r * 130 + cc];
                    const float xp = buf[r * 130 + (cc ^ 64)];
                    const int d = cc & 63;
                    const float cf = rc[token * 64 + d], sf = rs[token * 64 + d];
                    const float o = (cc < 64) ? xv * cf - xp * sf : xv * cf + xp * sf;
                    __nv_bfloat16 h, l; split2(o, h, l);
                    ((__nv_bfloat16*)&hv)[c] = h; ((__nv_bfloat16*)&lv)[c] = l;
                }
                *(__nv_bfloat162*)(Oh + rowoff + col) = hv;
                *(__nv_bfloat162*)(Ol + rowoff + col) = lv;
            }
        }
    }
}

// ===== dual-B FFN GEMM: gate & up in one kernel, GeGLU in registers =====
#define FAP  (128 * ROW2)
#define FSTG (6 * FAP)
#define GSMEMF (3 * FSTG)

__global__ __launch_bounds__(256, 1) void gemm_mma_ffn(
    const __nv_bfloat16* __restrict__ Ah, const __nv_bfloat16* __restrict__ Al,
    const __nv_bfloat16* __restrict__ Bgh, const __nv_bfloat16* __restrict__ Bgl,
    const __nv_bfloat16* __restrict__ Buh, const __nv_bfloat16* __restrict__ Bul,
    __nv_bfloat16* __restrict__ Oh, __nv_bfloat16* __restrict__ Ol,
    int M, int N, int K)
{
    extern __shared__ __align__(128) char smem[];
    const uint32_t sb = smem_to_u32(smem);
    const int tid = threadIdx.x;
    const int wid = tid >> 5, lane = tid & 31;
    const int wm = wid >> 2, wn = wid & 3;
    const int m0 = blockIdx.y * 128, n0 = blockIdx.x * 128;

    const int arow = tid >> 1;
    const int acs  = (tid & 1) * 2;
    const int brow = tid >> 2;
    const int bcs  = tid & 3;
    const __nv_bfloat16* gA[2]  = { Ah  + (size_t)(m0 + arow) * K + acs * 8,
                                    Al  + (size_t)(m0 + arow) * K + acs * 8 };
    const __nv_bfloat16* gB[4]  = { Bgh + (size_t)(n0 + brow) * K + bcs * 8,
                                    Bgl + (size_t)(n0 + brow) * K + bcs * 8,
                                    Buh + (size_t)(n0 + brow) * K + bcs * 8,
                                    Bul + (size_t)(n0 + brow) * K + bcs * 8 };
    const size_t brow2 = (size_t)64 * K;
    const uint32_t aS = (uint32_t)(arow * ROW2 + acs * 16);
    const uint32_t bS = (uint32_t)(brow * ROW2 + bcs * 16);

    const int nch = K / 32;

    auto issue = [&](int c) {
        const uint32_t st = sb + (uint32_t)(c % 3) * FSTG;
        const size_t ko = (size_t)c * 32;
        CP_ASYNC16(st + aS,              gA[0] + ko);
        CP_ASYNC16(st + aS + 16,         gA[0] + ko + 8);
        CP_ASYNC16(st + FAP + aS,        gA[1] + ko);
        CP_ASYNC16(st + FAP + aS + 16,   gA[1] + ko + 8);
        #pragma unroll
        for (int p = 0; p < 4; p++) {
            const uint32_t bo = st + (uint32_t)(2 + p) * FAP;
            CP_ASYNC16(bo + bS,             gB[p] + ko);
            CP_ASYNC16(bo + bS + 64 * ROW2, gB[p] + brow2 + ko);
        }
    };

    issue(0); CP_COMMIT();
    issue(1); CP_COMMIT();

    const uint32_t aOff = (uint32_t)((wm * 64 + (lane & 15)) * ROW2 + (lane >> 4) * 16);
    const uint32_t bOff = (uint32_t)((wn * 32 + ((lane & 7) | ((lane >> 4) << 3))) * ROW2
                                     + ((lane >> 3) & 1) * 16);

    float accg[4][4][4], accu[4][4][4];
    #pragma unroll
    for (int i = 0; i < 4; i++)
        #pragma unroll
        for (int j = 0; j < 4; j++)
            #pragma unroll
            for (int q = 0; q < 4; q++) { accg[i][j][q] = 0.f; accu[i][j][q] = 0.f; }

    for (int c = 0; c < nch; ++c) {
        if (c + 1 < nch) { CP_WAIT(1); } else { CP_WAIT(0); }
        __syncthreads();
        if (c + 2 < nch) { issue(c + 2); CP_COMMIT(); }

        const uint32_t st = sb + (uint32_t)(c % 3) * FSTG;
        const uint32_t aH  = st + aOff;
        const uint32_t aL  = aH + FAP;
        const uint32_t bgH = st + 2 * FAP + bOff;
        const uint32_t bgL = bgH + FAP;
        const uint32_t buH = bgL + FAP;
        const uint32_t buL = buH + FAP;

        #pragma unroll
        for (int ks = 0; ks < 2; ks++) {
            uint32_t gh[2][4], gl[2][4], uh[2][4], ul[2][4];
            #pragma unroll
            for (int np = 0; np < 2; np++) {
                const uint32_t o = (uint32_t)(np * 16 * ROW2 + ks * 32);
                LDSM_X4(gh[np][0], gh[np][1], gh[np][2], gh[np][3], bgH + o);
                LDSM_X4(gl[np][0], gl[np][1], gl[np][2], gl[np][3], bgL + o);
                LDSM_X4(uh[np][0], uh[np][1], uh[np][2], uh[np][3], buH + o);
                LDSM_X4(ul[np][0], ul[np][1], ul[np][2], ul[np][3], buL + o);
            }
            #pragma unroll
            for (int mi = 0; mi < 4; mi++) {
                uint32_t ah[4], al[4];
                const uint32_t o = (uint32_t)(mi * 16 * ROW2 + ks * 32);
                LDSM_X4(ah[0], ah[1], ah[2], ah[3], aH + o);
                LDSM_X4(al[0], al[1], al[2], al[3], aL + o);
                #pragma unroll
                for (int np = 0; np < 2; np++)
                    #pragma unroll
                    for (int hf = 0; hf < 2; hf++)
                        MMA16816(accg[mi][np * 2 + hf], ah, gh[np][hf * 2], gh[np][hf * 2 + 1]);
                #pragma unroll
                for (int np = 0; np < 2; np++)
                    #pragma unroll
                    for (int hf = 0; hf < 2; hf++)
                        MMA16816(accg[mi][np * 2 + hf], ah, gl[np][hf * 2], gl[np][hf * 2 + 1]);
                #pragma unroll
                for (int np = 0; np < 2; np++)
                    #pragma unroll
                    for (int hf = 0; hf < 2; hf++)
                        MMA16816(accg[mi][np * 2 + hf], al, gh[np][hf * 2], gh[np][hf * 2 + 1]);
                #pragma unroll
                for (int np = 0; np < 2; np++)
                    #pragma unroll
                    for (int hf = 0; hf < 2; hf++)
                        MMA16816(accu[mi][np * 2 + hf], ah, uh[np][hf * 2], uh[np][hf * 2 + 1]);
                #pragma unroll
                for (int np = 0; np < 2; np++)
                    #pragma unroll
                    for (int hf = 0; hf < 2; hf++)
                        MMA16816(accu[mi][np * 2 + hf], ah, ul[np][hf * 2], ul[np][hf * 2 + 1]);
                #pragma unroll
                for (int np = 0; np < 2; np++)
                    #pragma unroll
                    for (int hf = 0; hf < 2; hf++)
                        MMA16816(accu[mi][np * 2 + hf], al, uh[np][hf * 2], uh[np][hf * 2 + 1]);
            }
        }
    }

    #pragma unroll
    for (int mi = 0; mi < 4; mi++) {
        #pragma unroll
        for (int rr = 0; rr < 2; rr++) {
            const int r = m0 + wm * 64 + mi * 16 + rr * 8 + (lane >> 2);
            #pragma unroll
            for (int ni = 0; ni < 4; ni++) {
                const int cc = n0 + wn * 32 + ni * 8 + (lane & 3) * 2;
                float r0 = gelu_tanh(accg[mi][ni][rr * 2 + 0]) * accu[mi][ni][rr * 2 + 0];
                float r1 = gelu_tanh(accg[mi][ni][rr * 2 + 1]) * accu[mi][ni][rr * 2 + 1];
                __nv_bfloat162 hv, lv;
                split2(r0, hv.x, lv.x); split2(r1, hv.y, lv.y);
                *(__nv_bfloat162*)(Oh + (size_t)r * N + cc) = hv;
                *(__nv_bfloat162*)(Ol + (size_t)r * N + cc) = lv;
            }
        }
    }
}

// ================= fused flash attention =================
#define FROW  272
#define FTILE (128 * FROW)
#define FQ_H  0
#define FQ_L  (FQ_H + FTILE)
#define FK_H  (FQ_L + FTILE)
#define FK_L  (FK_H + FTILE)
#define FV_H  (FK_L + FTILE)
#define FV_L  (FV_H + FTILE)
#define FP_H  FK_H
#define FP_L  FK_L
#define FRED  (FV_L + FTILE)
#define FSMEM (FRED + 2 * 4 * 128 * 4)

__global__ __launch_bounds__(256, 1) void attn_fused(
    const __nv_bfloat16* __restrict__ qh, const __nv_bfloat16* __restrict__ ql,
    const __nv_bfloat16* __restrict__ kh, const __nv_bfloat16* __restrict__ kl,
    const __nv_bfloat16* __restrict__ vth, const __nv_bfloat16* __restrict__ vtl,
    __nv_bfloat16* __restrict__ Oh, __nv_bfloat16* __restrict__ Ol)
{
    extern __shared__ __align__(128) char smem[];
    const uint32_t sb = smem_to_u32(smem);
    const int bh = blockIdx.y;
    const int b = bh >> 4, h = bh & 15, hk = h >> 1;
    const int it = 7 - blockIdx.x;
    const int i0 = it * 128;
    const int tid = threadIdx.x;
    const int wid = tid >> 5, lane = tid & 31;
    const int wm = wid >> 2, wn = wid & 3;

    const int lrow = tid >> 1, half = tid & 1;
    const uint32_t sA = (uint32_t)(lrow * FROW + half * 128);
    const size_t qoff  = ((size_t)(b * SS + i0 + lrow) * HH + h) * HD + half * 64;
    const size_t vbase = ((size_t)(b * KVHN + hk) * HD + lrow) * SS + half * 64;

    #pragma unroll
    for (int j = 0; j < 8; j++) {
        CP_ASYNC16(sb + FQ_H + sA + j * 16, qh + qoff + j * 8);
        CP_ASYNC16(sb + FQ_L + sA + j * 16, ql + qoff + j * 8);
    }
    {
        const size_t koff = ((size_t)(b * SS + lrow) * KVHN + hk) * HD + half * 64;
        #pragma unroll
        for (int j = 0; j < 8; j++) {
            CP_ASYNC16(sb + FK_H + sA + j * 16, kh + koff + j * 8);
            CP_ASYNC16(sb + FK_L + sA + j * 16, kl + koff + j * 8);
        }
    }
    CP_COMMIT();

    const uint32_t aOff = (uint32_t)((wm * 64 + (lane & 15)) * FROW + (lane >> 4) * 16);
    const uint32_t bOff = (uint32_t)((wn * 32 + ((lane & 7) | ((lane >> 4) << 3))) * FROW
                                     + ((lane >> 3) & 1) * 16);

    float accO[4][4][4];
    float m_run[4][2], l_run[4][2];
    #pragma unroll
    for (int i = 0; i < 4; i++) {
        m_run[i][0] = -1e30f; m_run[i][1] = -1e30f;
        l_run[i][0] = 0.f;    l_run[i][1] = 0.f;
        #pragma unroll
        for (int j = 0; j < 4; j++)
            #pragma unroll
            for (int q = 0; q < 4; q++) accO[i][j][q] = 0.f;
    }

    float* maxbuf = (float*)(smem + FRED);
    float* sumbuf = maxbuf + 4 * 128;
    const int rbase = wm * 64 + (lane >> 2);

    for (int jt = 0; jt <= it; ++jt) {
        const int j0 = jt * 128;
        #pragma unroll
        for (int j = 0; j < 8; j++) {
            CP_ASYNC16(sb + FV_H + sA + j * 16, vth + vbase + j0 + j * 8);
            CP_ASYNC16(sb + FV_L + sA + j * 16, vtl + vbase + j0 + j * 8);
        }
        CP_COMMIT();
        CP_WAIT(1);
        __syncthreads();

        float accS[4][4][4];
        #pragma unroll
        for (int i = 0; i < 4; i++)
            #pragma unroll
            for (int j = 0; j < 4; j++)
                #pragma unroll
                for (int q = 0; q < 4; q++) accS[i][j][q] = 0.f;
        #pragma unroll
        for (int ks = 0; ks < 8; ks++) {
            const uint32_t kof = (uint32_t)(ks * 32);
            uint32_t bhf[2][4], blf[2][4];
            #pragma unroll
            for (int np = 0; np < 2; np++) {
                const uint32_t o = (uint32_t)(np * 16 * FROW) + kof;
                LDSM_X4(bhf[np][0], bhf[np][1], bhf[np][2], bhf[np][3], sb + FK_H + bOff + o);
                LDSM_X4(blf[np][0], blf[np][1], blf[np][2], blf[np][3], sb + FK_L + bOff + o);
            }
            #pragma unroll
            for (int mi = 0; mi < 4; mi++) {
                uint32_t ah[4], al[4];
                const uint32_t o = (uint32_t)(mi * 16 * FROW) + kof;
                LDSM_X4(ah[0], ah[1], ah[2], ah[3], sb + FQ_H + aOff + o);
                LDSM_X4(al[0], al[1], al[2], al[3], sb + FQ_L + aOff + o);
                #pragma unroll
                for (int np = 0; np < 2; np++)
                    #pragma unroll
                    for (int hf = 0; hf < 2; hf++)
                        MMA16816(accS[mi][np * 2 + hf], ah, bhf[np][hf * 2], bhf[np][hf * 2 + 1]);
                #pragma unroll
                for (int np = 0; np < 2; np++)
                    #pragma unroll
                    for (int hf = 0; hf < 2; hf++)
                        MMA16816(accS[mi][np * 2 + hf], ah, blf[np][hf * 2], blf[np][hf * 2 + 1]);
                #pragma unroll
                for (int np = 0; np < 2; np++)
                    #pragma unroll
                    for (int hf = 0; hf < 2; hf++)
                        MMA16816(accS[mi][np * 2 + hf], al, bhf[np][hf * 2], bhf[np][hf * 2 + 1]);
            }
        }

        const bool diag = (jt == it);
        float mloc[4][2];
        #pragma unroll
        for (int mi = 0; mi < 4; mi++) {
            #pragma unroll
            for (int rr = 0; rr < 2; rr++) {
                const int rL = mi * 16 + rr * 8 + rbase;
                float mx = -3.4e38f;
                #pragma unroll
                for (int ni = 0; ni < 4; ni++) {
                    #pragma unroll
                    for (int c = 0; c < 2; c++) {
                        const int cL = wn * 32 + ni * 8 + (lane & 3) * 2 + c;
                        float s = tanhf(accS[mi][ni][rr * 2 + c] * 0.02f) * 50.f;
                        if (diag && cL > rL) s = KMASK;
                        accS[mi][ni][rr * 2 + c] = s;
                        mx = fmaxf(mx, s);
                    }
                }
                mloc[mi][rr] = mx;
            }
        }
        #pragma unroll
        for (int o = 1; o <= 2; o <<= 1)
            #pragma unroll
            for (int mi = 0; mi < 4; mi++)
                #pragma unroll
                for (int rr = 0; rr < 2; rr++)
                    mloc[mi][rr] = fmaxf(mloc[mi][rr], __shfl_xor_sync(0xffffffffu, mloc[mi][rr], o));
        if ((lane & 3) == 0)
            #pragma unroll
            for (int mi = 0; mi < 4; mi++)
                #pragma unroll
                for (int rr = 0; rr < 2; rr++)
                    maxbuf[wn * 128 + mi * 16 + rr * 8 + rbase] = mloc[mi][rr];
        __syncthreads();

        float alpha[4][2], mnew[4][2], sloc[4][2];
        #pragma unroll
        for (int mi = 0; mi < 4; mi++) {
            #pragma unroll
            for (int rr = 0; rr < 2; rr++) {
                const int r = mi * 16 + rr * 8 + rbase;
                float mt = fmaxf(fmaxf(maxbuf[r], maxbuf[128 + r]),
                                 fmaxf(maxbuf[256 + r], maxbuf[384 + r]));
                float mn = fmaxf(m_run[mi][rr], mt);
                alpha[mi][rr] = __expf(m_run[mi][rr] - mn);
                mnew[mi][rr] = mn;
                m_run[mi][rr] = mn;
                sloc[mi][rr] = 0.f;
            }
        }
        #pragma unroll
        for (int mi = 0; mi < 4; mi++) {
            #pragma unroll
            for (int rr = 0; rr < 2; rr++) {
                const int rL = mi * 16 + rr * 8 + rbase;
                #pragma unroll
                for (int ni = 0; ni < 4; ni++) {
                    float p0 = __expf(accS[mi][ni][rr * 2 + 0] - mnew[mi][rr]);
                    float p1 = __expf(accS[mi][ni][rr * 2 + 1] - mnew[mi][rr]);
                    sloc[mi][rr] += p0 + p1;
                    const int cL = wn * 32 + ni * 8 + (lane & 3) * 2;
                    __nv_bfloat162 hv, lv;
                    split2(p0, hv.x, lv.x); split2(p1, hv.y, lv.y);
                    *(__nv_bfloat162*)(smem + FP_H + rL * FROW + cL * 2) = hv;
                    *(__nv_bfloat162*)(smem + FP_L + rL * FROW + cL * 2) = lv;
                }
            }
        }
        #pragma unroll
        for (int o = 1; o <= 2; o <<= 1)
            #pragma unroll
            for (int mi = 0; mi < 4; mi++)
                #pragma unroll
                for (int rr = 0; rr < 2; rr++)
                    sloc[mi][rr] += __shfl_xor_sync(0xffffffffu, sloc[mi][rr], o);
        if ((lane & 3) == 0)
            #pragma unroll
            for (int mi = 0; mi < 4; mi++)
                #pragma unroll
                for (int rr = 0; rr < 2; rr++)
                    sumbuf[wn * 128 + mi * 16 + rr * 8 + rbase] = sloc[mi][rr];
        __syncthreads();

        #pragma unroll
        for (int mi = 0; mi < 4; mi++) {
            #pragma unroll
            for (int rr = 0; rr < 2; rr++) {
                const int r = mi * 16 + rr * 8 + rbase;
                float st = sumbuf[r] + sumbuf[128 + r] + sumbuf[256 + r] + sumbuf[384 + r];
                l_run[mi][rr] = l_run[mi][rr] * alpha[mi][rr] + st;
                #pragma unroll
                for (int ni = 0; ni < 4; ni++) {
                    accO[mi][ni][rr * 2 + 0] *= alpha[mi][rr];
                    accO[mi][ni][rr * 2 + 1] *= alpha[mi][rr];
                }
            }
        }

        CP_WAIT(0);
        __syncthreads();

        #pragma unroll
        for (int ks = 0; ks < 8; ks++) {
            const uint32_t kof = (uint32_t)(ks * 32);
            uint32_t bhf[2][4], blf[2][4];
            #pragma unroll
            for (int np = 0; np < 2; np++) {
                const uint32_t o = (uint32_t)(np * 16 * FROW) + kof;
                LDSM_X4(bhf[np][0], bhf[np][1], bhf[np][2], bhf[np][3], sb + FV_H + bOff + o);
                LDSM_X4(blf[np][0], blf[np][1], blf[np][2], blf[np][3], sb + FV_L + bOff + o);
            }
            #pragma unroll
            for (int mi = 0; mi < 4; mi++) {
                uint32_t ah[4], al[4];
                const uint32_t o = (uint32_t)(mi * 16 * FROW) + kof;
                LDSM_X4(ah[0], ah[1], ah[2], ah[3], sb + FP_H + aOff + o);
                LDSM_X4(al[0], al[1], al[2], al[3], sb + FP_L + aOff + o);
                #pragma unroll
                for (int np = 0; np < 2; np++)
                    #pragma unroll
                    for (int hf = 0; hf < 2; hf++)
                        MMA16816(accO[mi][np * 2 + hf], ah, bhf[np][hf * 2], bhf[np][hf * 2 + 1]);
                #pragma unroll
                for (int np = 0; np < 2; np++)
                    #pragma unroll
                    for (int hf = 0; hf < 2; hf++)
                        MMA16816(accO[mi][np * 2 + hf], ah, blf[np][hf * 2], blf[np][hf * 2 + 1]);
                #pragma unroll
                for (int np = 0; np < 2; np++)
                    #pragma unroll
                    for (int hf = 0; hf < 2; hf++)
                        MMA16816(accO[mi][np * 2 + hf], al, bhf[np][hf * 2], bhf[np][hf * 2 + 1]);
            }
        }
        __syncthreads();

        if (jt < it) {
            const size_t koff = ((size_t)(b * SS + j0 + 128 + lrow) * KVHN + hk) * HD + half * 64;
            #pragma unroll
            for (int j = 0; j < 8; j++) {
                CP_ASYNC16(sb + FK_H + sA + j * 16, kh + koff + j * 8);
                CP_ASYNC16(sb + FK_L + sA + j * 16, kl + koff + j * 8);
            }
            CP_COMMIT();
        }
    }

    #pragma unroll
    for (int mi = 0; mi < 4; mi++) {
        #pragma unroll
        for (int rr = 0; rr < 2; rr++) {
            const float inv = 1.f / l_run[mi][rr];
            const int r = wm * 64 + mi * 16 + rr * 8 + (lane >> 2);
            const size_t rowoff = ((size_t)b * SS + i0 + r) * (HH * HD) + h * HD;
            #pragma unroll
            for (int ni = 0; ni < 4; ni++) {
                const int cc = wn * 32 + ni * 8 + (lane & 3) * 2;
                __nv_bfloat162 hv, lv;
                split2(accO[mi][ni][rr * 2 + 0] * inv, hv.x, lv.x);
                split2(accO[mi][ni][rr * 2 + 1] * inv, hv.y, lv.y);
                *(__nv_bfloat162*)(Oh + rowoff + cc) = hv;
                *(__nv_bfloat162*)(Ol + rowoff + cc) = lv;
            }
        }
    }
}

// ================= launch =================
static inline void run_split(const float* w, __nv_bfloat16* h, __nv_bfloat16* l, size_t n) {
    int n8 = (int)(n / 8);
    split_kernel<<<(n8 + 255) / 256, 256>>>((const float4*)w, (uint4*)h, (uint4*)l, n8);
}

extern "C" void kernel_launch(void* const* d_in, const int* in_sizes, int n_in,
                              void* d_out, int out_size)
{
    const float* x          = (const float*)d_in[0];
    const int*   positions  = (const int*)  d_in[1];
    const float* wq         = (const float*)d_in[4];
    const float* wk         = (const float*)d_in[5];
    const float* wv         = (const float*)d_in[6];
    const float* wo         = (const float*)d_in[7];
    const float* q_scale    = (const float*)d_in[8];
    const float* k_scale    = (const float*)d_in[9];
    const float* pre_attn   = (const float*)d_in[10];
    const float* post_attn  = (const float*)d_in[11];
    const float* pre_ffn    = (const float*)d_in[12];
    const float* post_ffn   = (const float*)d_in[13];
    const float* w_gate     = (const float*)d_in[14];
    const float* w_up       = (const float*)d_in[15];
    const float* w_down     = (const float*)d_in[16];
    const float* layer_scal = (const float*)d_in[17];
    float* out = (float*)d_out;

    float *tmp_, *x2_, *ffn_, *rc_, *rs_;
    __nv_bfloat16 *ah_, *al_, *uh_, *ul_, *qh_, *ql_, *kh_, *kl_, *vth_, *vtl_;
    __nv_bfloat16 *wqh, *wql, *wkh, *wkl, *wvh, *wvl, *woh, *wol, *wgh, *wgl, *wuh, *wul, *wdh, *wdl;
    cudaGetSymbolAddress((void**)&tmp_, g_tmp);
    cudaGetSymbolAddress((void**)&x2_,  g_x2);
    cudaGetSymbolAddress((void**)&ffn_, g_ffn);
    cudaGetSymbolAddress((void**)&rc_,  g_ropec);
    cudaGetSymbolAddress((void**)&rs_,  g_ropes);
    cudaGetSymbolAddress((void**)&ah_,  g_ah);
    cudaGetSymbolAddress((void**)&al_,  g_al);
    cudaGetSymbolAddress((void**)&uh_,  g_uh);
    cudaGetSymbolAddress((void**)&ul_,  g_ul);
    cudaGetSymbolAddress((void**)&qh_,  g_qh);  cudaGetSymbolAddress((void**)&ql_,  g_ql);
    cudaGetSymbolAddress((void**)&kh_,  g_kh);  cudaGetSymbolAddress((void**)&kl_,  g_kl);
    cudaGetSymbolAddress((void**)&vth_, g_vth); cudaGetSymbolAddress((void**)&vtl_, g_vtl);
    cudaGetSymbolAddress((void**)&wqh, g_wqh); cudaGetSymbolAddress((void**)&wql, g_wql);
    cudaGetSymbolAddress((void**)&wkh, g_wkh); cudaGetSymbolAddress((void**)&wkl, g_wkl);
    cudaGetSymbolAddress((void**)&wvh, g_wvh); cudaGetSymbolAddress((void**)&wvl, g_wvl);
    cudaGetSymbolAddress((void**)&woh, g_woh); cudaGetSymbolAddress((void**)&wol, g_wol);
    cudaGetSymbolAddress((void**)&wgh, g_wgh); cudaGetSymbolAddress((void**)&wgl, g_wgl);
    cudaGetSymbolAddress((void**)&wuh, g_wuh); cudaGetSymbolAddress((void**)&wul, g_wul);
    cudaGetSymbolAddress((void**)&wdh, g_wdh); cudaGetSymbolAddress((void**)&wdl, g_wdl);

    cudaFuncSetAttribute(gemm_mma,     cudaFuncAttributeMaxDynamicSharedMemorySize, GSMEM2);
    cudaFuncSetAttribute(gemm_mma_qkv, cudaFuncAttributeMaxDynamicSharedMemorySize, GSMEM2);
    cudaFuncSetAttribute(gemm_mma_ffn, cudaFuncAttributeMaxDynamicSharedMemorySize, GSMEMF);
    cudaFuncSetAttribute(attn_fused,   cudaFuncAttributeMaxDynamicSharedMemorySize, FSMEM);

    // weight splits + rope table
    run_split(wq,     wqh, wql, (size_t)HH * HD * DD);
    run_split(wk,     wkh, wkl, (size_t)KVHN * HD * DD);
    run_split(wv,     wvh, wvl, (size_t)KVHN * HD * DD);
    run_split(wo,     woh, wol, (size_t)DD * HH * HD);
    run_split(w_gate, wgh, wgl, (size_t)FFN * DD);
    run_split(w_up,   wuh, wul, (size_t)FFN * DD);
    run_split(w_down, wdh, wdl, (size_t)DD * FFN);
    rope_table_kernel<<<MM, 64>>>(positions, rc_, rs_);

    // ---- attention sub-block (QKV with fused norm/rope/transpose epilogues) ----
    rmsnorm_kernel<<<MM, 256>>>(x, pre_attn, nullptr, nullptr, nullptr, ah_, al_, DD);
    gemm_mma_qkv<<<dim3((HH*HD)/128,   MM/256), 512, GSMEM2>>>(
        ah_, al_, wqh, wql, q_scale, rc_, rs_, qh_, ql_, HH,   0, MM, HH*HD,   DD);
    gemm_mma_qkv<<<dim3((KVHN*HD)/128, MM/256), 512, GSMEM2>>>(
        ah_, al_, wkh, wkl, k_scale, rc_, rs_, kh_, kl_, KVHN, 0, MM, KVHN*HD, DD);
    gemm_mma_qkv<<<dim3((KVHN*HD)/128, MM/256), 512, GSMEM2>>>(
        ah_, al_, wvh, wvl, nullptr, rc_, rs_, vth_, vtl_, KVHN, 2, MM, KVHN*HD, DD);
    attn_fused<<<dim3(SS/128, BB*HH), 256, FSMEM>>>(qh_, ql_, kh_, kl_, vth_, vtl_, ah_, al_);
    gemm_mma<<<dim3(DD/128, MM/256), 512, GSMEM2>>>(ah_, al_, woh, wol, tmp_, MM, DD, HH*HD);

    // fused: x2 = rms(tmp)*post_attn + x;  ah/al = split(rms(x2)*pre_ffn)
    rmsnorm2_kernel<<<MM, 256>>>(tmp_, post_attn, x, pre_ffn, x2_, ah_, al_);

    // ---- FFN sub-block ----
    gemm_mma_ffn<<<dim3(FFN/128, MM/128), 256, GSMEMF>>>(ah_, al_, wgh, wgl, wuh, wul,
                                                         uh_, ul_, MM, FFN, DD);
    gemm_mma<<<dim3(DD/128, MM/256), 512, GSMEM2>>>(uh_, ul_, wdh, wdl, ffn_, MM, DD, FFN);
    rmsnorm_kernel<<<MM, 256>>>(ffn_, post_ffn, x2_, layer_scal, out, nullptr, nullptr, DD);
}

// round 17
// speedup vs baseline: 1.4403x; 1.0613x over previous
#include <cuda_runtime.h>
#include <cuda_bf16.h>
#include <cstdint>
#include <math.h>

#define BB 4
#define SS 1024
#define DD 2048
#define HH 16
#define KVHN 8
#define HD 128
#define FFN 8192
#define MM (BB*SS)
#define EPS_RMS 1e-6f
#define KMASK -1e30f

// ================= PTX helpers (base sm_103 ISA only) =================
__device__ __forceinline__ uint32_t smem_to_u32(const void* p) {
    uint32_t a;
    asm("{ .reg .u64 t; cvta.to.shared.u64 t, %1; cvt.u32.u64 %0, t; }" : "=r"(a) : "l"(p));
    return a;
}
#define CP_ASYNC16(sa, gp) \
    asm volatile("cp.async.cg.shared.global [%0], [%1], 16;" :: "r"(sa), "l"(gp) : "memory")
#define CP_COMMIT() asm volatile("cp.async.commit_group;" ::: "memory")
#define CP_WAIT(n)  asm volatile("cp.async.wait_group %0;" :: "n"(n) : "memory")

#define LDSM_X4(r0, r1, r2, r3, sa) \
    asm volatile("ldmatrix.sync.aligned.m8n8.x4.shared.b16 {%0,%1,%2,%3}, [%4];" \
                 : "=r"(r0), "=r"(r1), "=r"(r2), "=r"(r3) : "r"(sa))

#define MMA16816(d, a, b0, b1) \
    asm volatile("mma.sync.aligned.m16n8k16.row.col.f32.bf16.bf16.f32 " \
                 "{%0,%1,%2,%3}, {%4,%5,%6,%7}, {%8,%9}, {%0,%1,%2,%3};" \
                 : "+f"((d)[0]), "+f"((d)[1]), "+f"((d)[2]), "+f"((d)[3]) \
                 : "r"((a)[0]), "r"((a)[1]), "r"((a)[2]), "r"((a)[3]), "r"(b0), "r"(b1))

#define STS128(r0, r1, r2, r3, sa) \
    asm volatile("st.shared.v4.b32 [%0], {%1, %2, %3, %4};" \
                 :: "r"(sa), "r"(r0), "r"(r1), "r"(r2), "r"(r3) : "memory")

// ================= scratch =================
__device__ float g_tmp [(size_t)MM*DD];
__device__ float g_x2  [(size_t)MM*DD];
__device__ float g_ffn [(size_t)MM*DD];
__device__ __nv_bfloat16 g_ah[(size_t)MM*FFN];
__device__ __nv_bfloat16 g_al[(size_t)MM*FFN];
__device__ __nv_bfloat16 g_uh[(size_t)MM*FFN];
__device__ __nv_bfloat16 g_ul[(size_t)MM*FFN];
// attention bf16 operands
__device__ __nv_bfloat16 g_qh[(size_t)MM*HH*HD],   g_ql[(size_t)MM*HH*HD];
__device__ __nv_bfloat16 g_kh[(size_t)MM*KVHN*HD], g_kl[(size_t)MM*KVHN*HD];
__device__ __nv_bfloat16 g_vth[(size_t)MM*KVHN*HD],g_vtl[(size_t)MM*KVHN*HD];
// RoPE cos/sin table [token][64]
__device__ float g_ropec[(size_t)MM*64];
__device__ float g_ropes[(size_t)MM*64];

__device__ __forceinline__ void split2(float v, __nv_bfloat16& h, __nv_bfloat16& l) {
    h = __float2bfloat16(v);
    l = __float2bfloat16(v - __bfloat162float(h));
}
__device__ __forceinline__ float gelu_tanh(float x) {
    float t = 0.7978845608028654f * (x + 0.044715f * x * x * x);
    return 0.5f * x * (1.f + tanhf(t));
}
// split 8 fp32 (two float4) into 16B hi + 16B lo packed bf16
#define SPLIT8(f0, f1, hv, lv) do { \
    __nv_bfloat162 h0,h1,h2,h3,l0,l1,l2,l3; \
    split2((f0).x,h0.x,l0.x); split2((f0).y,h0.y,l0.y); \
    split2((f0).z,h1.x,l1.x); split2((f0).w,h1.y,l1.y); \
    split2((f1).x,h2.x,l2.x); split2((f1).y,h2.y,l2.y); \
    split2((f1).z,h3.x,l3.x); split2((f1).w,h3.y,l3.y); \
    (hv).x=*(uint32_t*)&h0; (hv).y=*(uint32_t*)&h1; (hv).z=*(uint32_t*)&h2; (hv).w=*(uint32_t*)&h3; \
    (lv).x=*(uint32_t*)&l0; (lv).y=*(uint32_t*)&l1; (lv).z=*(uint32_t*)&l2; (lv).w=*(uint32_t*)&l3; \
} while(0)

// ================= RoPE cos/sin table =================
__global__ __launch_bounds__(64) void rope_table_kernel(
    const int* __restrict__ positions, float* __restrict__ rc, float* __restrict__ rs)
{
    const int token = blockIdx.x;
    const int d = threadIdx.x;
    const int pos = positions[token];
    double freq = pow(10000.0, -((double)(2 * d) / 128.0));
    double ang = (double)pos * freq;
    double dsin, dcos;
    sincos(ang, &dsin, &dcos);
    rc[token * 64 + d] = (float)dcos;
    rs[token * 64 + d] = (float)dsin;
}

// ================= RMSNorm =================
__global__ __launch_bounds__(256) void rmsnorm_kernel(
    const float* __restrict__ in, const float* __restrict__ scale,
    const float* __restrict__ resid, const float* __restrict__ lsc,
    float* __restrict__ out, __nv_bfloat16* __restrict__ oh,
    __nv_bfloat16* __restrict__ ol, int N)
{
    __shared__ float red[8];
    const size_t row = blockIdx.x;
    const float* x = in + row * (size_t)N;
    float ss = 0.f;
    for (int j = threadIdx.x; j < N; j += 256) { float v = x[j]; ss = fmaf(v, v, ss); }
    int lane = threadIdx.x & 31, wid = threadIdx.x >> 5;
    #pragma unroll
    for (int o = 16; o > 0; o >>= 1) ss += __shfl_down_sync(0xffffffffu, ss, o);
    if (lane == 0) red[wid] = ss;
    __syncthreads();
    if (threadIdx.x == 0) {
        float s = 0.f;
        #pragma unroll
        for (int w = 0; w < 8; w++) s += red[w];
        red[0] = s;
    }
    __syncthreads();
    const float r = rsqrtf(red[0] / (float)N + EPS_RMS);
    const float ls = lsc ? lsc[0] : 1.f;
    const float* rp = resid ? resid + row * (size_t)N : nullptr;
    for (int j = threadIdx.x; j < N; j += 256) {
        float v = x[j] * r;
        if (scale) v *= scale[j];
        if (rp) v += rp[j];
        v *= ls;
        if (out) out[row * (size_t)N + j] = v;
        if (oh) {
            __nv_bfloat16 h, l; split2(v, h, l);
            oh[row * (size_t)N + j] = h; ol[row * (size_t)N + j] = l;
        }
    }
}

// ===== fused double RMSNorm =====
__global__ __launch_bounds__(256) void rmsnorm2_kernel(
    const float* __restrict__ tmp, const float* __restrict__ s1,
    const float* __restrict__ resid, const float* __restrict__ s2,
    float* __restrict__ x2, __nv_bfloat16* __restrict__ oh,
    __nv_bfloat16* __restrict__ ol)
{
    __shared__ float red[8];
    const size_t base = (size_t)blockIdx.x * DD;
    const int tid = threadIdx.x;
    const int lane = tid & 31, wid = tid >> 5;
    float t[8];
    float ss = 0.f;
    #pragma unroll
    for (int q = 0; q < 8; q++) {
        t[q] = tmp[base + q * 256 + tid];
        ss = fmaf(t[q], t[q], ss);
    }
    #pragma unroll
    for (int o = 16; o > 0; o >>= 1) ss += __shfl_down_sync(0xffffffffu, ss, o);
    if (lane == 0) red[wid] = ss;
    __syncthreads();
    if (tid == 0) {
        float s = 0.f;
        #pragma unroll
        for (int w = 0; w < 8; w++) s += red[w];
        red[0] = s;
    }
    __syncthreads();
    const float r1 = rsqrtf(red[0] / (float)DD + EPS_RMS);
    __syncthreads();
    float v[8];
    float ss2 = 0.f;
    #pragma unroll
    for (int q = 0; q < 8; q++) {
        const int j = q * 256 + tid;
        v[q] = t[q] * r1 * s1[j] + resid[base + j];
        x2[base + j] = v[q];
        ss2 = fmaf(v[q], v[q], ss2);
    }
    #pragma unroll
    for (int o = 16; o > 0; o >>= 1) ss2 += __shfl_down_sync(0xffffffffu, ss2, o);
    if (lane == 0) red[wid] = ss2;
    __syncthreads();
    if (tid == 0) {
        float s = 0.f;
        #pragma unroll
        for (int w = 0; w < 8; w++) s += red[w];
        red[0] = s;
    }
    __syncthreads();
    const float r2 = rsqrtf(red[0] / (float)DD + EPS_RMS);
    #pragma unroll
    for (int q = 0; q < 8; q++) {
        const int j = q * 256 + tid;
        float o = v[q] * r2 * s2[j];
        __nv_bfloat16 h, l; split2(o, h, l);
        oh[base + j] = h; ol[base + j] = l;
    }
}

// ====== HMMA bf16x3 GEMM core, fp32 B with ON-THE-FLY hi/lo split in loader ======
// CTA 256x128, 512 threads. A (bf16 hi/lo): 3-stage cp.async. B (fp32 weights):
// register-staged LDG float4 -> split -> STS, double-buffered smem.
#define ROW2  80
#define AP    (256 * ROW2)        // 20480 per A part
#define ASTG  (2 * AP)            // 40960 per A stage
#define BP    (128 * ROW2)        // 10240 per B part
#define BBASE (3 * ASTG)          // 122880
#define BSTG  (2 * BP)            // 20480 per B stage
#define GSMEM3 (BBASE + 2 * BSTG) // 163840

#define GEMM_MAIN_FP32B()                                                         \
    extern __shared__ __align__(128) char smem[];                                 \
    const uint32_t sb = smem_to_u32(smem);                                        \
    const int tid = threadIdx.x;                                                  \
    const int wid = tid >> 5, lane = tid & 31;                                    \
    const int wm = wid >> 2, wn = wid & 3;                                        \
    const int m0 = blockIdx.y * 256, n0 = blockIdx.x * 128;                       \
    const int arow = tid >> 1, acs = (tid & 1) * 2;                               \
    const int brow = tid >> 2, bcs = tid & 3;                                     \
    const __nv_bfloat16* gAh = Ah + (size_t)(m0 + arow) * K + acs * 8;            \
    const __nv_bfloat16* gAl = Al + (size_t)(m0 + arow) * K + acs * 8;            \
    const float* gB = B + (size_t)(n0 + brow) * K + bcs * 8;                      \
    const uint32_t aS = (uint32_t)(arow * ROW2 + acs * 16);                       \
    const uint32_t bS = (uint32_t)(brow * ROW2 + bcs * 16);                       \
    const int nch = K / 32;                                                       \
    auto issueA = [&](int c) {                                                    \
        const uint32_t st = sb + (uint32_t)(c % 3) * ASTG;                        \
        const size_t ko = (size_t)c * 32;                                         \
        CP_ASYNC16(st + aS,           gAh + ko);                                  \
        CP_ASYNC16(st + aS + 16,      gAh + ko + 8);                              \
        CP_ASYNC16(st + AP + aS,      gAl + ko);                                  \
        CP_ASYNC16(st + AP + aS + 16, gAl + ko + 8);                              \
    };                                                                            \
    issueA(0); CP_COMMIT();                                                       \
    issueA(1); CP_COMMIT();                                                       \
    float4 rb0 = *(const float4*)(gB);                                            \
    float4 rb1 = *(const float4*)(gB + 4);                                        \
    const uint32_t aOff = (uint32_t)((wm * 64 + (lane & 15)) * ROW2 + (lane >> 4) * 16); \
    const uint32_t bOff = (uint32_t)((wn * 32 + ((lane & 7) | ((lane >> 4) << 3))) * ROW2 \
                                     + ((lane >> 3) & 1) * 16);                   \
    float acc[4][4][4];                                                           \
    _Pragma("unroll")                                                             \
    for (int i = 0; i < 4; i++)                                                   \
        _Pragma("unroll")                                                         \
        for (int j = 0; j < 4; j++)                                               \
            _Pragma("unroll")                                                     \
            for (int q = 0; q < 4; q++) acc[i][j][q] = 0.f;                       \
    for (int c = 0; c < nch; ++c) {                                               \
        {                                                                         \
            uint4 hv, lv; SPLIT8(rb0, rb1, hv, lv);                               \
            const uint32_t bst = sb + BBASE + (uint32_t)(c & 1) * BSTG;           \
            STS128(hv.x, hv.y, hv.z, hv.w, bst + bS);                             \
            STS128(lv.x, lv.y, lv.z, lv.w, bst + BP + bS);                        \
        }                                                                         \
        if (c + 1 < nch) { CP_WAIT(1); } else { CP_WAIT(0); }                     \
        __syncthreads();                                                          \
        if (c + 2 < nch) { issueA(c + 2); CP_COMMIT(); }                          \
        if (c + 1 < nch) {                                                        \
            rb0 = *(const float4*)(gB + (size_t)(c + 1) * 32);                    \
            rb1 = *(const float4*)(gB + (size_t)(c + 1) * 32 + 4);                \
        }                                                                         \
        const uint32_t aH = sb + (uint32_t)(c % 3) * ASTG + aOff;                 \
        const uint32_t aL = aH + AP;                                              \
        const uint32_t bH = sb + BBASE + (uint32_t)(c & 1) * BSTG + bOff;         \
        const uint32_t bL = bH + BP;                                              \
        _Pragma("unroll")                                                         \
        for (int ks = 0; ks < 2; ks++) {                                          \
            uint32_t bh[2][4], bl[2][4];                                          \
            _Pragma("unroll")                                                     \
            for (int np = 0; np < 2; np++) {                                      \
                const uint32_t o = (uint32_t)(np * 16 * ROW2 + ks * 32);          \
                LDSM_X4(bh[np][0], bh[np][1], bh[np][2], bh[np][3], bH + o);      \
                LDSM_X4(bl[np][0], bl[np][1], bl[np][2], bl[np][3], bL + o);      \
            }                                                                     \
            _Pragma("unroll")                                                     \
            for (int mi = 0; mi < 4; mi++) {                                      \
                uint32_t ah[4], al[4];                                            \
                const uint32_t o = (uint32_t)(mi * 16 * ROW2 + ks * 32);          \
                LDSM_X4(ah[0], ah[1], ah[2], ah[3], aH + o);                      \
                LDSM_X4(al[0], al[1], al[2], al[3], aL + o);                      \
                _Pragma("unroll")                                                 \
                for (int np = 0; np < 2; np++)                                    \
                    _Pragma("unroll")                                             \
                    for (int hf = 0; hf < 2; hf++)                                \
                        MMA16816(acc[mi][np * 2 + hf], ah, bh[np][hf * 2], bh[np][hf * 2 + 1]); \
                _Pragma("unroll")                                                 \
                for (int np = 0; np < 2; np++)                                    \
                    _Pragma("unroll")                                             \
                    for (int hf = 0; hf < 2; hf++)                                \
                        MMA16816(acc[mi][np * 2 + hf], ah, bl[np][hf * 2], bl[np][hf * 2 + 1]); \
                _Pragma("unroll")                                                 \
                for (int np = 0; np < 2; np++)                                    \
                    _Pragma("unroll")                                             \
                    for (int hf = 0; hf < 2; hf++)                                \
                        MMA16816(acc[mi][np * 2 + hf], al, bh[np][hf * 2], bh[np][hf * 2 + 1]); \
            }                                                                     \
        }                                                                         \
    }

__global__ __launch_bounds__(512, 1) void gemm_mma(
    const __nv_bfloat16* __restrict__ Ah, const __nv_bfloat16* __restrict__ Al,
    const float* __restrict__ B, float* __restrict__ C, int M, int N, int K)
{
    GEMM_MAIN_FP32B()
    #pragma unroll
    for (int mi = 0; mi < 4; mi++) {
        const int r = m0 + wm * 64 + mi * 16 + (lane >> 2);
        #pragma unroll
        for (int ni = 0; ni < 4; ni++) {
            const int cc = n0 + wn * 32 + ni * 8 + (lane & 3) * 2;
            *(float2*)&C[(size_t)r * N + cc]       = make_float2(acc[mi][ni][0], acc[mi][ni][1]);
            *(float2*)&C[(size_t)(r + 8) * N + cc] = make_float2(acc[mi][ni][2], acc[mi][ni][3]);
        }
    }
}

// ===== QKV GEMM with fused head-RMSNorm (+ RoPE / V-transpose) epilogue =====
__global__ __launch_bounds__(512, 1) void gemm_mma_qkv(
    const __nv_bfloat16* __restrict__ Ah, const __nv_bfloat16* __restrict__ Al,
    const float* __restrict__ B,
    const float* __restrict__ scale,
    const float* __restrict__ rc, const float* __restrict__ rs,
    __nv_bfloat16* __restrict__ Oh, __nv_bfloat16* __restrict__ Ol,
    int nheads, int mode, int M, int N, int K)
{
    GEMM_MAIN_FP32B()
    __syncthreads();   // mainloop smem reads done; reuse smem for epilogue
    float* buf = (float*)smem;                    // [256][130] fp32
    float* red = (float*)(smem + 256 * 130 * 4);  // [4][256]
    const int head = n0 >> 7;
    const int qrow = lane >> 2;

    #pragma unroll
    for (int mi = 0; mi < 4; mi++) {
        #pragma unroll
        for (int rr = 0; rr < 2; rr++) {
            float ssq = 0.f;
            #pragma unroll
            for (int ni = 0; ni < 4; ni++) {
                float a0 = acc[mi][ni][rr * 2], a1 = acc[mi][ni][rr * 2 + 1];
                ssq = fmaf(a0, a0, ssq); ssq = fmaf(a1, a1, ssq);
            }
            ssq += __shfl_xor_sync(0xffffffffu, ssq, 1);
            ssq += __shfl_xor_sync(0xffffffffu, ssq, 2);
            if ((lane & 3) == 0)
                red[wn * 256 + wm * 64 + mi * 16 + rr * 8 + qrow] = ssq;
        }
    }
    __syncthreads();

    #pragma unroll
    for (int mi = 0; mi < 4; mi++) {
        #pragma unroll
        for (int rr = 0; rr < 2; rr++) {
            const int r = wm * 64 + mi * 16 + rr * 8 + qrow;
            const float tot = red[r] + red[256 + r] + red[512 + r] + red[768 + r];
            const float rn = rsqrtf(tot * (1.f / 128.f) + EPS_RMS);
            const int token = m0 + r;
            #pragma unroll
            for (int ni = 0; ni < 4; ni++) {
                const int col = wn * 32 + ni * 8 + (lane & 3) * 2;
                float v0 = acc[mi][ni][rr * 2]     * rn;
                float v1 = acc[mi][ni][rr * 2 + 1] * rn;
                if (scale) { v0 *= scale[col]; v1 *= scale[col + 1]; }
                if (mode == 2) {
                    const int bq = token >> 10, s = token & (SS - 1);
                    const size_t base = (size_t)(bq * KVHN + head) * HD;
                    __nv_bfloat16 h0, l0, h1, l1;
                    split2(v0, h0, l0); split2(v1, h1, l1);
                    Oh[(base + col)     * SS + s] = h0; Ol[(base + col)     * SS + s] = l0;
                    Oh[(base + col + 1) * SS + s] = h1; Ol[(base + col + 1) * SS + s] = l1;
                } else {
                    buf[r * 130 + col]     = v0;
                    buf[r * 130 + col + 1] = v1;
                }
            }
        }
    }
    if (mode == 2) return;
    __syncthreads();

    #pragma unroll
    for (int mi = 0; mi < 4; mi++) {
        #pragma unroll
        for (int rr = 0; rr < 2; rr++) {
            const int r = wm * 64 + mi * 16 + rr * 8 + qrow;
            const int token = m0 + r;
            const size_t rowoff = ((size_t)token * nheads + head) * HD;
            #pragma unroll
            for (int ni = 0; ni < 4; ni++) {
                const int col = wn * 32 + ni * 8 + (lane & 3) * 2;
                __nv_bfloat162 hv, lv;
                #pragma unroll
                for (int c = 0; c < 2; c++) {
                    const int cc = col + c;
                    const float xv = buf[r * 130 + cc];
                    const float xp = buf[r * 130 + (cc ^ 64)];
                    const int d = cc & 63;
                    const float cf = rc[token * 64 + d], sf = rs[token * 64 + d];
                    const float o = (cc < 64) ? xv * cf - xp * sf : xv * cf + xp * sf;
                    __nv_bfloat16 h, l; split2(o, h, l);
                    ((__nv_bfloat16*)&hv)[c] = h; ((__nv_bfloat16*)&lv)[c] = l;
                }
                *(__nv_bfloat162*)(Oh + rowoff + col) = hv;
                *(__nv_bfloat162*)(Ol + rowoff + col) = lv;
            }
        }
    }
}

// ===== dual-B FFN GEMM (fp32 weights, on-the-fly split), GeGLU in registers =====
// CTA 128x128, 256 threads. A: 3-stage cp.async; Bg+Bu: register-staged LDG, 2-stage.
#define APF   (128 * ROW2)          // 10240
#define ASTGF (2 * APF)             // 20480
#define BBASEF (3 * ASTGF)          // 61440
#define BSTGF (4 * APF)             // 40960 (gate hi/lo + up hi/lo)
#define GSMEMF (BBASEF + 2 * BSTGF) // 143360

__global__ __launch_bounds__(256, 1) void gemm_mma_ffn(
    const __nv_bfloat16* __restrict__ Ah, const __nv_bfloat16* __restrict__ Al,
    const float* __restrict__ Bg, const float* __restrict__ Bu,
    __nv_bfloat16* __restrict__ Oh, __nv_bfloat16* __restrict__ Ol,
    int M, int N, int K)
{
    extern __shared__ __align__(128) char smem[];
    const uint32_t sb = smem_to_u32(smem);
    const int tid = threadIdx.x;
    const int wid = tid >> 5, lane = tid & 31;
    const int wm = wid >> 2, wn = wid & 3;
    const int m0 = blockIdx.y * 128, n0 = blockIdx.x * 128;

    const int arow = tid >> 1, acs = (tid & 1) * 2;
    const int brow = tid >> 2, bcs = tid & 3;
    const __nv_bfloat16* gAh = Ah + (size_t)(m0 + arow) * K + acs * 8;
    const __nv_bfloat16* gAl = Al + (size_t)(m0 + arow) * K + acs * 8;
    const float* gBg = Bg + (size_t)(n0 + brow) * K + bcs * 8;
    const float* gBu = Bu + (size_t)(n0 + brow) * K + bcs * 8;
    const size_t brow2 = (size_t)64 * K;
    const uint32_t aS = (uint32_t)(arow * ROW2 + acs * 16);
    const uint32_t bS = (uint32_t)(brow * ROW2 + bcs * 16);

    const int nch = K / 32;

    auto issueA = [&](int c) {
        const uint32_t st = sb + (uint32_t)(c % 3) * ASTGF;
        const size_t ko = (size_t)c * 32;
        CP_ASYNC16(st + aS,            gAh + ko);
        CP_ASYNC16(st + aS + 16,       gAh + ko + 8);
        CP_ASYNC16(st + APF + aS,      gAl + ko);
        CP_ASYNC16(st + APF + aS + 16, gAl + ko + 8);
    };
    issueA(0); CP_COMMIT();
    issueA(1); CP_COMMIT();

    float4 rg[4], ru[4];   // gate/up rows {brow, brow+64}, 2 float4 each
    rg[0] = *(const float4*)(gBg);             rg[1] = *(const float4*)(gBg + 4);
    rg[2] = *(const float4*)(gBg + brow2);     rg[3] = *(const float4*)(gBg + brow2 + 4);
    ru[0] = *(const float4*)(gBu);             ru[1] = *(const float4*)(gBu + 4);
    ru[2] = *(const float4*)(gBu + brow2);     ru[3] = *(const float4*)(gBu + brow2 + 4);

    const uint32_t aOff = (uint32_t)((wm * 64 + (lane & 15)) * ROW2 + (lane >> 4) * 16);
    const uint32_t bOff = (uint32_t)((wn * 32 + ((lane & 7) | ((lane >> 4) << 3))) * ROW2
                                     + ((lane >> 3) & 1) * 16);

    float accg[4][4][4], accu[4][4][4];
    #pragma unroll
    for (int i = 0; i < 4; i++)
        #pragma unroll
        for (int j = 0; j < 4; j++)
            #pragma unroll
            for (int q = 0; q < 4; q++) { accg[i][j][q] = 0.f; accu[i][j][q] = 0.f; }

    for (int c = 0; c < nch; ++c) {
        {
            const uint32_t bst = sb + BBASEF + (uint32_t)(c & 1) * BSTGF;
            uint4 hv, lv;
            SPLIT8(rg[0], rg[1], hv, lv);
            STS128(hv.x, hv.y, hv.z, hv.w, bst + bS);
            STS128(lv.x, lv.y, lv.z, lv.w, bst + APF + bS);
            SPLIT8(rg[2], rg[3], hv, lv);
            STS128(hv.x, hv.y, hv.z, hv.w, bst + bS + 64 * ROW2);
            STS128(lv.x, lv.y, lv.z, lv.w, bst + APF + bS + 64 * ROW2);
            SPLIT8(ru[0], ru[1], hv, lv);
            STS128(hv.x, hv.y, hv.z, hv.w, bst + 2 * APF + bS);
            STS128(lv.x, lv.y, lv.z, lv.w, bst + 3 * APF + bS);
            SPLIT8(ru[2], ru[3], hv, lv);
            STS128(hv.x, hv.y, hv.z, hv.w, bst + 2 * APF + bS + 64 * ROW2);
            STS128(lv.x, lv.y, lv.z, lv.w, bst + 3 * APF + bS + 64 * ROW2);
        }
        if (c + 1 < nch) { CP_WAIT(1); } else { CP_WAIT(0); }
        __syncthreads();
        if (c + 2 < nch) { issueA(c + 2); CP_COMMIT(); }
        if (c + 1 < nch) {
            const size_t ko = (size_t)(c + 1) * 32;
            rg[0] = *(const float4*)(gBg + ko);         rg[1] = *(const float4*)(gBg + ko + 4);
            rg[2] = *(const float4*)(gBg + brow2 + ko); rg[3] = *(const float4*)(gBg + brow2 + ko + 4);
            ru[0] = *(const float4*)(gBu + ko);         ru[1] = *(const float4*)(gBu + ko + 4);
            ru[2] = *(const float4*)(gBu + brow2 + ko); ru[3] = *(const float4*)(gBu + brow2 + ko + 4);
        }

        const uint32_t aH  = sb + (uint32_t)(c % 3) * ASTGF + aOff;
        const uint32_t aL  = aH + APF;
        const uint32_t bst = sb + BBASEF + (uint32_t)(c & 1) * BSTGF;
        const uint32_t bgH = bst + bOff;
        const uint32_t bgL = bgH + APF;
        const uint32_t buH = bgL + APF;
        const uint32_t buL = buH + APF;

        #pragma unroll
        for (int ks = 0; ks < 2; ks++) {
            uint32_t gh[2][4], gl[2][4], uh[2][4], ul[2][4];
            #pragma unroll
            for (int np = 0; np < 2; np++) {
                const uint32_t o = (uint32_t)(np * 16 * ROW2 + ks * 32);
                LDSM_X4(gh[np][0], gh[np][1], gh[np][2], gh[np][3], bgH + o);
                LDSM_X4(gl[np][0], gl[np][1], gl[np][2], gl[np][3], bgL + o);
                LDSM_X4(uh[np][0], uh[np][1], uh[np][2], uh[np][3], buH + o);
                LDSM_X4(ul[np][0], ul[np][1], ul[np][2], ul[np][3], buL + o);
            }
            #pragma unroll
            for (int mi = 0; mi < 4; mi++) {
                uint32_t ah[4], al[4];
                const uint32_t o = (uint32_t)(mi * 16 * ROW2 + ks * 32);
                LDSM_X4(ah[0], ah[1], ah[2], ah[3], aH + o);
                LDSM_X4(al[0], al[1], al[2], al[3], aL + o);
                #pragma unroll
                for (int np = 0; np < 2; np++)
                    #pragma unroll
                    for (int hf = 0; hf < 2; hf++)
                        MMA16816(accg[mi][np * 2 + hf], ah, gh[np][hf * 2], gh[np][hf * 2 + 1]);
                #pragma unroll
                for (int np = 0; np < 2; np++)
                    #pragma unroll
                    for (int hf = 0; hf < 2; hf++)
                        MMA16816(accg[mi][np * 2 + hf], ah, gl[np][hf * 2], gl[np][hf * 2 + 1]);
                #pragma unroll
                for (int np = 0; np < 2; np++)
                    #pragma unroll
                    for (int hf = 0; hf < 2; hf++)
                        MMA16816(accg[mi][np * 2 + hf], al, gh[np][hf * 2], gh[np][hf * 2 + 1]);
                #pragma unroll
                for (int np = 0; np < 2; np++)
                    #pragma unroll
                    for (int hf = 0; hf < 2; hf++)
                        MMA16816(accu[mi][np * 2 + hf], ah, uh[np][hf * 2], uh[np][hf * 2 + 1]);
                #pragma unroll
                for (int np = 0; np < 2; np++)
                    #pragma unroll
                    for (int hf = 0; hf < 2; hf++)
                        MMA16816(accu[mi][np * 2 + hf], ah, ul[np][hf * 2], ul[np][hf * 2 + 1]);
                #pragma unroll
                for (int np = 0; np < 2; np++)
                    #pragma unroll
                    for (int hf = 0; hf < 2; hf++)
                        MMA16816(accu[mi][np * 2 + hf], al, uh[np][hf * 2], uh[np][hf * 2 + 1]);
            }
        }
    }

    #pragma unroll
    for (int mi = 0; mi < 4; mi++) {
        #pragma unroll
        for (int rr = 0; rr < 2; rr++) {
            const int r = m0 + wm * 64 + mi * 16 + rr * 8 + (lane >> 2);
            #pragma unroll
            for (int ni = 0; ni < 4; ni++) {
                const int cc = n0 + wn * 32 + ni * 8 + (lane & 3) * 2;
                float r0 = gelu_tanh(accg[mi][ni][rr * 2 + 0]) * accu[mi][ni][rr * 2 + 0];
                float r1 = gelu_tanh(accg[mi][ni][rr * 2 + 1]) * accu[mi][ni][rr * 2 + 1];
                __nv_bfloat162 hv, lv;
                split2(r0, hv.x, lv.x); split2(r1, hv.y, lv.y);
                *(__nv_bfloat162*)(Oh + (size_t)r * N + cc) = hv;
                *(__nv_bfloat162*)(Ol + (size_t)r * N + cc) = lv;
            }
        }
    }
}

// ================= fused flash attention (unchanged, passing) =================
#define FROW  272
#define FTILE (128 * FROW)
#define FQ_H  0
#define FQ_L  (FQ_H + FTILE)
#define FK_H  (FQ_L + FTILE)
#define FK_L  (FK_H + FTILE)
#define FV_H  (FK_L + FTILE)
#define FV_L  (FV_H + FTILE)
#define FP_H  FK_H
#define FP_L  FK_L
#define FRED  (FV_L + FTILE)
#define FSMEM (FRED + 2 * 4 * 128 * 4)

__global__ __launch_bounds__(256, 1) void attn_fused(
    const __nv_bfloat16* __restrict__ qh, const __nv_bfloat16* __restrict__ ql,
    const __nv_bfloat16* __restrict__ kh, const __nv_bfloat16* __restrict__ kl,
    const __nv_bfloat16* __restrict__ vth, const __nv_bfloat16* __restrict__ vtl,
    __nv_bfloat16* __restrict__ Oh, __nv_bfloat16* __restrict__ Ol)
{
    extern __shared__ __align__(128) char smem[];
    const uint32_t sb = smem_to_u32(smem);
    const int bh = blockIdx.y;
    const int b = bh >> 4, h = bh & 15, hk = h >> 1;
    const int it = 7 - blockIdx.x;
    const int i0 = it * 128;
    const int tid = threadIdx.x;
    const int wid = tid >> 5, lane = tid & 31;
    const int wm = wid >> 2, wn = wid & 3;

    const int lrow = tid >> 1, half = tid & 1;
    const uint32_t sA = (uint32_t)(lrow * FROW + half * 128);
    const size_t qoff  = ((size_t)(b * SS + i0 + lrow) * HH + h) * HD + half * 64;
    const size_t vbase = ((size_t)(b * KVHN + hk) * HD + lrow) * SS + half * 64;

    #pragma unroll
    for (int j = 0; j < 8; j++) {
        CP_ASYNC16(sb + FQ_H + sA + j * 16, qh + qoff + j * 8);
        CP_ASYNC16(sb + FQ_L + sA + j * 16, ql + qoff + j * 8);
    }
    {
        const size_t koff = ((size_t)(b * SS + lrow) * KVHN + hk) * HD + half * 64;
        #pragma unroll
        for (int j = 0; j < 8; j++) {
            CP_ASYNC16(sb + FK_H + sA + j * 16, kh + koff + j * 8);
            CP_ASYNC16(sb + FK_L + sA + j * 16, kl + koff + j * 8);
        }
    }
    CP_COMMIT();

    const uint32_t aOff = (uint32_t)((wm * 64 + (lane & 15)) * FROW + (lane >> 4) * 16);
    const uint32_t bOff = (uint32_t)((wn * 32 + ((lane & 7) | ((lane >> 4) << 3))) * FROW
                                     + ((lane >> 3) & 1) * 16);

    float accO[4][4][4];
    float m_run[4][2], l_run[4][2];
    #pragma unroll
    for (int i = 0; i < 4; i++) {
        m_run[i][0] = -1e30f; m_run[i][1] = -1e30f;
        l_run[i][0] = 0.f;    l_run[i][1] = 0.f;
        #pragma unroll
        for (int j = 0; j < 4; j++)
            #pragma unroll
            for (int q = 0; q < 4; q++) accO[i][j][q] = 0.f;
    }

    float* maxbuf = (float*)(smem + FRED);
    float* sumbuf = maxbuf + 4 * 128;
    const int rbase = wm * 64 + (lane >> 2);

    for (int jt = 0; jt <= it; ++jt) {
        const int j0 = jt * 128;
        #pragma unroll
        for (int j = 0; j < 8; j++) {
            CP_ASYNC16(sb + FV_H + sA + j * 16, vth + vbase + j0 + j * 8);
            CP_ASYNC16(sb + FV_L + sA + j * 16, vtl + vbase + j0 + j * 8);
        }
        CP_COMMIT();
        CP_WAIT(1);
        __syncthreads();

        float accS[4][4][4];
        #pragma unroll
        for (int i = 0; i < 4; i++)
            #pragma unroll
            for (int j = 0; j < 4; j++)
                #pragma unroll
                for (int q = 0; q < 4; q++) accS[i][j][q] = 0.f;
        #pragma unroll
        for (int ks = 0; ks < 8; ks++) {
            const uint32_t kof = (uint32_t)(ks * 32);
            uint32_t bhf[2][4], blf[2][4];
            #pragma unroll
            for (int np = 0; np < 2; np++) {
                const uint32_t o = (uint32_t)(np * 16 * FROW) + kof;
                LDSM_X4(bhf[np][0], bhf[np][1], bhf[np][2], bhf[np][3], sb + FK_H + bOff + o);
                LDSM_X4(blf[np][0], blf[np][1], blf[np][2], blf[np][3], sb + FK_L + bOff + o);
            }
            #pragma unroll
            for (int mi = 0; mi < 4; mi++) {
                uint32_t ah[4], al[4];
                const uint32_t o = (uint32_t)(mi * 16 * FROW) + kof;
                LDSM_X4(ah[0], ah[1], ah[2], ah[3], sb + FQ_H + aOff + o);
                LDSM_X4(al[0], al[1], al[2], al[3], sb + FQ_L + aOff + o);
                #pragma unroll
                for (int np = 0; np < 2; np++)
                    #pragma unroll
                    for (int hf = 0; hf < 2; hf++)
                        MMA16816(accS[mi][np * 2 + hf], ah, bhf[np][hf * 2], bhf[np][hf * 2 + 1]);
                #pragma unroll
                for (int np = 0; np < 2; np++)
                    #pragma unroll
                    for (int hf = 0; hf < 2; hf++)
                        MMA16816(accS[mi][np * 2 + hf], ah, blf[np][hf * 2], blf[np][hf * 2 + 1]);
                #pragma unroll
                for (int np = 0; np < 2; np++)
                    #pragma unroll
                    for (int hf = 0; hf < 2; hf++)
                        MMA16816(accS[mi][np * 2 + hf], al, bhf[np][hf * 2], bhf[np][hf * 2 + 1]);
            }
        }

        const bool diag = (jt == it);
        float mloc[4][2];
        #pragma unroll
        for (int mi = 0; mi < 4; mi++) {
            #pragma unroll
            for (int rr = 0; rr < 2; rr++) {
                const int rL = mi * 16 + rr * 8 + rbase;
                float mx = -3.4e38f;
                #pragma unroll
                for (int ni = 0; ni < 4; ni++) {
                    #pragma unroll
                    for (int c = 0; c < 2; c++) {
                        const int cL = wn * 32 + ni * 8 + (lane & 3) * 2 + c;
                        float s = tanhf(accS[mi][ni][rr * 2 + c] * 0.02f) * 50.f;
                        if (diag && cL > rL) s = KMASK;
                        accS[mi][ni][rr * 2 + c] = s;
                        mx = fmaxf(mx, s);
                    }
                }
                mloc[mi][rr] = mx;
            }
        }
        #pragma unroll
        for (int o = 1; o <= 2; o <<= 1)
            #pragma unroll
            for (int mi = 0; mi < 4; mi++)
                #pragma unroll
                for (int rr = 0; rr < 2; rr++)
                    mloc[mi][rr] = fmaxf(mloc[mi][rr], __shfl_xor_sync(0xffffffffu, mloc[mi][rr], o));
        if ((lane & 3) == 0)
            #pragma unroll
            for (int mi = 0; mi < 4; mi++)
                #pragma unroll
                for (int rr = 0; rr < 2; rr++)
                    maxbuf[wn * 128 + mi * 16 + rr * 8 + rbase] = mloc[mi][rr];
        __syncthreads();

        float alpha[4][2], mnew[4][2], sloc[4][2];
        #pragma unroll
        for (int mi = 0; mi < 4; mi++) {
            #pragma unroll
            for (int rr = 0; rr < 2; rr++) {
                const int r = mi * 16 + rr * 8 + rbase;
                float mt = fmaxf(fmaxf(maxbuf[r], maxbuf[128 + r]),
                                 fmaxf(maxbuf[256 + r], maxbuf[384 + r]));
                float mn = fmaxf(m_run[mi][rr], mt);
                alpha[mi][rr] = __expf(m_run[mi][rr] - mn);
                mnew[mi][rr] = mn;
                m_run[mi][rr] = mn;
                sloc[mi][rr] = 0.f;
            }
        }
        #pragma unroll
        for (int mi = 0; mi < 4; mi++) {
            #pragma unroll
            for (int rr = 0; rr < 2; rr++) {
                const int rL = mi * 16 + rr * 8 + rbase;
                #pragma unroll
                for (int ni = 0; ni < 4; ni++) {
                    float p0 = __expf(accS[mi][ni][rr * 2 + 0] - mnew[mi][rr]);
                    float p1 = __expf(accS[mi][ni][rr * 2 + 1] - mnew[mi][rr]);
                    sloc[mi][rr] += p0 + p1;
                    const int cL = wn * 32 + ni * 8 + (lane & 3) * 2;
                    __nv_bfloat162 hv, lv;
                    split2(p0, hv.x, lv.x); split2(p1, hv.y, lv.y);
                    *(__nv_bfloat162*)(smem + FP_H + rL * FROW + cL * 2) = hv;
                    *(__nv_bfloat162*)(smem + FP_L + rL * FROW + cL * 2) = lv;
                }
            }
        }
        #pragma unroll
        for (int o = 1; o <= 2; o <<= 1)
            #pragma unroll
            for (int mi = 0; mi < 4; mi++)
                #pragma unroll
                for (int rr = 0; rr < 2; rr++)
                    sloc[mi][rr] += __shfl_xor_sync(0xffffffffu, sloc[mi][rr], o);
        if ((lane & 3) == 0)
            #pragma unroll
            for (int mi = 0; mi < 4; mi++)
                #pragma unroll
                for (int rr = 0; rr < 2; rr++)
                    sumbuf[wn * 128 + mi * 16 + rr * 8 + rbase] = sloc[mi][rr];
        __syncthreads();

        #pragma unroll
        for (int mi = 0; mi < 4; mi++) {
            #pragma unroll
            for (int rr = 0; rr < 2; rr++) {
                const int r = mi * 16 + rr * 8 + rbase;
                float st = sumbuf[r] + sumbuf[128 + r] + sumbuf[256 + r] + sumbuf[384 + r];
                l_run[mi][rr] = l_run[mi][rr] * alpha[mi][rr] + st;
                #pragma unroll
                for (int ni = 0; ni < 4; ni++) {
                    accO[mi][ni][rr * 2 + 0] *= alpha[mi][rr];
                    accO[mi][ni][rr * 2 + 1] *= alpha[mi][rr];
                }
            }
        }

        CP_WAIT(0);
        __syncthreads();

        #pragma unroll
        for (int ks = 0; ks < 8; ks++) {
            const uint32_t kof = (uint32_t)(ks * 32);
            uint32_t bhf[2][4], blf[2][4];
            #pragma unroll
            for (int np = 0; np < 2; np++) {
                const uint32_t o = (uint32_t)(np * 16 * FROW) + kof;
                LDSM_X4(bhf[np][0], bhf[np][1], bhf[np][2], bhf[np][3], sb + FV_H + bOff + o);
                LDSM_X4(blf[np][0], blf[np][1], blf[np][2], blf[np][3], sb + FV_L + bOff + o);
            }
            #pragma unroll
            for (int mi = 0; mi < 4; mi++) {
                uint32_t ah[4], al[4];
                const uint32_t o = (uint32_t)(mi * 16 * FROW) + kof;
                LDSM_X4(ah[0], ah[1], ah[2], ah[3], sb + FP_H + aOff + o);
                LDSM_X4(al[0], al[1], al[2], al[3], sb + FP_L + aOff + o);
                #pragma unroll
                for (int np = 0; np < 2; np++)
                    #pragma unroll
                    for (int hf = 0; hf < 2; hf++)
                        MMA16816(accO[mi][np * 2 + hf], ah, bhf[np][hf * 2], bhf[np][hf * 2 + 1]);
                #pragma unroll
                for (int np = 0; np < 2; np++)
                    #pragma unroll
                    for (int hf = 0; hf < 2; hf++)
                        MMA16816(accO[mi][np * 2 + hf], ah, blf[np][hf * 2], blf[np][hf * 2 + 1]);
                #pragma unroll
                for (int np = 0; np < 2; np++)
                    #pragma unroll
                    for (int hf = 0; hf < 2; hf++)
                        MMA16816(accO[mi][np * 2 + hf], al, bhf[np][hf * 2], bhf[np][hf * 2 + 1]);
            }
        }
        __syncthreads();

        if (jt < it) {
            const size_t koff = ((size_t)(b * SS + j0 + 128 + lrow) * KVHN + hk) * HD + half * 64;
            #pragma unroll
            for (int j = 0; j < 8; j++) {
                CP_ASYNC16(sb + FK_H + sA + j * 16, kh + koff + j * 8);
                CP_ASYNC16(sb + FK_L + sA + j * 16, kl + koff + j * 8);
            }
            CP_COMMIT();
        }
    }

    #pragma unroll
    for (int mi = 0; mi < 4; mi++) {
        #pragma unroll
        for (int rr = 0; rr < 2; rr++) {
            const float inv = 1.f / l_run[mi][rr];
            const int r = wm * 64 + mi * 16 + rr * 8 + (lane >> 2);
            const size_t rowoff = ((size_t)b * SS + i0 + r) * (HH * HD) + h * HD;
            #pragma unroll
            for (int ni = 0; ni < 4; ni++) {
                const int cc = wn * 32 + ni * 8 + (lane & 3) * 2;
                __nv_bfloat162 hv, lv;
                split2(accO[mi][ni][rr * 2 + 0] * inv, hv.x, lv.x);
                split2(accO[mi][ni][rr * 2 + 1] * inv, hv.y, lv.y);
                *(__nv_bfloat162*)(Oh + rowoff + cc) = hv;
                *(__nv_bfloat162*)(Ol + rowoff + cc) = lv;
            }
        }
    }
}

// ================= launch =================
extern "C" void kernel_launch(void* const* d_in, const int* in_sizes, int n_in,
                              void* d_out, int out_size)
{
    const float* x          = (const float*)d_in[0];
    const int*   positions  = (const int*)  d_in[1];
    const float* wq         = (const float*)d_in[4];
    const float* wk         = (const float*)d_in[5];
    const float* wv         = (const float*)d_in[6];
    const float* wo         = (const float*)d_in[7];
    const float* q_scale    = (const float*)d_in[8];
    const float* k_scale    = (const float*)d_in[9];
    const float* pre_attn   = (const float*)d_in[10];
    const float* post_attn  = (const float*)d_in[11];
    const float* pre_ffn    = (const float*)d_in[12];
    const float* post_ffn   = (const float*)d_in[13];
    const float* w_gate     = (const float*)d_in[14];
    const float* w_up       = (const float*)d_in[15];
    const float* w_down     = (const float*)d_in[16];
    const float* layer_scal = (const float*)d_in[17];
    float* out = (float*)d_out;

    float *tmp_, *x2_, *ffn_, *rc_, *rs_;
    __nv_bfloat16 *ah_, *al_, *uh_, *ul_, *qh_, *ql_, *kh_, *kl_, *vth_, *vtl_;
    cudaGetSymbolAddress((void**)&tmp_, g_tmp);
    cudaGetSymbolAddress((void**)&x2_,  g_x2);
    cudaGetSymbolAddress((void**)&ffn_, g_ffn);
    cudaGetSymbolAddress((void**)&rc_,  g_ropec);
    cudaGetSymbolAddress((void**)&rs_,  g_ropes);
    cudaGetSymbolAddress((void**)&ah_,  g_ah);
    cudaGetSymbolAddress((void**)&al_,  g_al);
    cudaGetSymbolAddress((void**)&uh_,  g_uh);
    cudaGetSymbolAddress((void**)&ul_,  g_ul);
    cudaGetSymbolAddress((void**)&qh_,  g_qh);  cudaGetSymbolAddress((void**)&ql_,  g_ql);
    cudaGetSymbolAddress((void**)&kh_,  g_kh);  cudaGetSymbolAddress((void**)&kl_,  g_kl);
    cudaGetSymbolAddress((void**)&vth_, g_vth); cudaGetSymbolAddress((void**)&vtl_, g_vtl);

    cudaFuncSetAttribute(gemm_mma,     cudaFuncAttributeMaxDynamicSharedMemorySize, GSMEM3);
    cudaFuncSetAttribute(gemm_mma_qkv, cudaFuncAttributeMaxDynamicSharedMemorySize, GSMEM3);
    cudaFuncSetAttribute(gemm_mma_ffn, cudaFuncAttributeMaxDynamicSharedMemorySize, GSMEMF);
    cudaFuncSetAttribute(attn_fused,   cudaFuncAttributeMaxDynamicSharedMemorySize, FSMEM);

    rope_table_kernel<<<MM, 64>>>(positions, rc_, rs_);

    // ---- attention sub-block (QKV with fused norm/rope/transpose epilogues) ----
    rmsnorm_kernel<<<MM, 256>>>(x, pre_attn, nullptr, nullptr, nullptr, ah_, al_, DD);
    gemm_mma_qkv<<<dim3((HH*HD)/128,   MM/256), 512, GSMEM3>>>(
        ah_, al_, wq, q_scale, rc_, rs_, qh_, ql_, HH,   0, MM, HH*HD,   DD);
    gemm_mma_qkv<<<dim3((KVHN*HD)/128, MM/256), 512, GSMEM3>>>(
        ah_, al_, wk, k_scale, rc_, rs_, kh_, kl_, KVHN, 0, MM, KVHN*HD, DD);
    gemm_mma_qkv<<<dim3((KVHN*HD)/128, MM/256), 512, GSMEM3>>>(
        ah_, al_, wv, nullptr, rc_, rs_, vth_, vtl_, KVHN, 2, MM, KVHN*HD, DD);
    attn_fused<<<dim3(SS/128, BB*HH), 256, FSMEM>>>(qh_, ql_, kh_, kl_, vth_, vtl_, ah_, al_);
    gemm_mma<<<dim3(DD/128, MM/256), 512, GSMEM3>>>(ah_, al_, wo, tmp_, MM, DD, HH*HD);

    // fused: x2 = rms(tmp)*post_attn + x;  ah/al = split(rms(x2)*pre_ffn)
    rmsnorm2_kernel<<<MM, 256>>>(tmp_, post_attn, x, pre_ffn, x2_, ah_, al_);

    // ---- FFN sub-block ----
    gemm_mma_ffn<<<dim3(FFN/128, MM/128), 256, GSMEMF>>>(ah_, al_, w_gate, w_up,
                                                         uh_, ul_, MM, FFN, DD);
    gemm_mma<<<dim3(DD/128, MM/256), 512, GSMEM3>>>(uh_, ul_, w_down, ffn_, MM, DD, FFN);
    rmsnorm_kernel<<<MM, 256>>>(ffn_, post_ffn, x2_, layer_scal, out, nullptr, nullptr, DD);
}